// round 1
// baseline (speedup 1.0000x reference)
#include <cuda_runtime.h>
#include <math.h>

#define NT 8
#define NN 50000
#define NE 800000
#define HD 128
#define NL 2

// ---------------- static device scratch (no allocs allowed) ----------------
__device__ float g_h[NL][NN * HD];        // hidden state per layer
__device__ float g_aggX[NN * HD];         // A @ inp
__device__ float g_aggH[NN * HD];         // A @ h
__device__ float g_aggRH[NN * HD];        // A @ (r*h)
__device__ float g_z[NN * HD];            // z gate
__device__ float g_rh[NN * HD];           // r*h
__device__ int   g_cnt[NN];
__device__ int   g_cur[NN];
__device__ int   g_offs[NN + 1];
__device__ float g_dinv[NN];
__device__ int   g_ccol[NE];
__device__ float g_cw[NE];
__device__ float g_Bzr[NL][256 * 256];    // packed [Wxz Wxr; Whz Whr]
__device__ float g_Bh [NL][256 * 128];    // packed [Wxh; Whh]
__device__ float g_bzr[NL][256];
__device__ float g_bh [NL][128];

// ---------------- setup kernels ----------------
__global__ void k_zero_counts() {
    int i = blockIdx.x * blockDim.x + threadIdx.x;
    if (i < NN) { g_cnt[i] = 0; g_cur[i] = 0; }
}

__global__ void k_count(const int* __restrict__ ei) {
    int e = blockIdx.x * blockDim.x + threadIdx.x;
    if (e < NE) atomicAdd(&g_cnt[ei[e]], 1);
}

__global__ void k_dinv() {
    int i = blockIdx.x * blockDim.x + threadIdx.x;
    if (i < NN) g_dinv[i] = rsqrtf((float)(g_cnt[i] + 2));
}

// single-block exclusive scan of g_cnt -> g_offs (one-time per launch, tiny)
__global__ void k_scan() {
    __shared__ int s[1024];
    __shared__ int carry;
    int tid = threadIdx.x;
    if (tid == 0) carry = 0;
    __syncthreads();
    for (int base = 0; base < NN; base += 1024) {
        int i = base + tid;
        int v = (i < NN) ? g_cnt[i] : 0;
        s[tid] = v;
        __syncthreads();
        #pragma unroll
        for (int off = 1; off < 1024; off <<= 1) {
            int t = (tid >= off) ? s[tid - off] : 0;
            __syncthreads();
            s[tid] += t;
            __syncthreads();
        }
        int c = carry;
        if (i < NN) g_offs[i] = c + s[tid] - v;
        __syncthreads();
        if (tid == 0) carry = c + s[1023];
        __syncthreads();
    }
    if (tid == 0) g_offs[NN] = carry;
}

__global__ void k_fill(const int* __restrict__ ei) {
    int e = blockIdx.x * blockDim.x + threadIdx.x;
    if (e < NE) {
        int r = ei[e];
        int c = ei[NE + e];
        int pos = g_offs[r] + atomicAdd(&g_cur[r], 1);
        g_ccol[pos] = c;
        g_cw[pos]  = g_dinv[r] * g_dinv[c];
    }
}

__global__ void k_pack(const float* __restrict__ Wxz, const float* __restrict__ Whz,
                       const float* __restrict__ Wxr, const float* __restrict__ Whr,
                       const float* __restrict__ Wxh, const float* __restrict__ Whh) {
    int i = blockIdx.x * blockDim.x + threadIdx.x;
    const int tot_zr = NL * 256 * 256;
    if (i < tot_zr) {
        int l = i / (256 * 256);
        int kj = i % (256 * 256);
        int k = kj / 256, j = kj % 256;
        const float* W = (k < 128) ? ((j < 128) ? Wxz : Wxr)
                                   : ((j < 128) ? Whz : Whr);
        g_Bzr[l][kj] = W[l * HD * HD + (k & 127) * HD + (j & 127)];
    } else {
        int i2 = i - tot_zr;
        if (i2 < NL * 256 * 128) {
            int l = i2 / (256 * 128);
            int kj = i2 % (256 * 128);
            int k = kj / 128, j = kj % 128;
            const float* W = (k < 128) ? Wxh : Whh;
            g_Bh[l][kj] = W[l * HD * HD + (k & 127) * HD + j];
        }
    }
}

__global__ void k_bias(const float* __restrict__ bxz, const float* __restrict__ bhz,
                       const float* __restrict__ bxr, const float* __restrict__ bhr,
                       const float* __restrict__ bxh, const float* __restrict__ bhh) {
    int i = blockIdx.x * blockDim.x + threadIdx.x;
    if (i < NL * 256) {
        int l = i / 256, j = i % 256;
        g_bzr[l][j] = (j < 128) ? (bxz[l * HD + j] + bhz[l * HD + j])
                                : (bxr[l * HD + j - 128] + bhr[l * HD + j - 128]);
    }
    if (i < NL * 128) {
        int l = i / 128, j = i % 128;
        g_bh[l][j] = bxh[l * HD + j] + bhh[l * HD + j];
    }
}

__global__ void k_copy_h0(const float4* __restrict__ h0) {
    int i = blockIdx.x * blockDim.x + threadIdx.x;
    if (i < NL * NN * HD / 4) ((float4*)&g_h[0][0])[i] = h0[i];
}

// ---------------- SpMM: out[r] = 2*dinv[r]^2*src[r] + sum_e w[e]*src[col[e]] ----------------
// one warp per row, float4 per lane (128 floats / row)
__global__ void __launch_bounds__(256) k_spmm(const float* __restrict__ src,
                                              float* __restrict__ out) {
    int warp = (blockIdx.x * blockDim.x + threadIdx.x) >> 5;
    int lane = threadIdx.x & 31;
    if (warp >= NN) return;
    const float4* s4 = (const float4*)src;
    float di = g_dinv[warp];
    float4 v = s4[(size_t)warp * 32 + lane];
    float ws = 2.f * di * di;
    float4 acc = make_float4(ws * v.x, ws * v.y, ws * v.z, ws * v.w);
    int e = g_offs[warp], end = g_offs[warp + 1];
    for (; e < end; ++e) {
        int   c = g_ccol[e];
        float w = g_cw[e];
        float4 u = s4[(size_t)c * 32 + lane];
        acc.x += w * u.x; acc.y += w * u.y; acc.z += w * u.z; acc.w += w * u.w;
    }
    ((float4*)out)[(size_t)warp * 32 + lane] = acc;
}

// ---------------- fused SGEMM: C = [A0|A1] (Mx256) @ B (256xNcols) + bias ----------------
// MODE 0 (zr): cols 0..127 -> z = sigmoid(v); cols 128..255 -> rh = sigmoid(v)*h
// MODE 1 (h):  hn = z*h + (1-z)*tanh(v); write to outA (h buf) and optionally outB (d_out)
#define BM 128
#define BN 128
#define BK 16

template <int MODE>
__global__ void __launch_bounds__(256) k_gemm(
    const float* __restrict__ A0, const float* __restrict__ A1,
    const float* __restrict__ B,  const float* __restrict__ bias,
    const float* __restrict__ hbuf, const float* __restrict__ zbuf,
    float* __restrict__ outA, float* __restrict__ outB, int ldB) {

    __shared__ float As[BK][BM];
    __shared__ float Bs[BK][BN];

    int tid = threadIdx.x;
    int tx = tid & 15;
    int ty = tid >> 4;
    int rowBase = blockIdx.x * BM;
    int colBase = blockIdx.y * BN;

    float acc[8][8];
    #pragma unroll
    for (int i = 0; i < 8; ++i)
        #pragma unroll
        for (int j = 0; j < 8; ++j) acc[i][j] = 0.f;

    for (int kt = 0; kt < 256; kt += BK) {
        const float* Asrc = (kt < 128) ? A0 : A1;
        int kin = kt & 127;
        // load A tile (transpose into As[k][m])
        #pragma unroll
        for (int u = 0; u < 2; ++u) {
            int idx = tid * 2 + u;      // 0..511
            int r = idx >> 2;           // 0..127
            int q = idx & 3;
            int gr = rowBase + r;
            float4 v = (gr < NN)
                ? ((const float4*)(Asrc + (size_t)gr * HD + kin))[q]
                : make_float4(0.f, 0.f, 0.f, 0.f);
            As[q * 4 + 0][r] = v.x;
            As[q * 4 + 1][r] = v.y;
            As[q * 4 + 2][r] = v.z;
            As[q * 4 + 3][r] = v.w;
        }
        // load B tile
        #pragma unroll
        for (int u = 0; u < 2; ++u) {
            int idx = tid * 2 + u;      // 0..511
            int kk = idx >> 5;          // 0..15
            int q  = idx & 31;
            float4 v = ((const float4*)(B + (size_t)(kt + kk) * ldB + colBase))[q];
            ((float4*)&Bs[kk][0])[q] = v;
        }
        __syncthreads();
        #pragma unroll
        for (int kk = 0; kk < BK; ++kk) {
            float a[8], b[8];
            float4 a0 = ((const float4*)&As[kk][0])[ty * 2];
            float4 a1 = ((const float4*)&As[kk][0])[ty * 2 + 1];
            float4 b0 = ((const float4*)&Bs[kk][0])[tx * 2];
            float4 b1 = ((const float4*)&Bs[kk][0])[tx * 2 + 1];
            a[0]=a0.x; a[1]=a0.y; a[2]=a0.z; a[3]=a0.w;
            a[4]=a1.x; a[5]=a1.y; a[6]=a1.z; a[7]=a1.w;
            b[0]=b0.x; b[1]=b0.y; b[2]=b0.z; b[3]=b0.w;
            b[4]=b1.x; b[5]=b1.y; b[6]=b1.z; b[7]=b1.w;
            #pragma unroll
            for (int i = 0; i < 8; ++i)
                #pragma unroll
                for (int j = 0; j < 8; ++j)
                    acc[i][j] += a[i] * b[j];
        }
        __syncthreads();
    }

    // fused epilogue
    #pragma unroll
    for (int i = 0; i < 8; ++i) {
        int m = rowBase + ty * 8 + i;
        if (m >= NN) continue;
        #pragma unroll
        for (int j = 0; j < 8; ++j) {
            int n = colBase + tx * 8 + j;
            float v = acc[i][j] + bias[n];
            if (MODE == 0) {
                float s = 1.f / (1.f + __expf(-v));
                if (n < 128) {
                    outA[(size_t)m * HD + n] = s;                         // z
                } else {
                    int n2 = n - 128;
                    outB[(size_t)m * HD + n2] = s * hbuf[(size_t)m * HD + n2];  // r*h
                }
            } else {
                float ht = tanhf(v);
                float zz = zbuf[(size_t)m * HD + n];
                float hh = hbuf[(size_t)m * HD + n];
                float hn = zz * hh + (1.f - zz) * ht;
                outA[(size_t)m * HD + n] = hn;
                if (outB) outB[(size_t)m * HD + n] = hn;
            }
        }
    }
}

// ---------------- host ----------------
extern "C" void kernel_launch(void* const* d_in, const int* in_sizes, int n_in,
                              void* d_out, int out_size) {
    if (n_in < 15) return;
    const float* x   = (const float*)d_in[0];
    const float* h0  = (const float*)d_in[1];
    const int*   ei  = (const int*)  d_in[2];
    const float* Wxz = (const float*)d_in[3];
    const float* Whz = (const float*)d_in[4];
    const float* Wxr = (const float*)d_in[5];
    const float* Whr = (const float*)d_in[6];
    const float* Wxh = (const float*)d_in[7];
    const float* Whh = (const float*)d_in[8];
    const float* bxz = (const float*)d_in[9];
    const float* bhz = (const float*)d_in[10];
    const float* bxr = (const float*)d_in[11];
    const float* bhr = (const float*)d_in[12];
    const float* bxh = (const float*)d_in[13];
    const float* bhh = (const float*)d_in[14];
    float* out = (float*)d_out;

    float *p_h, *p_aggX, *p_aggH, *p_aggRH, *p_z, *p_rh, *p_Bzr, *p_Bh, *p_bzr, *p_bh;
    cudaGetSymbolAddress((void**)&p_h,     g_h);
    cudaGetSymbolAddress((void**)&p_aggX,  g_aggX);
    cudaGetSymbolAddress((void**)&p_aggH,  g_aggH);
    cudaGetSymbolAddress((void**)&p_aggRH, g_aggRH);
    cudaGetSymbolAddress((void**)&p_z,     g_z);
    cudaGetSymbolAddress((void**)&p_rh,    g_rh);
    cudaGetSymbolAddress((void**)&p_Bzr,   g_Bzr);
    cudaGetSymbolAddress((void**)&p_Bh,    g_Bh);
    cudaGetSymbolAddress((void**)&p_bzr,   g_bzr);
    cudaGetSymbolAddress((void**)&p_bh,    g_bh);

    // ---- setup (re-done every launch; deterministic up to fp add order) ----
    k_zero_counts<<<(NN + 255) / 256, 256>>>();
    k_count<<<(NE + 255) / 256, 256>>>(ei);
    k_dinv<<<(NN + 255) / 256, 256>>>();
    k_scan<<<1, 1024>>>();
    k_fill<<<(NE + 255) / 256, 256>>>(ei);
    {
        int tot = NL * 256 * 256 + NL * 256 * 128;
        k_pack<<<(tot + 255) / 256, 256>>>(Wxz, Whz, Wxr, Whr, Wxh, Whh);
    }
    k_bias<<<2, 256>>>(bxz, bhz, bxr, bhr, bxh, bhh);
    k_copy_h0<<<(NL * NN * HD / 4 + 255) / 256, 256>>>((const float4*)h0);

    // ---- recurrence ----
    const int spmm_blocks = (NN + 7) / 8;     // 8 warps/block
    const int gM = (NN + BM - 1) / BM;        // 391
    for (int t = 0; t < NT; ++t) {
        for (int l = 0; l < NL; ++l) {
            const float* inp = (l == 0) ? (x + (size_t)t * NN * HD) : p_h;  // g_h[0]
            float* h = p_h + (size_t)l * NN * HD;

            k_spmm<<<spmm_blocks, 256>>>(inp, p_aggX);
            k_spmm<<<spmm_blocks, 256>>>(h,   p_aggH);

            k_gemm<0><<<dim3(gM, 2), 256>>>(p_aggX, p_aggH,
                                            p_Bzr + (size_t)l * 256 * 256,
                                            p_bzr + (size_t)l * 256,
                                            h, nullptr, p_z, p_rh, 256);

            k_spmm<<<spmm_blocks, 256>>>(p_rh, p_aggRH);

            float* out2 = (l == NL - 1) ? (out + (size_t)t * NN * HD) : nullptr;
            k_gemm<1><<<dim3(gM, 1), 256>>>(p_aggX, p_aggRH,
                                            p_Bh + (size_t)l * 256 * 128,
                                            p_bh + (size_t)l * 128,
                                            h, p_z, h, out2, 128);
        }
    }
}

// round 3
// speedup vs baseline: 1.5128x; 1.5128x over previous
#include <cuda_runtime.h>
#include <cuda_bf16.h>
#include <math.h>
#include <stdint.h>

#define NT 8
#define NN 50000
#define NE 800000
#define HD 128
#define NL 2

__device__ __forceinline__ uint32_t smem_u32(const void* p) {
    uint32_t a;
    asm("{ .reg .u64 t; cvta.to.shared.u64 t, %1; cvt.u32.u64 %0, t; }" : "=r"(a) : "l"(p));
    return a;
}
__device__ __forceinline__ float sigf(float x) { return 1.f / (1.f + __expf(-x)); }

__device__ __forceinline__ void mma16816(float* d, const uint32_t* a, const uint32_t* b) {
    asm volatile("mma.sync.aligned.m16n8k16.row.col.f32.bf16.bf16.f32 "
        "{%0,%1,%2,%3}, {%4,%5,%6,%7}, {%8,%9}, {%0,%1,%2,%3};"
        : "+f"(d[0]), "+f"(d[1]), "+f"(d[2]), "+f"(d[3])
        : "r"(a[0]), "r"(a[1]), "r"(a[2]), "r"(a[3]), "r"(b[0]), "r"(b[1]));
}
__device__ __forceinline__ void ldsm4(uint32_t* r, uint32_t addr) {
    asm volatile("ldmatrix.sync.aligned.m8n8.x4.shared.b16 {%0,%1,%2,%3}, [%4];"
        : "=r"(r[0]), "=r"(r[1]), "=r"(r[2]), "=r"(r[3]) : "r"(addr));
}

// ================= static device scratch =================
__device__ float g_h[NL][NN * HD];
__device__ float g_z[NN * HD];
__device__ float g_rh[NN * HD];
__device__ __align__(128) __nv_bfloat16 g_aXh[NN * HD];
__device__ __align__(128) __nv_bfloat16 g_aXl[NN * HD];
__device__ __align__(128) __nv_bfloat16 g_aYh[NN * HD];
__device__ __align__(128) __nv_bfloat16 g_aYl[NN * HD];
__device__ __align__(128) __nv_bfloat16 g_aRh[NN * HD];
__device__ __align__(128) __nv_bfloat16 g_aRl[NN * HD];
__device__ int   g_cnt[NN];
__device__ int   g_cur[NN];
__device__ int   g_offs[NN + 1];
__device__ float g_dinv[NN];
__device__ int   g_ccol[NE];
__device__ float g_cw[NE];
__device__ int   g_bsum[64];
__device__ int   g_bbase[64];
// packed B: [N][K=256] bf16 hi/lo
__device__ __align__(128) __nv_bfloat16 g_Bzr_hi[NL * 256 * 256];
__device__ __align__(128) __nv_bfloat16 g_Bzr_lo[NL * 256 * 256];
__device__ __align__(128) __nv_bfloat16 g_Bh_hi[NL * 128 * 256];
__device__ __align__(128) __nv_bfloat16 g_Bh_lo[NL * 128 * 256];
__device__ float g_bzr[NL][256];
__device__ float g_bh [NL][128];

// ================= setup kernels =================
__global__ void k_zero_counts() {
    int i = blockIdx.x * blockDim.x + threadIdx.x;
    if (i < NN) { g_cnt[i] = 0; g_cur[i] = 0; }
}
__global__ void k_count(const int* __restrict__ ei) {
    int e = blockIdx.x * blockDim.x + threadIdx.x;
    if (e < NE) atomicAdd(&g_cnt[ei[e]], 1);
}
__global__ void k_dinv() {
    int i = blockIdx.x * blockDim.x + threadIdx.x;
    if (i < NN) g_dinv[i] = rsqrtf((float)(g_cnt[i] + 2));
}
__global__ void k_scan1() {
    __shared__ int s[1024];
    int t = threadIdx.x;
    int i = blockIdx.x * 1024 + t;
    int v = (i < NN) ? g_cnt[i] : 0;
    s[t] = v; __syncthreads();
    #pragma unroll
    for (int off = 1; off < 1024; off <<= 1) {
        int x = (t >= off) ? s[t - off] : 0;
        __syncthreads(); s[t] += x; __syncthreads();
    }
    if (i < NN) g_offs[i] = s[t] - v;
    if (t == 1023) g_bsum[blockIdx.x] = s[1023];
}
__global__ void k_scan2() {
    __shared__ int s[64];
    int t = threadIdx.x;
    const int NB = (NN + 1023) / 1024;
    int v = (t < NB) ? g_bsum[t] : 0;
    s[t] = v; __syncthreads();
    #pragma unroll
    for (int off = 1; off < 64; off <<= 1) {
        int x = (t >= off) ? s[t - off] : 0;
        __syncthreads(); s[t] += x; __syncthreads();
    }
    if (t < NB) g_bbase[t] = s[t] - v;
    if (t == 63) g_offs[NN] = s[63];
}
__global__ void k_scan3() {
    int i = blockIdx.x * 1024 + threadIdx.x;
    if (i < NN) g_offs[i] += g_bbase[blockIdx.x];
}
__global__ void k_fill(const int* __restrict__ ei) {
    int e = blockIdx.x * blockDim.x + threadIdx.x;
    if (e < NE) {
        int r = ei[e];
        int c = ei[NE + e];
        int pos = g_offs[r] + atomicAdd(&g_cur[r], 1);
        g_ccol[pos] = c;
        g_cw[pos] = g_dinv[r] * g_dinv[c];
    }
}
__global__ void k_pack(const float* __restrict__ Wxz, const float* __restrict__ Whz,
                       const float* __restrict__ Wxr, const float* __restrict__ Whr,
                       const float* __restrict__ Wxh, const float* __restrict__ Whh) {
    int i = blockIdx.x * blockDim.x + threadIdx.x;
    const int ZR = NL * 256 * 256;
    const int HSZ = NL * 128 * 256;
    if (i < ZR) {
        int l = i / (256 * 256);
        int nk = i % (256 * 256);
        int n = nk / 256, k = nk % 256;
        const float* W = (k < 128) ? ((n < 128) ? Wxz : Wxr)
                                   : ((n < 128) ? Whz : Whr);
        float w = W[l * HD * HD + (k & 127) * HD + (n & 127)];
        __nv_bfloat16 hi = __float2bfloat16_rn(w);
        __nv_bfloat16 lo = __float2bfloat16_rn(w - __bfloat162float(hi));
        g_Bzr_hi[l * 256 * 256 + nk] = hi;
        g_Bzr_lo[l * 256 * 256 + nk] = lo;
    } else if (i < ZR + HSZ) {
        int i2 = i - ZR;
        int l = i2 / (128 * 256);
        int nk = i2 % (128 * 256);
        int n = nk / 256, k = nk % 256;
        const float* W = (k < 128) ? Wxh : Whh;
        float w = W[l * HD * HD + (k & 127) * HD + n];
        __nv_bfloat16 hi = __float2bfloat16_rn(w);
        __nv_bfloat16 lo = __float2bfloat16_rn(w - __bfloat162float(hi));
        g_Bh_hi[l * 128 * 256 + nk] = hi;
        g_Bh_lo[l * 128 * 256 + nk] = lo;
    }
}
__global__ void k_bias(const float* __restrict__ bxz, const float* __restrict__ bhz,
                       const float* __restrict__ bxr, const float* __restrict__ bhr,
                       const float* __restrict__ bxh, const float* __restrict__ bhh) {
    int i = blockIdx.x * blockDim.x + threadIdx.x;
    if (i < NL * 256) {
        int l = i / 256, j = i % 256;
        g_bzr[l][j] = (j < 128) ? (bxz[l * HD + j] + bhz[l * HD + j])
                                : (bxr[l * HD + j - 128] + bhr[l * HD + j - 128]);
    }
    if (i < NL * 128) {
        int l = i / 128, j = i % 128;
        g_bh[l][j] = bxh[l * HD + j] + bhh[l * HD + j];
    }
}
__global__ void k_copy_h0(const float4* __restrict__ h0) {
    int i = blockIdx.x * blockDim.x + threadIdx.x;
    if (i < NL * NN * HD / 4) ((float4*)&g_h[0][0])[i] = h0[i];
}

// ================= SpMM: fp32 gather -> bf16 hi/lo planes =================
__global__ void __launch_bounds__(256) k_spmm(const float* __restrict__ src,
                                              __nv_bfloat16* __restrict__ ohi,
                                              __nv_bfloat16* __restrict__ olo) {
    int warp = (blockIdx.x * blockDim.x + threadIdx.x) >> 5;
    int lane = threadIdx.x & 31;
    if (warp >= NN) return;
    const float4* s4 = (const float4*)src;
    float di = g_dinv[warp];
    float4 v = s4[(size_t)warp * 32 + lane];
    float ws = 2.f * di * di;
    float4 acc = make_float4(ws * v.x, ws * v.y, ws * v.z, ws * v.w);
    int e = g_offs[warp], end = g_offs[warp + 1];
    for (; e < end; ++e) {
        int   c = g_ccol[e];
        float w = g_cw[e];
        float4 u = s4[(size_t)c * 32 + lane];
        acc.x += w * u.x; acc.y += w * u.y; acc.z += w * u.z; acc.w += w * u.w;
    }
    __nv_bfloat16 h0 = __float2bfloat16_rn(acc.x);
    __nv_bfloat16 h1 = __float2bfloat16_rn(acc.y);
    __nv_bfloat16 h2 = __float2bfloat16_rn(acc.z);
    __nv_bfloat16 h3 = __float2bfloat16_rn(acc.w);
    __nv_bfloat16 l0 = __float2bfloat16_rn(acc.x - __bfloat162float(h0));
    __nv_bfloat16 l1 = __float2bfloat16_rn(acc.y - __bfloat162float(h1));
    __nv_bfloat16 l2 = __float2bfloat16_rn(acc.z - __bfloat162float(h2));
    __nv_bfloat16 l3 = __float2bfloat16_rn(acc.w - __bfloat162float(h3));
    size_t base = (size_t)warp * HD + lane * 4;
    uint2 wh, wl;
    wh.x = (uint32_t)__bfloat16_as_ushort(h0) | ((uint32_t)__bfloat16_as_ushort(h1) << 16);
    wh.y = (uint32_t)__bfloat16_as_ushort(h2) | ((uint32_t)__bfloat16_as_ushort(h3) << 16);
    wl.x = (uint32_t)__bfloat16_as_ushort(l0) | ((uint32_t)__bfloat16_as_ushort(l1) << 16);
    wl.y = (uint32_t)__bfloat16_as_ushort(l2) | ((uint32_t)__bfloat16_as_ushort(l3) << 16);
    *(uint2*)(ohi + base) = wh;
    *(uint2*)(olo + base) = wl;
}

// ================= HMMA GEMM: C = [Ax|Ay](Mx256) @ W(256xNTOT) via bf16 3-pass split =================
// smem tiles: A hi/lo 128x64, B hi/lo 128x64 (per n-tile of 128), SW128-style xor swizzle.
// MODE 0 (NTOT=256, grid.y=2): cols 0-127 -> z=sigmoid; cols 128-255 -> rh=sigmoid*h
// MODE 1 (NTOT=128, grid.y=1): hn = z*h + (1-z)*tanh(v) -> outA (and outB if non-null)
#define SAH 0
#define SAL 16384
#define SBH 32768
#define SBL 49152
#define SBIAS 65536
#define SMEM_GEMM (65536 + 512)

template <int MODE>
__global__ void __launch_bounds__(256) k_mma_gemm(
    const __nv_bfloat16* __restrict__ Axh, const __nv_bfloat16* __restrict__ Axl,
    const __nv_bfloat16* __restrict__ Ayh, const __nv_bfloat16* __restrict__ Ayl,
    const __nv_bfloat16* __restrict__ Bhi, const __nv_bfloat16* __restrict__ Blo,
    const float* __restrict__ bias, const float* __restrict__ hbuf,
    const float* __restrict__ zbuf, float* __restrict__ outA, float* __restrict__ outB) {

    extern __shared__ char smem[];
    uint32_t sb = smem_u32(smem);
    float* biasS = (float*)(smem + SBIAS);
    int tid = threadIdx.x;
    int lane = tid & 31, warp = tid >> 5;
    int wm = warp >> 2, wn = warp & 3;          // 2 x 4 warp grid; warp tile 64x32
    int rowBase = blockIdx.x * 128;
    int nTile = blockIdx.y * 128;

    if (tid < 128) biasS[tid] = bias[nTile + tid];

    float acc[4][4][4];
    #pragma unroll
    for (int i = 0; i < 4; ++i)
        #pragma unroll
        for (int j = 0; j < 4; ++j)
            #pragma unroll
            for (int q = 0; q < 4; ++q) acc[i][j][q] = 0.f;

    const uint32_t swx = (uint32_t)(lane & 7) << 4;   // swizzle xor, constant per thread

    #pragma unroll 1
    for (int kc = 0; kc < 4; ++kc) {
        const __nv_bfloat16* Aph = (kc < 2) ? Axh : Ayh;
        const __nv_bfloat16* Apl = (kc < 2) ? Axl : Ayl;
        int kgA = (kc & 1) * 64;
        #pragma unroll
        for (int u = 0; u < 4; ++u) {
            int idx = u * 256 + tid;            // 0..1023
            int row = idx >> 3, c = idx & 7;
            int gm = rowBase + row;
            uint4 z4 = make_uint4(0, 0, 0, 0);
            size_t gofs = (size_t)gm * HD + kgA + c * 8;
            uint4 vh = (gm < NN) ? *(const uint4*)(Aph + gofs) : z4;
            uint4 vl = (gm < NN) ? *(const uint4*)(Apl + gofs) : z4;
            uint32_t soff = (uint32_t)row * 128 + (((uint32_t)c * 16) ^ (((uint32_t)row & 7) << 4));
            *(uint4*)(smem + SAH + soff) = vh;
            *(uint4*)(smem + SAL + soff) = vl;
            int gn = nTile + row;
            size_t bofs = (size_t)gn * 256 + kc * 64 + c * 8;
            *(uint4*)(smem + SBH + soff) = *(const uint4*)(Bhi + bofs);
            *(uint4*)(smem + SBL + soff) = *(const uint4*)(Blo + bofs);
        }
        __syncthreads();

        #pragma unroll
        for (int p = 0; p < 3; ++p) {
            uint32_t aBase = sb + ((p == 1) ? SAL : SAH);
            uint32_t bBase = sb + ((p == 2) ? SBL : SBH);
            #pragma unroll
            for (int kk = 0; kk < 4; ++kk) {
                uint32_t a[4][4];
                #pragma unroll
                for (int i = 0; i < 4; ++i) {
                    uint32_t m = (uint32_t)(wm * 64 + i * 16 + (lane & 15));
                    uint32_t k2 = (uint32_t)(kk * 16 + ((lane & 16) >> 1)) * 2;
                    ldsm4(a[i], aBase + m * 128 + (k2 ^ swx));
                }
                uint32_t b[4][2];
                #pragma unroll
                for (int jj = 0; jj < 2; ++jj) {
                    uint32_t n = (uint32_t)(wn * 32 + jj * 16 + (lane & 7) + ((lane & 16) >> 1));
                    uint32_t k2 = (uint32_t)(kk * 16 + (lane & 8)) * 2;
                    uint32_t r[4];
                    ldsm4(r, bBase + n * 128 + (k2 ^ swx));
                    b[jj * 2][0] = r[0]; b[jj * 2][1] = r[1];
                    b[jj * 2 + 1][0] = r[2]; b[jj * 2 + 1][1] = r[3];
                }
                #pragma unroll
                for (int i = 0; i < 4; ++i)
                    #pragma unroll
                    for (int j = 0; j < 4; ++j)
                        mma16816(acc[i][j], a[i], b[j]);
            }
        }
        __syncthreads();
    }

    // ---------- fused epilogue ----------
    #pragma unroll
    for (int i = 0; i < 4; ++i) {
        #pragma unroll
        for (int j = 0; j < 4; ++j) {
            int cl = wn * 32 + j * 8 + (lane & 3) * 2;   // tile-local col (even)
            int c0 = nTile + cl;                          // global col in [0,NTOT)
            float bs0 = biasS[cl], bs1 = biasS[cl + 1];
            #pragma unroll
            for (int half = 0; half < 2; ++half) {
                int m0 = rowBase + wm * 64 + i * 16 + (lane >> 2) + half * 8;
                if (m0 >= NN) continue;
                float v0 = acc[i][j][half * 2 + 0] + bs0;
                float v1 = acc[i][j][half * 2 + 1] + bs1;
                if (MODE == 0) {
                    if (c0 < 128) {
                        *(float2*)(outA + (size_t)m0 * HD + c0) =
                            make_float2(sigf(v0), sigf(v1));
                    } else {
                        int n2 = c0 - 128;
                        float2 hv = *(const float2*)(hbuf + (size_t)m0 * HD + n2);
                        *(float2*)(outB + (size_t)m0 * HD + n2) =
                            make_float2(sigf(v0) * hv.x, sigf(v1) * hv.y);
                    }
                } else {
                    float2 hv = *(const float2*)(hbuf + (size_t)m0 * HD + c0);
                    float2 zv = *(const float2*)(zbuf + (size_t)m0 * HD + c0);
                    float o0 = zv.x * hv.x + (1.f - zv.x) * tanhf(v0);
                    float o1 = zv.y * hv.y + (1.f - zv.y) * tanhf(v1);
                    *(float2*)(outA + (size_t)m0 * HD + c0) = make_float2(o0, o1);
                    if (outB)
                        *(float2*)(outB + (size_t)m0 * HD + c0) = make_float2(o0, o1);
                }
            }
        }
    }
}

// ================= host =================
extern "C" void kernel_launch(void* const* d_in, const int* in_sizes, int n_in,
                              void* d_out, int out_size) {
    if (n_in < 15) return;
    const float* x   = (const float*)d_in[0];
    const float* h0  = (const float*)d_in[1];
    const int*   ei  = (const int*)  d_in[2];
    const float* Wxz = (const float*)d_in[3];
    const float* Whz = (const float*)d_in[4];
    const float* Wxr = (const float*)d_in[5];
    const float* Whr = (const float*)d_in[6];
    const float* Wxh = (const float*)d_in[7];
    const float* Whh = (const float*)d_in[8];
    const float* bxz = (const float*)d_in[9];
    const float* bhz = (const float*)d_in[10];
    const float* bxr = (const float*)d_in[11];
    const float* bhr = (const float*)d_in[12];
    const float* bxh = (const float*)d_in[13];
    const float* bhh = (const float*)d_in[14];
    float* out = (float*)d_out;

    float *p_h, *p_z, *p_rh, *p_bzr, *p_bh;
    __nv_bfloat16 *p_aXh, *p_aXl, *p_aYh, *p_aYl, *p_aRh, *p_aRl;
    __nv_bfloat16 *p_Bzr_hi, *p_Bzr_lo, *p_Bh_hi, *p_Bh_lo;
    cudaGetSymbolAddress((void**)&p_h,      g_h);
    cudaGetSymbolAddress((void**)&p_z,      g_z);
    cudaGetSymbolAddress((void**)&p_rh,     g_rh);
    cudaGetSymbolAddress((void**)&p_aXh,    g_aXh);
    cudaGetSymbolAddress((void**)&p_aXl,    g_aXl);
    cudaGetSymbolAddress((void**)&p_aYh,    g_aYh);
    cudaGetSymbolAddress((void**)&p_aYl,    g_aYl);
    cudaGetSymbolAddress((void**)&p_aRh,    g_aRh);
    cudaGetSymbolAddress((void**)&p_aRl,    g_aRl);
    cudaGetSymbolAddress((void**)&p_Bzr_hi, g_Bzr_hi);
    cudaGetSymbolAddress((void**)&p_Bzr_lo, g_Bzr_lo);
    cudaGetSymbolAddress((void**)&p_Bh_hi,  g_Bh_hi);
    cudaGetSymbolAddress((void**)&p_Bh_lo,  g_Bh_lo);
    cudaGetSymbolAddress((void**)&p_bzr,    g_bzr);
    cudaGetSymbolAddress((void**)&p_bh,     g_bh);

    cudaFuncSetAttribute(k_mma_gemm<0>, cudaFuncAttributeMaxDynamicSharedMemorySize, SMEM_GEMM);
    cudaFuncSetAttribute(k_mma_gemm<1>, cudaFuncAttributeMaxDynamicSharedMemorySize, SMEM_GEMM);

    // ---- setup ----
    const int NB = (NN + 1023) / 1024;  // 49
    k_zero_counts<<<(NN + 255) / 256, 256>>>();
    k_count<<<(NE + 255) / 256, 256>>>(ei);
    k_dinv<<<(NN + 255) / 256, 256>>>();
    k_scan1<<<NB, 1024>>>();
    k_scan2<<<1, 64>>>();
    k_scan3<<<NB, 1024>>>();
    k_fill<<<(NE + 255) / 256, 256>>>(ei);
    {
        int tot = NL * 256 * 256 + NL * 128 * 256;
        k_pack<<<(tot + 255) / 256, 256>>>(Wxz, Whz, Wxr, Whr, Wxh, Whh);
    }
    k_bias<<<2, 256>>>(bxz, bhz, bxr, bhr, bxh, bhh);
    k_copy_h0<<<(NL * NN * HD / 4 + 255) / 256, 256>>>((const float4*)h0);

    // ---- recurrence ----
    const int spmm_blocks = (NN + 7) / 8;
    const int gM = (NN + 127) / 128;  // 391
    for (int t = 0; t < NT; ++t) {
        for (int l = 0; l < NL; ++l) {
            const float* inp = (l == 0) ? (x + (size_t)t * NN * HD) : p_h;
            float* h = p_h + (size_t)l * NN * HD;

            k_spmm<<<spmm_blocks, 256>>>(inp, p_aXh, p_aXl);
            k_spmm<<<spmm_blocks, 256>>>(h,   p_aYh, p_aYl);

            k_mma_gemm<0><<<dim3(gM, 2), 256, SMEM_GEMM>>>(
                p_aXh, p_aXl, p_aYh, p_aYl,
                p_Bzr_hi + (size_t)l * 256 * 256, p_Bzr_lo + (size_t)l * 256 * 256,
                p_bzr + (size_t)l * 256, h, nullptr, p_z, p_rh);

            k_spmm<<<spmm_blocks, 256>>>(p_rh, p_aRh, p_aRl);

            float* out2 = (l == NL - 1) ? (out + (size_t)t * NN * HD) : nullptr;
            k_mma_gemm<1><<<dim3(gM, 1), 256, SMEM_GEMM>>>(
                p_aXh, p_aXl, p_aRh, p_aRl,
                p_Bh_hi + (size_t)l * 128 * 256, p_Bh_lo + (size_t)l * 128 * 256,
                p_bh + (size_t)l * 128, h, p_z, h, out2);
        }
    }
}

// round 4
// speedup vs baseline: 2.0410x; 1.3492x over previous
#include <cuda_runtime.h>
#include <cuda_bf16.h>
#include <math.h>
#include <stdint.h>

#define NT 8
#define NN 50000
#define NE 800000
#define HD 128
#define NL 2

__device__ __forceinline__ uint32_t smem_u32(const void* p) {
    uint32_t a;
    asm("{ .reg .u64 t; cvta.to.shared.u64 t, %1; cvt.u32.u64 %0, t; }" : "=r"(a) : "l"(p));
    return a;
}
__device__ __forceinline__ float sigf(float x) { return 1.f / (1.f + __expf(-x)); }

__device__ __forceinline__ void mma16816(float* d, const uint32_t* a, const uint32_t* b) {
    asm volatile("mma.sync.aligned.m16n8k16.row.col.f32.bf16.bf16.f32 "
        "{%0,%1,%2,%3}, {%4,%5,%6,%7}, {%8,%9}, {%0,%1,%2,%3};"
        : "+f"(d[0]), "+f"(d[1]), "+f"(d[2]), "+f"(d[3])
        : "r"(a[0]), "r"(a[1]), "r"(a[2]), "r"(a[3]), "r"(b[0]), "r"(b[1]));
}
__device__ __forceinline__ void ldsm4(uint32_t* r, uint32_t addr) {
    asm volatile("ldmatrix.sync.aligned.m8n8.x4.shared.b16 {%0,%1,%2,%3}, [%4];"
        : "=r"(r[0]), "=r"(r[1]), "=r"(r[2]), "=r"(r[3]) : "r"(addr));
}
__device__ __forceinline__ void cpa16(uint32_t dst, const void* src, bool pred) {
    asm volatile("cp.async.cg.shared.global [%0], [%1], 16, %2;"
        :: "r"(dst), "l"(__cvta_generic_to_global(src)), "r"(pred ? 16 : 0) : "memory");
}
#define CP_COMMIT() asm volatile("cp.async.commit_group;" ::: "memory")
#define CP_WAIT1()  asm volatile("cp.async.wait_group 1;" ::: "memory")

// ================= static device scratch =================
__device__ float g_h[NL][NN * HD];
__device__ float g_z[NN * HD];
__device__ float g_rh[NN * HD];
__device__ __align__(128) __nv_bfloat16 g_aXh[NN * HD];
__device__ __align__(128) __nv_bfloat16 g_aXl[NN * HD];
__device__ __align__(128) __nv_bfloat16 g_aYh[NN * HD];
__device__ __align__(128) __nv_bfloat16 g_aYl[NN * HD];
__device__ __align__(128) __nv_bfloat16 g_aRh[NN * HD];
__device__ __align__(128) __nv_bfloat16 g_aRl[NN * HD];
__device__ int   g_cnt[NN];
__device__ int   g_cur[NN];
__device__ int   g_offs[NN + 1];
__device__ float g_dinv[NN];
__device__ int2  g_epack[NE];             // (col, weight-bits)
__device__ int   g_bsum[64];
__device__ int   g_bbase[64];
__device__ __align__(128) __nv_bfloat16 g_Bzr_hi[NL * 256 * 256];
__device__ __align__(128) __nv_bfloat16 g_Bzr_lo[NL * 256 * 256];
__device__ __align__(128) __nv_bfloat16 g_Bh_hi[NL * 128 * 256];
__device__ __align__(128) __nv_bfloat16 g_Bh_lo[NL * 128 * 256];
__device__ float g_bzr[NL][256];
__device__ float g_bh [NL][128];

// ================= setup kernels =================
__global__ void k_zero() {
    int i = blockIdx.x * blockDim.x + threadIdx.x;
    if (i < NN) { g_cnt[i] = 0; g_cur[i] = 0; }
}
__global__ void k_count(const int* __restrict__ ei) {
    int e = blockIdx.x * blockDim.x + threadIdx.x;
    if (e < NE) atomicAdd(&g_cnt[ei[e]], 1);
}
__global__ void k_scan1() {
    __shared__ int s[1024];
    int t = threadIdx.x;
    int i = blockIdx.x * 1024 + t;
    int v = (i < NN) ? g_cnt[i] : 0;
    if (i < NN) g_dinv[i] = rsqrtf((float)(v + 2));
    s[t] = v; __syncthreads();
    #pragma unroll
    for (int off = 1; off < 1024; off <<= 1) {
        int x = (t >= off) ? s[t - off] : 0;
        __syncthreads(); s[t] += x; __syncthreads();
    }
    if (i < NN) g_offs[i] = s[t] - v;
    if (t == 1023) g_bsum[blockIdx.x] = s[1023];
}
__global__ void k_scan2() {
    __shared__ int s[64];
    int t = threadIdx.x;
    const int NB = (NN + 1023) / 1024;
    int v = (t < NB) ? g_bsum[t] : 0;
    s[t] = v; __syncthreads();
    #pragma unroll
    for (int off = 1; off < 64; off <<= 1) {
        int x = (t >= off) ? s[t - off] : 0;
        __syncthreads(); s[t] += x; __syncthreads();
    }
    if (t < NB) g_bbase[t] = s[t] - v;
    if (t == 63) g_offs[NN] = s[63];
}
__global__ void k_scan3() {
    int i = blockIdx.x * 1024 + threadIdx.x;
    if (i < NN) g_offs[i] += g_bbase[blockIdx.x];
}
__global__ void k_fill(const int* __restrict__ ei) {
    int e = blockIdx.x * blockDim.x + threadIdx.x;
    if (e < NE) {
        int r = ei[e];
        int c = ei[NE + e];
        int pos = g_offs[r] + atomicAdd(&g_cur[r], 1);
        g_epack[pos] = make_int2(c, __float_as_int(g_dinv[r] * g_dinv[c]));
    }
}
// pack weights (hi/lo bf16, B^T layout [N][K]), fold biases, copy h0 — one kernel
__global__ void k_init(const float* __restrict__ Wxz, const float* __restrict__ Whz,
                       const float* __restrict__ Wxr, const float* __restrict__ Whr,
                       const float* __restrict__ Wxh, const float* __restrict__ Whh,
                       const float* __restrict__ bxz, const float* __restrict__ bhz,
                       const float* __restrict__ bxr, const float* __restrict__ bhr,
                       const float* __restrict__ bxh, const float* __restrict__ bhh,
                       const float4* __restrict__ h0) {
    int i = blockIdx.x * blockDim.x + threadIdx.x;
    const int ZR = NL * 256 * 256;          // 131072
    const int HS = NL * 128 * 256;          // 65536
    const int B1 = ZR + HS;
    const int B2 = B1 + NL * 256;
    const int B3 = B2 + NL * 128;
    const int CP = NL * NN * HD / 4;        // 3.2M float4
    if (i < ZR) {
        int l = i / (256 * 256);
        int nk = i % (256 * 256);
        int n = nk / 256, k = nk % 256;
        const float* W = (k < 128) ? ((n < 128) ? Wxz : Wxr)
                                   : ((n < 128) ? Whz : Whr);
        float w = W[l * HD * HD + (k & 127) * HD + (n & 127)];
        __nv_bfloat16 hi = __float2bfloat16_rn(w);
        g_Bzr_hi[l * 256 * 256 + nk] = hi;
        g_Bzr_lo[l * 256 * 256 + nk] = __float2bfloat16_rn(w - __bfloat162float(hi));
    } else if (i < B1) {
        int i2 = i - ZR;
        int l = i2 / (128 * 256);
        int nk = i2 % (128 * 256);
        int n = nk / 256, k = nk % 256;
        const float* W = (k < 128) ? Wxh : Whh;
        float w = W[l * HD * HD + (k & 127) * HD + n];
        __nv_bfloat16 hi = __float2bfloat16_rn(w);
        g_Bh_hi[l * 128 * 256 + nk] = hi;
        g_Bh_lo[l * 128 * 256 + nk] = __float2bfloat16_rn(w - __bfloat162float(hi));
    } else if (i < B2) {
        int i2 = i - B1;
        int l = i2 / 256, j = i2 % 256;
        g_bzr[l][j] = (j < 128) ? (bxz[l * HD + j] + bhz[l * HD + j])
                                : (bxr[l * HD + j - 128] + bhr[l * HD + j - 128]);
    } else if (i < B3) {
        int i2 = i - B2;
        int l = i2 / 128, j = i2 % 128;
        g_bh[l][j] = bxh[l * HD + j] + bhh[l * HD + j];
    } else if (i - B3 < CP) {
        ((float4*)&g_h[0][0])[i - B3] = h0[i - B3];
    }
}

// ================= SpMM helpers =================
__device__ __forceinline__ void store_hl(float4 acc, __nv_bfloat16* oh,
                                         __nv_bfloat16* ol, size_t base) {
    __nv_bfloat16 h0 = __float2bfloat16_rn(acc.x);
    __nv_bfloat16 h1 = __float2bfloat16_rn(acc.y);
    __nv_bfloat16 h2 = __float2bfloat16_rn(acc.z);
    __nv_bfloat16 h3 = __float2bfloat16_rn(acc.w);
    uint2 wh, wl;
    wh.x = (uint32_t)__bfloat16_as_ushort(h0) | ((uint32_t)__bfloat16_as_ushort(h1) << 16);
    wh.y = (uint32_t)__bfloat16_as_ushort(h2) | ((uint32_t)__bfloat16_as_ushort(h3) << 16);
    __nv_bfloat16 l0 = __float2bfloat16_rn(acc.x - __bfloat162float(h0));
    __nv_bfloat16 l1 = __float2bfloat16_rn(acc.y - __bfloat162float(h1));
    __nv_bfloat16 l2 = __float2bfloat16_rn(acc.z - __bfloat162float(h2));
    __nv_bfloat16 l3 = __float2bfloat16_rn(acc.w - __bfloat162float(h3));
    wl.x = (uint32_t)__bfloat16_as_ushort(l0) | ((uint32_t)__bfloat16_as_ushort(l1) << 16);
    wl.y = (uint32_t)__bfloat16_as_ushort(l2) | ((uint32_t)__bfloat16_as_ushort(l3) << 16);
    *(uint2*)(oh + base) = wh;
    *(uint2*)(ol + base) = wl;
}

// dual SpMM: aggregate two sources with one edge pass
__global__ void __launch_bounds__(256) k_spmm2(
    const float* __restrict__ srcA, const float* __restrict__ srcB,
    __nv_bfloat16* __restrict__ oAh, __nv_bfloat16* __restrict__ oAl,
    __nv_bfloat16* __restrict__ oBh, __nv_bfloat16* __restrict__ oBl) {
    int row = (blockIdx.x * blockDim.x + threadIdx.x) >> 5;
    int lane = threadIdx.x & 31;
    if (row >= NN) return;
    const float4* sA = (const float4*)srcA;
    const float4* sB = (const float4*)srcB;
    float di = g_dinv[row];
    float ws = 2.f * di * di;
    float4 a0 = sA[(size_t)row * 32 + lane];
    float4 b0 = sB[(size_t)row * 32 + lane];
    float4 accA = make_float4(ws * a0.x, ws * a0.y, ws * a0.z, ws * a0.w);
    float4 accB = make_float4(ws * b0.x, ws * b0.y, ws * b0.z, ws * b0.w);
    int e = g_offs[row], end = g_offs[row + 1];
    #pragma unroll 2
    for (; e < end; ++e) {
        int2 ew = g_epack[e];
        float w = __int_as_float(ew.y);
        float4 u = sA[(size_t)ew.x * 32 + lane];
        float4 v = sB[(size_t)ew.x * 32 + lane];
        accA.x += w * u.x; accA.y += w * u.y; accA.z += w * u.z; accA.w += w * u.w;
        accB.x += w * v.x; accB.y += w * v.y; accB.z += w * v.z; accB.w += w * v.w;
    }
    size_t base = (size_t)row * HD + lane * 4;
    store_hl(accA, oAh, oAl, base);
    store_hl(accB, oBh, oBl, base);
}

// single SpMM (for r*h)
__global__ void __launch_bounds__(256) k_spmm(const float* __restrict__ src,
                                              __nv_bfloat16* __restrict__ ohi,
                                              __nv_bfloat16* __restrict__ olo) {
    int row = (blockIdx.x * blockDim.x + threadIdx.x) >> 5;
    int lane = threadIdx.x & 31;
    if (row >= NN) return;
    const float4* s4 = (const float4*)src;
    float di = g_dinv[row];
    float4 v = s4[(size_t)row * 32 + lane];
    float ws = 2.f * di * di;
    float4 acc = make_float4(ws * v.x, ws * v.y, ws * v.z, ws * v.w);
    int e = g_offs[row], end = g_offs[row + 1];
    #pragma unroll 2
    for (; e < end; ++e) {
        int2 ew = g_epack[e];
        float w = __int_as_float(ew.y);
        float4 u = s4[(size_t)ew.x * 32 + lane];
        acc.x += w * u.x; acc.y += w * u.y; acc.z += w * u.z; acc.w += w * u.w;
    }
    store_hl(acc, ohi, olo, (size_t)row * HD + lane * 4);
}

// ================= pipelined HMMA GEMM =================
// C = [Ax|Ay](Mx256) @ W(256xNTOT), bf16 3-term split (hi*hi + hi*lo + lo*hi).
// 8 K-stages of 32; per-stage smem: A 128rows x (hi64B|lo64B), B 128rows x (hi64B|lo64B).
// Double-buffered with cp.async. SW128-style xor swizzle per 128B row.
// MODE 0 (grid.y=2): n<128 -> z=sigmoid(v); n>=128 -> rh=sigmoid(v)*h
// MODE 1 (grid.y=1): hn = z*h + (1-z)*tanh(v)
#define SMEM_GEMM (65536 + 512)

template <int MODE>
__global__ void __launch_bounds__(256) k_mma_gemm(
    const __nv_bfloat16* __restrict__ Axh, const __nv_bfloat16* __restrict__ Axl,
    const __nv_bfloat16* __restrict__ Ayh, const __nv_bfloat16* __restrict__ Ayl,
    const __nv_bfloat16* __restrict__ Bhi, const __nv_bfloat16* __restrict__ Blo,
    const float* __restrict__ bias, const float* __restrict__ hbuf,
    const float* __restrict__ zbuf, float* __restrict__ outA, float* __restrict__ outB) {

    extern __shared__ char smem[];
    uint32_t sb = smem_u32(smem);
    float* biasS = (float*)(smem + 65536);
    int tid = threadIdx.x;
    int lane = tid & 31, warp = tid >> 5;
    int wm = warp >> 2, wn = warp & 3;          // 2x4 warps, 64x32 warp tile
    int rowBase = blockIdx.x * 128;
    int nTile = blockIdx.y * 128;

    if (tid < 128) biasS[tid] = bias[nTile + tid];

    float acc[4][4][4];
    #pragma unroll
    for (int i = 0; i < 4; ++i)
        #pragma unroll
        for (int j = 0; j < 4; ++j)
            #pragma unroll
            for (int q = 0; q < 4; ++q) acc[i][j][q] = 0.f;

    const uint32_t swx = (uint32_t)(lane & 7) << 4;

    auto prefetch = [&](int s, int b) {
        const __nv_bfloat16* Aph = (s < 4) ? Axh : Ayh;
        const __nv_bfloat16* Apl = (s < 4) ? Axl : Ayl;
        int ka = (s & 3) * 32;
        int kb = s * 32;
        #pragma unroll
        for (int u = 0; u < 4; ++u) {
            int idx = u * 256 + tid;            // A: 1024 x 16B
            int row = idx >> 3, c = idx & 7;
            int gm = rowBase + row;
            const __nv_bfloat16* src = ((c < 4) ? Aph : Apl) + (size_t)gm * HD + ka + (c & 3) * 8;
            uint32_t dst = sb + b * 32768 + (uint32_t)row * 128 +
                           (((uint32_t)c * 16) ^ (((uint32_t)row & 7) << 4));
            cpa16(dst, src, gm < NN);
        }
        #pragma unroll
        for (int u = 0; u < 4; ++u) {
            int idx = u * 256 + tid;            // B: 1024 x 16B
            int row = idx >> 3, c = idx & 7;
            int gn = nTile + row;
            const __nv_bfloat16* src = ((c < 4) ? Bhi : Blo) + (size_t)gn * 256 + kb + (c & 3) * 8;
            uint32_t dst = sb + b * 32768 + 16384 + (uint32_t)row * 128 +
                           (((uint32_t)c * 16) ^ (((uint32_t)row & 7) << 4));
            cpa16(dst, src, true);
        }
    };

    prefetch(0, 0); CP_COMMIT();
    prefetch(1, 1); CP_COMMIT();

    #pragma unroll 1
    for (int s = 0; s < 8; ++s) {
        CP_WAIT1();
        __syncthreads();
        uint32_t aBase = sb + (uint32_t)(s & 1) * 32768;
        uint32_t bBase = aBase + 16384;
        #pragma unroll
        for (int kk = 0; kk < 2; ++kk) {
            uint32_t ah[4][4], al[4][4], bh[4][2], bl[4][2];
            #pragma unroll
            for (int i = 0; i < 4; ++i) {
                uint32_t m = (uint32_t)(wm * 64 + i * 16 + (lane & 15));
                uint32_t kab = (uint32_t)(kk * 32 + (lane & 16));
                ldsm4(ah[i], aBase + m * 128 + (kab ^ swx));
                ldsm4(al[i], aBase + m * 128 + ((64 + kab) ^ swx));
            }
            #pragma unroll
            for (int jj = 0; jj < 2; ++jj) {
                uint32_t n = (uint32_t)(wn * 32 + jj * 16 + (lane & 7) + ((lane & 16) >> 1));
                uint32_t kbb = (uint32_t)(kk * 32 + ((lane & 8) << 1));
                uint32_t r[4];
                ldsm4(r, bBase + n * 128 + (kbb ^ swx));
                bh[jj * 2][0] = r[0]; bh[jj * 2][1] = r[1];
                bh[jj * 2 + 1][0] = r[2]; bh[jj * 2 + 1][1] = r[3];
                ldsm4(r, bBase + n * 128 + ((64 + kbb) ^ swx));
                bl[jj * 2][0] = r[0]; bl[jj * 2][1] = r[1];
                bl[jj * 2 + 1][0] = r[2]; bl[jj * 2 + 1][1] = r[3];
            }
            #pragma unroll
            for (int i = 0; i < 4; ++i)
                #pragma unroll
                for (int j = 0; j < 4; ++j) {
                    mma16816(acc[i][j], ah[i], bh[j]);   // hi*hi
                    mma16816(acc[i][j], ah[i], bl[j]);   // hi*lo
                    mma16816(acc[i][j], al[i], bh[j]);   // lo*hi
                }
        }
        __syncthreads();
        if (s < 6) prefetch(s + 2, s & 1);
        CP_COMMIT();
    }

    // ---------- fused epilogue ----------
    #pragma unroll
    for (int i = 0; i < 4; ++i) {
        #pragma unroll
        for (int j = 0; j < 4; ++j) {
            int cl = wn * 32 + j * 8 + (lane & 3) * 2;
            int c0 = nTile + cl;
            float bs0 = biasS[cl], bs1 = biasS[cl + 1];
            #pragma unroll
            for (int half = 0; half < 2; ++half) {
                int m0 = rowBase + wm * 64 + i * 16 + (lane >> 2) + half * 8;
                if (m0 >= NN) continue;
                float v0 = acc[i][j][half * 2 + 0] + bs0;
                float v1 = acc[i][j][half * 2 + 1] + bs1;
                if (MODE == 0) {
                    if (c0 < 128) {
                        *(float2*)(outA + (size_t)m0 * HD + c0) =
                            make_float2(sigf(v0), sigf(v1));
                    } else {
                        int n2 = c0 - 128;
                        float2 hv = *(const float2*)(hbuf + (size_t)m0 * HD + n2);
                        *(float2*)(outB + (size_t)m0 * HD + n2) =
                            make_float2(sigf(v0) * hv.x, sigf(v1) * hv.y);
                    }
                } else {
                    float2 hv = *(const float2*)(hbuf + (size_t)m0 * HD + c0);
                    float2 zv = *(const float2*)(zbuf + (size_t)m0 * HD + c0);
                    float o0 = zv.x * hv.x + (1.f - zv.x) * tanhf(v0);
                    float o1 = zv.y * hv.y + (1.f - zv.y) * tanhf(v1);
                    *(float2*)(outA + (size_t)m0 * HD + c0) = make_float2(o0, o1);
                    if (outB)
                        *(float2*)(outB + (size_t)m0 * HD + c0) = make_float2(o0, o1);
                }
            }
        }
    }
}

// ================= host =================
extern "C" void kernel_launch(void* const* d_in, const int* in_sizes, int n_in,
                              void* d_out, int out_size) {
    if (n_in < 15) return;
    const float* x   = (const float*)d_in[0];
    const float* h0  = (const float*)d_in[1];
    const int*   ei  = (const int*)  d_in[2];
    const float* Wxz = (const float*)d_in[3];
    const float* Whz = (const float*)d_in[4];
    const float* Wxr = (const float*)d_in[5];
    const float* Whr = (const float*)d_in[6];
    const float* Wxh = (const float*)d_in[7];
    const float* Whh = (const float*)d_in[8];
    const float* bxz = (const float*)d_in[9];
    const float* bhz = (const float*)d_in[10];
    const float* bxr = (const float*)d_in[11];
    const float* bhr = (const float*)d_in[12];
    const float* bxh = (const float*)d_in[13];
    const float* bhh = (const float*)d_in[14];
    float* out = (float*)d_out;

    float *p_h, *p_z, *p_rh, *p_bzr, *p_bh;
    __nv_bfloat16 *p_aXh, *p_aXl, *p_aYh, *p_aYl, *p_aRh, *p_aRl;
    __nv_bfloat16 *p_Bzr_hi, *p_Bzr_lo, *p_Bh_hi, *p_Bh_lo;
    cudaGetSymbolAddress((void**)&p_h,      g_h);
    cudaGetSymbolAddress((void**)&p_z,      g_z);
    cudaGetSymbolAddress((void**)&p_rh,     g_rh);
    cudaGetSymbolAddress((void**)&p_aXh,    g_aXh);
    cudaGetSymbolAddress((void**)&p_aXl,    g_aXl);
    cudaGetSymbolAddress((void**)&p_aYh,    g_aYh);
    cudaGetSymbolAddress((void**)&p_aYl,    g_aYl);
    cudaGetSymbolAddress((void**)&p_aRh,    g_aRh);
    cudaGetSymbolAddress((void**)&p_aRl,    g_aRl);
    cudaGetSymbolAddress((void**)&p_Bzr_hi, g_Bzr_hi);
    cudaGetSymbolAddress((void**)&p_Bzr_lo, g_Bzr_lo);
    cudaGetSymbolAddress((void**)&p_Bh_hi,  g_Bh_hi);
    cudaGetSymbolAddress((void**)&p_Bh_lo,  g_Bh_lo);
    cudaGetSymbolAddress((void**)&p_bzr,    g_bzr);
    cudaGetSymbolAddress((void**)&p_bh,     g_bh);

    cudaFuncSetAttribute(k_mma_gemm<0>, cudaFuncAttributeMaxDynamicSharedMemorySize, SMEM_GEMM);
    cudaFuncSetAttribute(k_mma_gemm<1>, cudaFuncAttributeMaxDynamicSharedMemorySize, SMEM_GEMM);

    // ---- setup: 7 launches ----
    const int NB = (NN + 1023) / 1024;  // 49
    k_zero<<<(NN + 255) / 256, 256>>>();
    k_count<<<(NE + 255) / 256, 256>>>(ei);
    k_scan1<<<NB, 1024>>>();
    k_scan2<<<1, 64>>>();
    k_scan3<<<NB, 1024>>>();
    k_fill<<<(NE + 255) / 256, 256>>>(ei);
    {
        int tot = NL * 256 * 256 + NL * 128 * 256 + NL * 256 + NL * 128 + NL * NN * HD / 4;
        k_init<<<(tot + 255) / 256, 256>>>(Wxz, Whz, Wxr, Whr, Wxh, Whh,
                                           bxz, bhz, bxr, bhr, bxh, bhh,
                                           (const float4*)h0);
    }

    // ---- recurrence ----
    const int spmm_blocks = (NN + 7) / 8;
    const int gM = (NN + 127) / 128;  // 391
    for (int t = 0; t < NT; ++t) {
        for (int l = 0; l < NL; ++l) {
            const float* inp = (l == 0) ? (x + (size_t)t * NN * HD) : p_h;
            float* h = p_h + (size_t)l * NN * HD;

            k_spmm2<<<spmm_blocks, 256>>>(inp, h, p_aXh, p_aXl, p_aYh, p_aYl);

            k_mma_gemm<0><<<dim3(gM, 2), 256, SMEM_GEMM>>>(
                p_aXh, p_aXl, p_aYh, p_aYl,
                p_Bzr_hi + (size_t)l * 256 * 256, p_Bzr_lo + (size_t)l * 256 * 256,
                p_bzr + (size_t)l * 256, h, nullptr, p_z, p_rh);

            k_spmm<<<spmm_blocks, 256>>>(p_rh, p_aRh, p_aRl);

            float* out2 = (l == NL - 1) ? (out + (size_t)t * NN * HD) : nullptr;
            k_mma_gemm<1><<<dim3(gM, 1), 256, SMEM_GEMM>>>(
                p_aXh, p_aXl, p_aRh, p_aRl,
                p_Bh_hi + (size_t)l * 128 * 256, p_Bh_lo + (size_t)l * 128 * 256,
                p_bh + (size_t)l * 128, h, p_z, h, out2);
        }
    }
}

// round 5
// speedup vs baseline: 2.1587x; 1.0577x over previous
#include <cuda_runtime.h>
#include <cuda_fp16.h>
#include <math.h>
#include <stdint.h>

#define NT 8
#define NN 50000
#define NE 800000
#define HD 128
#define NL 2

__device__ __forceinline__ uint32_t smem_u32(const void* p) {
    uint32_t a;
    asm("{ .reg .u64 t; cvta.to.shared.u64 t, %1; cvt.u32.u64 %0, t; }" : "=r"(a) : "l"(p));
    return a;
}
__device__ __forceinline__ float sigf(float x) { return 1.f / (1.f + __expf(-x)); }

__device__ __forceinline__ void mma16816(float* d, const uint32_t* a, const uint32_t* b) {
    asm volatile("mma.sync.aligned.m16n8k16.row.col.f32.f16.f16.f32 "
        "{%0,%1,%2,%3}, {%4,%5,%6,%7}, {%8,%9}, {%0,%1,%2,%3};"
        : "+f"(d[0]), "+f"(d[1]), "+f"(d[2]), "+f"(d[3])
        : "r"(a[0]), "r"(a[1]), "r"(a[2]), "r"(a[3]), "r"(b[0]), "r"(b[1]));
}
__device__ __forceinline__ void ldsm4(uint32_t* r, uint32_t addr) {
    asm volatile("ldmatrix.sync.aligned.m8n8.x4.shared.b16 {%0,%1,%2,%3}, [%4];"
        : "=r"(r[0]), "=r"(r[1]), "=r"(r[2]), "=r"(r[3]) : "r"(addr));
}
__device__ __forceinline__ void cpa16(uint32_t dst, const void* src, bool pred) {
    asm volatile("cp.async.cg.shared.global [%0], [%1], 16, %2;"
        :: "r"(dst), "l"(__cvta_generic_to_global(src)), "r"(pred ? 16 : 0) : "memory");
}
#define CP_COMMIT() asm volatile("cp.async.commit_group;" ::: "memory")
#define CP_WAIT1()  asm volatile("cp.async.wait_group 1;" ::: "memory")

__device__ __forceinline__ uint2 packh4(float4 a) {
    __half2 p0 = __float22half2_rn(make_float2(a.x, a.y));
    __half2 p1 = __float22half2_rn(make_float2(a.z, a.w));
    uint2 r;
    r.x = *(uint32_t*)&p0;
    r.y = *(uint32_t*)&p1;
    return r;
}
__device__ __forceinline__ float4 upkh4(uint2 u) {
    float2 f0 = __half22float2(*(__half2*)&u.x);
    float2 f1 = __half22float2(*(__half2*)&u.y);
    return make_float4(f0.x, f0.y, f1.x, f1.y);
}

// ================= static device scratch =================
__device__ float g_h[NL][NN * HD];                 // fp32 hidden (epilogue reads)
__device__ float g_z[NN * HD];                     // z gate fp32
__device__ __align__(128) __half g_xf16[NT * NN * HD];   // fp16 copy of x
__device__ __align__(128) __half g_hf16[NL][NN * HD];    // fp16 copy of h (gather table)
__device__ __align__(128) __half g_rhf16[NN * HD];       // fp16 r*h (gather table)
__device__ __align__(128) __half g_aX[NN * HD];          // fp16 aggregates (GEMM A)
__device__ __align__(128) __half g_aY[NN * HD];
__device__ __align__(128) __half g_aR[NN * HD];
__device__ int   g_cnt[NN];
__device__ int   g_cur[NN];
__device__ int   g_offs[NN + 1];
__device__ float g_dinv[NN];
__device__ int2  g_epack[NE];
__device__ int   g_bsum[64];
__device__ int   g_bbase[64];
// packed B^T [N][K=256] fp16 hi/lo
__device__ __align__(128) __half g_Bzr_hi[NL * 256 * 256];
__device__ __align__(128) __half g_Bzr_lo[NL * 256 * 256];
__device__ __align__(128) __half g_Bh_hi[NL * 128 * 256];
__device__ __align__(128) __half g_Bh_lo[NL * 128 * 256];
__device__ float g_bzr[NL][256];
__device__ float g_bh [NL][128];

// ================= setup kernels =================
__global__ void k_zero() {
    int i = blockIdx.x * blockDim.x + threadIdx.x;
    if (i < NN) { g_cnt[i] = 0; g_cur[i] = 0; }
}
__global__ void k_count(const int* __restrict__ ei) {
    int e = blockIdx.x * blockDim.x + threadIdx.x;
    if (e < NE) atomicAdd(&g_cnt[ei[e]], 1);
}
__global__ void k_scan1() {
    __shared__ int s[1024];
    int t = threadIdx.x;
    int i = blockIdx.x * 1024 + t;
    int v = (i < NN) ? g_cnt[i] : 0;
    if (i < NN) g_dinv[i] = rsqrtf((float)(v + 2));
    s[t] = v; __syncthreads();
    #pragma unroll
    for (int off = 1; off < 1024; off <<= 1) {
        int x = (t >= off) ? s[t - off] : 0;
        __syncthreads(); s[t] += x; __syncthreads();
    }
    if (i < NN) g_offs[i] = s[t] - v;
    if (t == 1023) g_bsum[blockIdx.x] = s[1023];
}
__global__ void k_scan2() {
    __shared__ int s[64];
    int t = threadIdx.x;
    const int NB = (NN + 1023) / 1024;
    int v = (t < NB) ? g_bsum[t] : 0;
    s[t] = v; __syncthreads();
    #pragma unroll
    for (int off = 1; off < 64; off <<= 1) {
        int x = (t >= off) ? s[t - off] : 0;
        __syncthreads(); s[t] += x; __syncthreads();
    }
    if (t < NB) g_bbase[t] = s[t] - v;
    if (t == 63) g_offs[NN] = s[63];
}
__global__ void k_scan3() {
    int i = blockIdx.x * 1024 + threadIdx.x;
    if (i < NN) g_offs[i] += g_bbase[blockIdx.x];
}
__global__ void k_fill(const int* __restrict__ ei) {
    int e = blockIdx.x * blockDim.x + threadIdx.x;
    if (e < NE) {
        int r = ei[e];
        int c = ei[NE + e];
        int pos = g_offs[r] + atomicAdd(&g_cur[r], 1);
        g_epack[pos] = make_int2(c, __float_as_int(g_dinv[r] * g_dinv[c]));
    }
}
__global__ void k_xcvt(const float4* __restrict__ x) {
    int i = blockIdx.x * blockDim.x + threadIdx.x;
    if (i < NT * NN * HD / 4)
        ((uint2*)&g_xf16[0])[i] = packh4(x[i]);
}
// weights fp16 hi/lo [N][K], biases, h0 -> fp32 + fp16
__global__ void k_init(const float* __restrict__ Wxz, const float* __restrict__ Whz,
                       const float* __restrict__ Wxr, const float* __restrict__ Whr,
                       const float* __restrict__ Wxh, const float* __restrict__ Whh,
                       const float* __restrict__ bxz, const float* __restrict__ bhz,
                       const float* __restrict__ bxr, const float* __restrict__ bhr,
                       const float* __restrict__ bxh, const float* __restrict__ bhh,
                       const float4* __restrict__ h0) {
    int i = blockIdx.x * blockDim.x + threadIdx.x;
    const int ZR = NL * 256 * 256;
    const int HS = NL * 128 * 256;
    const int B1 = ZR + HS;
    const int B2 = B1 + NL * 256;
    const int B3 = B2 + NL * 128;
    const int CP = NL * NN * HD / 4;
    if (i < ZR) {
        int l = i / (256 * 256);
        int nk = i % (256 * 256);
        int n = nk / 256, k = nk % 256;
        const float* W = (k < 128) ? ((n < 128) ? Wxz : Wxr)
                                   : ((n < 128) ? Whz : Whr);
        float w = W[l * HD * HD + (k & 127) * HD + (n & 127)];
        __half hi = __float2half_rn(w);
        g_Bzr_hi[l * 256 * 256 + nk] = hi;
        g_Bzr_lo[l * 256 * 256 + nk] = __float2half_rn(w - __half2float(hi));
    } else if (i < B1) {
        int i2 = i - ZR;
        int l = i2 / (128 * 256);
        int nk = i2 % (128 * 256);
        int n = nk / 256, k = nk % 256;
        const float* W = (k < 128) ? Wxh : Whh;
        float w = W[l * HD * HD + (k & 127) * HD + n];
        __half hi = __float2half_rn(w);
        g_Bh_hi[l * 128 * 256 + nk] = hi;
        g_Bh_lo[l * 128 * 256 + nk] = __float2half_rn(w - __half2float(hi));
    } else if (i < B2) {
        int i2 = i - B1;
        int l = i2 / 256, j = i2 % 256;
        g_bzr[l][j] = (j < 128) ? (bxz[l * HD + j] + bhz[l * HD + j])
                                : (bxr[l * HD + j - 128] + bhr[l * HD + j - 128]);
    } else if (i < B3) {
        int i2 = i - B2;
        int l = i2 / 128, j = i2 % 128;
        g_bh[l][j] = bxh[l * HD + j] + bhh[l * HD + j];
    } else if (i - B3 < CP) {
        int j = i - B3;
        float4 v = h0[j];
        ((float4*)&g_h[0][0])[j] = v;
        ((uint2*)&g_hf16[0][0])[j] = packh4(v);
    }
}

// ================= SpMM (fp16 gather -> fp16 aggregate) =================
// dual: aggregate two fp16 sources in one edge pass
__global__ void __launch_bounds__(256) k_spmm2(
    const __half* __restrict__ srcA, const __half* __restrict__ srcB,
    __half* __restrict__ oA, __half* __restrict__ oB) {
    int row = (blockIdx.x * blockDim.x + threadIdx.x) >> 5;
    int lane = threadIdx.x & 31;
    if (row >= NN) return;
    const uint2* sA = (const uint2*)srcA;
    const uint2* sB = (const uint2*)srcB;
    float di = g_dinv[row];
    float ws = 2.f * di * di;
    float4 a0 = upkh4(sA[(size_t)row * 32 + lane]);
    float4 b0 = upkh4(sB[(size_t)row * 32 + lane]);
    float4 accA = make_float4(ws * a0.x, ws * a0.y, ws * a0.z, ws * a0.w);
    float4 accB = make_float4(ws * b0.x, ws * b0.y, ws * b0.z, ws * b0.w);
    int e = g_offs[row], end = g_offs[row + 1];
    #pragma unroll 2
    for (; e < end; ++e) {
        int2 ew = g_epack[e];
        float w = __int_as_float(ew.y);
        float4 u = upkh4(sA[(size_t)ew.x * 32 + lane]);
        float4 v = upkh4(sB[(size_t)ew.x * 32 + lane]);
        accA.x += w * u.x; accA.y += w * u.y; accA.z += w * u.z; accA.w += w * u.w;
        accB.x += w * v.x; accB.y += w * v.y; accB.z += w * v.z; accB.w += w * v.w;
    }
    size_t base = (size_t)row * 32 + lane;
    ((uint2*)oA)[base] = packh4(accA);
    ((uint2*)oB)[base] = packh4(accB);
}

__global__ void __launch_bounds__(256) k_spmm(const __half* __restrict__ src,
                                              __half* __restrict__ o) {
    int row = (blockIdx.x * blockDim.x + threadIdx.x) >> 5;
    int lane = threadIdx.x & 31;
    if (row >= NN) return;
    const uint2* s2 = (const uint2*)src;
    float di = g_dinv[row];
    float ws = 2.f * di * di;
    float4 v0 = upkh4(s2[(size_t)row * 32 + lane]);
    float4 acc = make_float4(ws * v0.x, ws * v0.y, ws * v0.z, ws * v0.w);
    int e = g_offs[row], end = g_offs[row + 1];
    #pragma unroll 2
    for (; e < end; ++e) {
        int2 ew = g_epack[e];
        float w = __int_as_float(ew.y);
        float4 u = upkh4(s2[(size_t)ew.x * 32 + lane]);
        acc.x += w * u.x; acc.y += w * u.y; acc.z += w * u.z; acc.w += w * u.w;
    }
    ((uint2*)o)[(size_t)row * 32 + lane] = packh4(acc);
}

// ================= pipelined HMMA GEMM (fp16 A single-plane, B hi/lo 2-pass) =================
// C = [Ax|Ay](Mx256) @ W(256xNTOT). 4 K-stages of 64, double-buffered cp.async.
// Stage smem: A 128x128B (16KB), Bhi 16KB, Blo 16KB -> 48KB/stage, 96KB total.
// MODE 0 (grid.y=2): n<128 -> z=sigmoid(v) [fp32]; n>=128 -> rh=sigmoid(v)*h [fp16]
// MODE 1 (grid.y=1): hn = z*h+(1-z)*tanh(v) -> h fp32, h fp16, optional out fp32
#define STAGE_B 49152
#define SMEM_GEMM (98304 + 512)

template <int MODE>
__global__ void __launch_bounds__(256) k_mma_gemm(
    const __half* __restrict__ Ax, const __half* __restrict__ Ay,
    const __half* __restrict__ Bhi, const __half* __restrict__ Blo,
    const float* __restrict__ bias, const float* __restrict__ hbuf,
    const float* __restrict__ zbuf, float* __restrict__ outA,
    __half* __restrict__ outH16, float* __restrict__ outB) {

    extern __shared__ char smem[];
    uint32_t sb = smem_u32(smem);
    float* biasS = (float*)(smem + 98304);
    int tid = threadIdx.x;
    int lane = tid & 31, warp = tid >> 5;
    int wm = warp >> 2, wn = warp & 3;          // 2x4 warps, 64x32 warp tile
    int rowBase = blockIdx.x * 128;
    int nTile = blockIdx.y * 128;

    if (tid < 128) biasS[tid] = bias[nTile + tid];

    float acc[4][4][4];
    #pragma unroll
    for (int i = 0; i < 4; ++i)
        #pragma unroll
        for (int j = 0; j < 4; ++j)
            #pragma unroll
            for (int q = 0; q < 4; ++q) acc[i][j][q] = 0.f;

    const uint32_t swx = (uint32_t)(lane & 7) << 4;

    auto prefetch = [&](int s, int b) {
        const __half* Ap = (s < 2) ? Ax : Ay;
        int ka = (s & 1) * 64;
        int kb = s * 64;
        uint32_t base = sb + (uint32_t)b * STAGE_B;
        #pragma unroll
        for (int u = 0; u < 4; ++u) {
            int idx = u * 256 + tid;            // 1024 chunks of 16B per tile
            int row = idx >> 3, c = idx & 7;
            uint32_t soff = (uint32_t)row * 128 +
                            (((uint32_t)c * 16) ^ (((uint32_t)row & 7) << 4));
            int gm = rowBase + row;
            cpa16(base + soff, Ap + (size_t)gm * HD + ka + c * 8, gm < NN);
            int gn = nTile + row;
            size_t bofs = (size_t)gn * 256 + kb + c * 8;
            cpa16(base + 16384 + soff, Bhi + bofs, true);
            cpa16(base + 32768 + soff, Blo + bofs, true);
        }
    };

    prefetch(0, 0); CP_COMMIT();
    prefetch(1, 1); CP_COMMIT();

    #pragma unroll 1
    for (int s = 0; s < 4; ++s) {
        CP_WAIT1();
        __syncthreads();
        uint32_t aBase = sb + (uint32_t)(s & 1) * STAGE_B;
        #pragma unroll
        for (int kk = 0; kk < 4; ++kk) {
            uint32_t a[4][4], bh[4][2], bl[4][2];
            #pragma unroll
            for (int i = 0; i < 4; ++i) {
                uint32_t m = (uint32_t)(wm * 64 + i * 16 + (lane & 15));
                uint32_t k2 = (uint32_t)(kk * 16 + ((lane & 16) >> 1)) * 2;
                ldsm4(a[i], aBase + m * 128 + (k2 ^ swx));
            }
            #pragma unroll
            for (int jj = 0; jj < 2; ++jj) {
                uint32_t n = (uint32_t)(wn * 32 + jj * 16 + (lane & 7) + ((lane & 16) >> 1));
                uint32_t k2 = (uint32_t)(kk * 16 + (lane & 8)) * 2;
                uint32_t r[4];
                ldsm4(r, aBase + 16384 + n * 128 + (k2 ^ swx));
                bh[jj * 2][0] = r[0]; bh[jj * 2][1] = r[1];
                bh[jj * 2 + 1][0] = r[2]; bh[jj * 2 + 1][1] = r[3];
                ldsm4(r, aBase + 32768 + n * 128 + (k2 ^ swx));
                bl[jj * 2][0] = r[0]; bl[jj * 2][1] = r[1];
                bl[jj * 2 + 1][0] = r[2]; bl[jj * 2 + 1][1] = r[3];
            }
            #pragma unroll
            for (int i = 0; i < 4; ++i)
                #pragma unroll
                for (int j = 0; j < 4; ++j) {
                    mma16816(acc[i][j], a[i], bh[j]);
                    mma16816(acc[i][j], a[i], bl[j]);
                }
        }
        __syncthreads();
        if (s < 2) prefetch(s + 2, s & 1);
        CP_COMMIT();
    }

    // ---------- fused epilogue ----------
    #pragma unroll
    for (int i = 0; i < 4; ++i) {
        #pragma unroll
        for (int j = 0; j < 4; ++j) {
            int cl = wn * 32 + j * 8 + (lane & 3) * 2;
            int c0 = nTile + cl;
            float bs0 = biasS[cl], bs1 = biasS[cl + 1];
            #pragma unroll
            for (int half = 0; half < 2; ++half) {
                int m0 = rowBase + wm * 64 + i * 16 + (lane >> 2) + half * 8;
                if (m0 >= NN) continue;
                float v0 = acc[i][j][half * 2 + 0] + bs0;
                float v1 = acc[i][j][half * 2 + 1] + bs1;
                if (MODE == 0) {
                    if (c0 < 128) {
                        *(float2*)(outA + (size_t)m0 * HD + c0) =
                            make_float2(sigf(v0), sigf(v1));
                    } else {
                        int n2 = c0 - 128;
                        float2 hv = *(const float2*)(hbuf + (size_t)m0 * HD + n2);
                        __half2 rh = __float22half2_rn(
                            make_float2(sigf(v0) * hv.x, sigf(v1) * hv.y));
                        *(__half2*)(outH16 + (size_t)m0 * HD + n2) = rh;
                    }
                } else {
                    float2 hv = *(const float2*)(hbuf + (size_t)m0 * HD + c0);
                    float2 zv = *(const float2*)(zbuf + (size_t)m0 * HD + c0);
                    float o0 = zv.x * hv.x + (1.f - zv.x) * tanhf(v0);
                    float o1 = zv.y * hv.y + (1.f - zv.y) * tanhf(v1);
                    *(float2*)(outA + (size_t)m0 * HD + c0) = make_float2(o0, o1);
                    *(__half2*)(outH16 + (size_t)m0 * HD + c0) =
                        __float22half2_rn(make_float2(o0, o1));
                    if (outB)
                        *(float2*)(outB + (size_t)m0 * HD + c0) = make_float2(o0, o1);
                }
            }
        }
    }
}

// ================= host =================
extern "C" void kernel_launch(void* const* d_in, const int* in_sizes, int n_in,
                              void* d_out, int out_size) {
    if (n_in < 15) return;
    const float* x   = (const float*)d_in[0];
    const float* h0  = (const float*)d_in[1];
    const int*   ei  = (const int*)  d_in[2];
    const float* Wxz = (const float*)d_in[3];
    const float* Whz = (const float*)d_in[4];
    const float* Wxr = (const float*)d_in[5];
    const float* Whr = (const float*)d_in[6];
    const float* Wxh = (const float*)d_in[7];
    const float* Whh = (const float*)d_in[8];
    const float* bxz = (const float*)d_in[9];
    const float* bhz = (const float*)d_in[10];
    const float* bxr = (const float*)d_in[11];
    const float* bhr = (const float*)d_in[12];
    const float* bxh = (const float*)d_in[13];
    const float* bhh = (const float*)d_in[14];
    float* out = (float*)d_out;

    float *p_h, *p_z, *p_bzr, *p_bh;
    __half *p_xf16, *p_hf16, *p_rhf16, *p_aX, *p_aY, *p_aR;
    __half *p_Bzr_hi, *p_Bzr_lo, *p_Bh_hi, *p_Bh_lo;
    cudaGetSymbolAddress((void**)&p_h,      g_h);
    cudaGetSymbolAddress((void**)&p_z,      g_z);
    cudaGetSymbolAddress((void**)&p_xf16,   g_xf16);
    cudaGetSymbolAddress((void**)&p_hf16,   g_hf16);
    cudaGetSymbolAddress((void**)&p_rhf16,  g_rhf16);
    cudaGetSymbolAddress((void**)&p_aX,     g_aX);
    cudaGetSymbolAddress((void**)&p_aY,     g_aY);
    cudaGetSymbolAddress((void**)&p_aR,     g_aR);
    cudaGetSymbolAddress((void**)&p_Bzr_hi, g_Bzr_hi);
    cudaGetSymbolAddress((void**)&p_Bzr_lo, g_Bzr_lo);
    cudaGetSymbolAddress((void**)&p_Bh_hi,  g_Bh_hi);
    cudaGetSymbolAddress((void**)&p_Bh_lo,  g_Bh_lo);
    cudaGetSymbolAddress((void**)&p_bzr,    g_bzr);
    cudaGetSymbolAddress((void**)&p_bh,     g_bh);

    cudaFuncSetAttribute(k_mma_gemm<0>, cudaFuncAttributeMaxDynamicSharedMemorySize, SMEM_GEMM);
    cudaFuncSetAttribute(k_mma_gemm<1>, cudaFuncAttributeMaxDynamicSharedMemorySize, SMEM_GEMM);

    // ---- setup ----
    const int NB = (NN + 1023) / 1024;
    k_zero<<<(NN + 255) / 256, 256>>>();
    k_count<<<(NE + 255) / 256, 256>>>(ei);
    k_scan1<<<NB, 1024>>>();
    k_scan2<<<1, 64>>>();
    k_scan3<<<NB, 1024>>>();
    k_fill<<<(NE + 255) / 256, 256>>>(ei);
    k_xcvt<<<(NT * NN * HD / 4 + 255) / 256, 256>>>((const float4*)x);
    {
        int tot = NL * 256 * 256 + NL * 128 * 256 + NL * 256 + NL * 128 + NL * NN * HD / 4;
        k_init<<<(tot + 255) / 256, 256>>>(Wxz, Whz, Wxr, Whr, Wxh, Whh,
                                           bxz, bhz, bxr, bhr, bxh, bhh,
                                           (const float4*)h0);
    }

    // ---- recurrence ----
    const int spmm_blocks = (NN + 7) / 8;
    const int gM = (NN + 127) / 128;  // 391
    for (int t = 0; t < NT; ++t) {
        for (int l = 0; l < NL; ++l) {
            const __half* inp16 = (l == 0) ? (p_xf16 + (size_t)t * NN * HD) : p_hf16;
            __half* h16 = p_hf16 + (size_t)l * NN * HD;
            float*  h   = p_h   + (size_t)l * NN * HD;

            k_spmm2<<<spmm_blocks, 256>>>(inp16, h16, p_aX, p_aY);

            k_mma_gemm<0><<<dim3(gM, 2), 256, SMEM_GEMM>>>(
                p_aX, p_aY,
                p_Bzr_hi + (size_t)l * 256 * 256, p_Bzr_lo + (size_t)l * 256 * 256,
                p_bzr + (size_t)l * 256, h, nullptr, p_z, p_rhf16, nullptr);

            k_spmm<<<spmm_blocks, 256>>>(p_rhf16, p_aR);

            float* out2 = (l == NL - 1) ? (out + (size_t)t * NN * HD) : nullptr;
            k_mma_gemm<1><<<dim3(gM, 1), 256, SMEM_GEMM>>>(
                p_aX, p_aR,
                p_Bh_hi + (size_t)l * 128 * 256, p_Bh_lo + (size_t)l * 128 * 256,
                p_bh + (size_t)l * 128, h, p_z, h, h16, out2);
        }
    }
}

// round 6
// speedup vs baseline: 2.8380x; 1.3147x over previous
#include <cuda_runtime.h>
#include <cuda_fp16.h>
#include <math.h>
#include <stdint.h>

#define NT 8
#define NN 50000
#define NE 800000
#define HD 128
#define NL 2

__device__ __forceinline__ uint32_t smem_u32(const void* p) {
    uint32_t a;
    asm("{ .reg .u64 t; cvta.to.shared.u64 t, %1; cvt.u32.u64 %0, t; }" : "=r"(a) : "l"(p));
    return a;
}
__device__ __forceinline__ float sigf(float x) { return 1.f / (1.f + __expf(-x)); }

__device__ __forceinline__ void mma16816(float* d, const uint32_t* a, const uint32_t* b) {
    asm volatile("mma.sync.aligned.m16n8k16.row.col.f32.f16.f16.f32 "
        "{%0,%1,%2,%3}, {%4,%5,%6,%7}, {%8,%9}, {%0,%1,%2,%3};"
        : "+f"(d[0]), "+f"(d[1]), "+f"(d[2]), "+f"(d[3])
        : "r"(a[0]), "r"(a[1]), "r"(a[2]), "r"(a[3]), "r"(b[0]), "r"(b[1]));
}
__device__ __forceinline__ void ldsm4(uint32_t* r, uint32_t addr) {
    asm volatile("ldmatrix.sync.aligned.m8n8.x4.shared.b16 {%0,%1,%2,%3}, [%4];"
        : "=r"(r[0]), "=r"(r[1]), "=r"(r[2]), "=r"(r[3]) : "r"(addr));
}
__device__ __forceinline__ void cpa16(uint32_t dst, const void* src, bool pred) {
    asm volatile("cp.async.cg.shared.global [%0], [%1], 16, %2;"
        :: "r"(dst), "l"(__cvta_generic_to_global(src)), "r"(pred ? 16 : 0) : "memory");
}
#define CP_COMMIT() asm volatile("cp.async.commit_group;" ::: "memory")
#define CP_WAIT1()  asm volatile("cp.async.wait_group 1;" ::: "memory")

__device__ __forceinline__ uint2 packh4(float4 a) {
    __half2 p0 = __float22half2_rn(make_float2(a.x, a.y));
    __half2 p1 = __float22half2_rn(make_float2(a.z, a.w));
    uint2 r;
    r.x = *(uint32_t*)&p0;
    r.y = *(uint32_t*)&p1;
    return r;
}
// accumulate 8 halves (uint4) into 8 fp32 with weight w
__device__ __forceinline__ void acc8(float* a, uint4 u, float w) {
    float2 f;
    f = __half22float2(*(__half2*)&u.x); a[0] += w * f.x; a[1] += w * f.y;
    f = __half22float2(*(__half2*)&u.y); a[2] += w * f.x; a[3] += w * f.y;
    f = __half22float2(*(__half2*)&u.z); a[4] += w * f.x; a[5] += w * f.y;
    f = __half22float2(*(__half2*)&u.w); a[6] += w * f.x; a[7] += w * f.y;
}
__device__ __forceinline__ uint4 pack8(const float* a) {
    uint4 r;
    __half2 h;
    h = __float22half2_rn(make_float2(a[0], a[1])); r.x = *(uint32_t*)&h;
    h = __float22half2_rn(make_float2(a[2], a[3])); r.y = *(uint32_t*)&h;
    h = __float22half2_rn(make_float2(a[4], a[5])); r.z = *(uint32_t*)&h;
    h = __float22half2_rn(make_float2(a[6], a[7])); r.w = *(uint32_t*)&h;
    return r;
}

// ================= static device scratch =================
__device__ float g_h[NL][NN * HD];
__device__ float g_z[NN * HD];
__device__ __align__(128) __half g_xf16[NT * NN * HD];
__device__ __align__(128) __half g_hf16[NL][NN * HD];
__device__ __align__(128) __half g_rhf16[NN * HD];
__device__ __align__(128) __half g_aX[NN * HD];
__device__ __align__(128) __half g_aY[NN * HD];
__device__ __align__(128) __half g_aR[NN * HD];
__device__ int   g_cnt[NN];
__device__ int   g_cur[NN];
__device__ int   g_offs[NN + 1];
__device__ float g_dinv[NN];
__device__ int2  g_epack[NE];
__device__ int   g_bsum[64];
__device__ int   g_bbase[64];
__device__ __align__(128) __half g_Bzr[NL * 256 * 256];   // [N][K] fp16
__device__ __align__(128) __half g_Bh [NL * 128 * 256];
__device__ float g_bzr[NL][256];
__device__ float g_bh [NL][128];

// ================= setup kernels =================
__global__ void k_zero() {
    int i = blockIdx.x * blockDim.x + threadIdx.x;
    if (i < NN) { g_cnt[i] = 0; g_cur[i] = 0; }
}
__global__ void k_count(const int* __restrict__ ei) {
    int e = blockIdx.x * blockDim.x + threadIdx.x;
    if (e < NE) atomicAdd(&g_cnt[ei[e]], 1);
}
__global__ void k_scan1() {
    __shared__ int s[1024];
    int t = threadIdx.x;
    int i = blockIdx.x * 1024 + t;
    int v = (i < NN) ? g_cnt[i] : 0;
    if (i < NN) g_dinv[i] = rsqrtf((float)(v + 2));
    s[t] = v; __syncthreads();
    #pragma unroll
    for (int off = 1; off < 1024; off <<= 1) {
        int x = (t >= off) ? s[t - off] : 0;
        __syncthreads(); s[t] += x; __syncthreads();
    }
    if (i < NN) g_offs[i] = s[t] - v;
    if (t == 1023) g_bsum[blockIdx.x] = s[1023];
}
__global__ void k_scan2() {
    __shared__ int s[64];
    int t = threadIdx.x;
    const int NB = (NN + 1023) / 1024;
    int v = (t < NB) ? g_bsum[t] : 0;
    s[t] = v; __syncthreads();
    #pragma unroll
    for (int off = 1; off < 64; off <<= 1) {
        int x = (t >= off) ? s[t - off] : 0;
        __syncthreads(); s[t] += x; __syncthreads();
    }
    if (t < NB) g_bbase[t] = s[t] - v;
    if (t == 63) g_offs[NN] = s[63];
}
__global__ void k_scan3() {
    int i = blockIdx.x * 1024 + threadIdx.x;
    if (i < NN) g_offs[i] += g_bbase[blockIdx.x];
}
__global__ void k_fill(const int* __restrict__ ei) {
    int e = blockIdx.x * blockDim.x + threadIdx.x;
    if (e < NE) {
        int r = ei[e];
        int c = ei[NE + e];
        int pos = g_offs[r] + atomicAdd(&g_cur[r], 1);
        g_epack[pos] = make_int2(c, __float_as_int(g_dinv[r] * g_dinv[c]));
    }
}
__global__ void k_xcvt(const float4* __restrict__ x) {
    int i = blockIdx.x * blockDim.x + threadIdx.x;
    if (i < NT * NN * HD / 4)
        ((uint2*)&g_xf16[0])[i] = packh4(x[i]);
}
__global__ void k_init(const float* __restrict__ Wxz, const float* __restrict__ Whz,
                       const float* __restrict__ Wxr, const float* __restrict__ Whr,
                       const float* __restrict__ Wxh, const float* __restrict__ Whh,
                       const float* __restrict__ bxz, const float* __restrict__ bhz,
                       const float* __restrict__ bxr, const float* __restrict__ bhr,
                       const float* __restrict__ bxh, const float* __restrict__ bhh,
                       const float4* __restrict__ h0) {
    int i = blockIdx.x * blockDim.x + threadIdx.x;
    const int ZR = NL * 256 * 256;
    const int HS = NL * 128 * 256;
    const int B1 = ZR + HS;
    const int B2 = B1 + NL * 256;
    const int B3 = B2 + NL * 128;
    const int CP = NL * NN * HD / 4;
    if (i < ZR) {
        int l = i / (256 * 256);
        int nk = i % (256 * 256);
        int n = nk / 256, k = nk % 256;
        const float* W = (k < 128) ? ((n < 128) ? Wxz : Wxr)
                                   : ((n < 128) ? Whz : Whr);
        g_Bzr[l * 256 * 256 + nk] =
            __float2half_rn(W[l * HD * HD + (k & 127) * HD + (n & 127)]);
    } else if (i < B1) {
        int i2 = i - ZR;
        int l = i2 / (128 * 256);
        int nk = i2 % (128 * 256);
        int n = nk / 256, k = nk % 256;
        const float* W = (k < 128) ? Wxh : Whh;
        g_Bh[l * 128 * 256 + nk] =
            __float2half_rn(W[l * HD * HD + (k & 127) * HD + n]);
    } else if (i < B2) {
        int i2 = i - B1;
        int l = i2 / 256, j = i2 % 256;
        g_bzr[l][j] = (j < 128) ? (bxz[l * HD + j] + bhz[l * HD + j])
                                : (bxr[l * HD + j - 128] + bhr[l * HD + j - 128]);
    } else if (i < B3) {
        int i2 = i - B2;
        int l = i2 / 128, j = i2 % 128;
        g_bh[l][j] = bxh[l * HD + j] + bhh[l * HD + j];
    } else if (i - B3 < CP) {
        int j = i - B3;
        float4 v = h0[j];
        ((float4*)&g_h[0][0])[j] = v;
        ((uint2*)&g_hf16[0][0])[j] = packh4(v);
    }
}

// ================= SpMM: half-warp per edge, 2 edges/warp/iter =================
// Lane layout: hw = lane>>4 (edge parity), sl = lane&15 (cols [sl*8, sl*8+8)).
// 16 lanes x uint4 = 256B = one full fp16 row. Reduce across halfwarps at end.
__global__ void __launch_bounds__(256) k_spmm2(
    const __half* __restrict__ srcA, const __half* __restrict__ srcB,
    __half* __restrict__ oA, __half* __restrict__ oB) {
    int row = (blockIdx.x * blockDim.x + threadIdx.x) >> 5;
    int lane = threadIdx.x & 31;
    if (row >= NN) return;
    int hw = lane >> 4, sl = lane & 15;
    const uint4* sA = (const uint4*)srcA;
    const uint4* sB = (const uint4*)srcB;
    float aA[8], aB[8];
    #pragma unroll
    for (int k = 0; k < 8; ++k) { aA[k] = 0.f; aB[k] = 0.f; }
    int e0 = g_offs[row], end = g_offs[row + 1];
    #pragma unroll 2
    for (int e = e0 + hw; e < end; e += 2) {
        int2 ew = g_epack[e];
        float w = __int_as_float(ew.y);
        uint4 u = sA[(size_t)ew.x * 16 + sl];
        uint4 v = sB[(size_t)ew.x * 16 + sl];
        acc8(aA, u, w);
        acc8(aB, v, w);
    }
    #pragma unroll
    for (int k = 0; k < 8; ++k) {
        aA[k] += __shfl_xor_sync(0xffffffff, aA[k], 16);
        aB[k] += __shfl_xor_sync(0xffffffff, aB[k], 16);
    }
    if (hw == 0) {
        float di = g_dinv[row];
        float ws = 2.f * di * di;
        acc8(aA, sA[(size_t)row * 16 + sl], ws);
        acc8(aB, sB[(size_t)row * 16 + sl], ws);
        ((uint4*)oA)[(size_t)row * 16 + sl] = pack8(aA);
        ((uint4*)oB)[(size_t)row * 16 + sl] = pack8(aB);
    }
}

__global__ void __launch_bounds__(256) k_spmm(const __half* __restrict__ src,
                                              __half* __restrict__ o) {
    int row = (blockIdx.x * blockDim.x + threadIdx.x) >> 5;
    int lane = threadIdx.x & 31;
    if (row >= NN) return;
    int hw = lane >> 4, sl = lane & 15;
    const uint4* s4 = (const uint4*)src;
    float a[8];
    #pragma unroll
    for (int k = 0; k < 8; ++k) a[k] = 0.f;
    int e0 = g_offs[row], end = g_offs[row + 1];
    #pragma unroll 2
    for (int e = e0 + hw; e < end; e += 2) {
        int2 ew = g_epack[e];
        float w = __int_as_float(ew.y);
        acc8(a, s4[(size_t)ew.x * 16 + sl], w);
    }
    #pragma unroll
    for (int k = 0; k < 8; ++k)
        a[k] += __shfl_xor_sync(0xffffffff, a[k], 16);
    if (hw == 0) {
        float di = g_dinv[row];
        acc8(a, s4[(size_t)row * 16 + sl], 2.f * di * di);
        ((uint4*)o)[(size_t)row * 16 + sl] = pack8(a);
    }
}

// ================= pipelined HMMA GEMM (fp16 A, fp16 B, single pass) =================
// C = [Ax|Ay](Mx256) @ W(256xNTOT). 4 K-stages of 64, double-buffered cp.async.
// Stage smem: A 128x128B (16KB) + B 128x128B (16KB) = 32KB/stage, 64KB total.
// MODE 0 (grid.y=2): n<128 -> z=sigmoid(v) [fp32]; n>=128 -> rh=sigmoid(v)*h [fp16]
// MODE 1 (grid.y=1): hn = z*h+(1-z)*tanh(v) -> h fp32, h fp16, optional out fp32
#define STAGE_B 32768
#define SMEM_GEMM (65536 + 512)

template <int MODE>
__global__ void __launch_bounds__(256) k_mma_gemm(
    const __half* __restrict__ Ax, const __half* __restrict__ Ay,
    const __half* __restrict__ B,
    const float* __restrict__ bias, const float* __restrict__ hbuf,
    const float* __restrict__ zbuf, float* __restrict__ outA,
    __half* __restrict__ outH16, float* __restrict__ outB) {

    extern __shared__ char smem[];
    uint32_t sb = smem_u32(smem);
    float* biasS = (float*)(smem + 65536);
    int tid = threadIdx.x;
    int lane = tid & 31, warp = tid >> 5;
    int wm = warp >> 2, wn = warp & 3;          // 2x4 warps, 64x32 warp tile
    int rowBase = blockIdx.x * 128;
    int nTile = blockIdx.y * 128;

    if (tid < 128) biasS[tid] = bias[nTile + tid];

    float acc[4][4][4];
    #pragma unroll
    for (int i = 0; i < 4; ++i)
        #pragma unroll
        for (int j = 0; j < 4; ++j)
            #pragma unroll
            for (int q = 0; q < 4; ++q) acc[i][j][q] = 0.f;

    const uint32_t swx = (uint32_t)(lane & 7) << 4;

    auto prefetch = [&](int s, int b) {
        const __half* Ap = (s < 2) ? Ax : Ay;
        int ka = (s & 1) * 64;
        int kb = s * 64;
        uint32_t base = sb + (uint32_t)b * STAGE_B;
        #pragma unroll
        for (int u = 0; u < 4; ++u) {
            int idx = u * 256 + tid;
            int row = idx >> 3, c = idx & 7;
            uint32_t soff = (uint32_t)row * 128 +
                            (((uint32_t)c * 16) ^ (((uint32_t)row & 7) << 4));
            int gm = rowBase + row;
            cpa16(base + soff, Ap + (size_t)gm * HD + ka + c * 8, gm < NN);
            int gn = nTile + row;
            cpa16(base + 16384 + soff, B + (size_t)gn * 256 + kb + c * 8, true);
        }
    };

    prefetch(0, 0); CP_COMMIT();
    prefetch(1, 1); CP_COMMIT();

    #pragma unroll 1
    for (int s = 0; s < 4; ++s) {
        CP_WAIT1();
        __syncthreads();
        uint32_t aBase = sb + (uint32_t)(s & 1) * STAGE_B;
        #pragma unroll
        for (int kk = 0; kk < 4; ++kk) {
            uint32_t a[4][4], bf[4][2];
            #pragma unroll
            for (int i = 0; i < 4; ++i) {
                uint32_t m = (uint32_t)(wm * 64 + i * 16 + (lane & 15));
                uint32_t k2 = (uint32_t)(kk * 16 + ((lane & 16) >> 1)) * 2;
                ldsm4(a[i], aBase + m * 128 + (k2 ^ swx));
            }
            #pragma unroll
            for (int jj = 0; jj < 2; ++jj) {
                uint32_t n = (uint32_t)(wn * 32 + jj * 16 + (lane & 7) + ((lane & 16) >> 1));
                uint32_t k2 = (uint32_t)(kk * 16 + (lane & 8)) * 2;
                uint32_t r[4];
                ldsm4(r, aBase + 16384 + n * 128 + (k2 ^ swx));
                bf[jj * 2][0] = r[0]; bf[jj * 2][1] = r[1];
                bf[jj * 2 + 1][0] = r[2]; bf[jj * 2 + 1][1] = r[3];
            }
            #pragma unroll
            for (int i = 0; i < 4; ++i)
                #pragma unroll
                for (int j = 0; j < 4; ++j)
                    mma16816(acc[i][j], a[i], bf[j]);
        }
        __syncthreads();
        if (s < 2) prefetch(s + 2, s & 1);
        CP_COMMIT();
    }

    // ---------- fused epilogue ----------
    #pragma unroll
    for (int i = 0; i < 4; ++i) {
        #pragma unroll
        for (int j = 0; j < 4; ++j) {
            int cl = wn * 32 + j * 8 + (lane & 3) * 2;
            int c0 = nTile + cl;
            float bs0 = biasS[cl], bs1 = biasS[cl + 1];
            #pragma unroll
            for (int half = 0; half < 2; ++half) {
                int m0 = rowBase + wm * 64 + i * 16 + (lane >> 2) + half * 8;
                if (m0 >= NN) continue;
                float v0 = acc[i][j][half * 2 + 0] + bs0;
                float v1 = acc[i][j][half * 2 + 1] + bs1;
                if (MODE == 0) {
                    if (c0 < 128) {
                        *(float2*)(outA + (size_t)m0 * HD + c0) =
                            make_float2(sigf(v0), sigf(v1));
                    } else {
                        int n2 = c0 - 128;
                        float2 hv = *(const float2*)(hbuf + (size_t)m0 * HD + n2);
                        __half2 rh = __float22half2_rn(
                            make_float2(sigf(v0) * hv.x, sigf(v1) * hv.y));
                        *(__half2*)(outH16 + (size_t)m0 * HD + n2) = rh;
                    }
                } else {
                    float2 hv = *(const float2*)(hbuf + (size_t)m0 * HD + c0);
                    float2 zv = *(const float2*)(zbuf + (size_t)m0 * HD + c0);
                    float o0 = zv.x * hv.x + (1.f - zv.x) * tanhf(v0);
                    float o1 = zv.y * hv.y + (1.f - zv.y) * tanhf(v1);
                    *(float2*)(outA + (size_t)m0 * HD + c0) = make_float2(o0, o1);
                    *(__half2*)(outH16 + (size_t)m0 * HD + c0) =
                        __float22half2_rn(make_float2(o0, o1));
                    if (outB)
                        *(float2*)(outB + (size_t)m0 * HD + c0) = make_float2(o0, o1);
                }
            }
        }
    }
}

// ================= host =================
extern "C" void kernel_launch(void* const* d_in, const int* in_sizes, int n_in,
                              void* d_out, int out_size) {
    if (n_in < 15) return;
    const float* x   = (const float*)d_in[0];
    const float* h0  = (const float*)d_in[1];
    const int*   ei  = (const int*)  d_in[2];
    const float* Wxz = (const float*)d_in[3];
    const float* Whz = (const float*)d_in[4];
    const float* Wxr = (const float*)d_in[5];
    const float* Whr = (const float*)d_in[6];
    const float* Wxh = (const float*)d_in[7];
    const float* Whh = (const float*)d_in[8];
    const float* bxz = (const float*)d_in[9];
    const float* bhz = (const float*)d_in[10];
    const float* bxr = (const float*)d_in[11];
    const float* bhr = (const float*)d_in[12];
    const float* bxh = (const float*)d_in[13];
    const float* bhh = (const float*)d_in[14];
    float* out = (float*)d_out;

    float *p_h, *p_z, *p_bzr, *p_bh;
    __half *p_xf16, *p_hf16, *p_rhf16, *p_aX, *p_aY, *p_aR, *p_Bzr, *p_Bh;
    cudaGetSymbolAddress((void**)&p_h,     g_h);
    cudaGetSymbolAddress((void**)&p_z,     g_z);
    cudaGetSymbolAddress((void**)&p_xf16,  g_xf16);
    cudaGetSymbolAddress((void**)&p_hf16,  g_hf16);
    cudaGetSymbolAddress((void**)&p_rhf16, g_rhf16);
    cudaGetSymbolAddress((void**)&p_aX,    g_aX);
    cudaGetSymbolAddress((void**)&p_aY,    g_aY);
    cudaGetSymbolAddress((void**)&p_aR,    g_aR);
    cudaGetSymbolAddress((void**)&p_Bzr,   g_Bzr);
    cudaGetSymbolAddress((void**)&p_Bh,    g_Bh);
    cudaGetSymbolAddress((void**)&p_bzr,   g_bzr);
    cudaGetSymbolAddress((void**)&p_bh,    g_bh);

    cudaFuncSetAttribute(k_mma_gemm<0>, cudaFuncAttributeMaxDynamicSharedMemorySize, SMEM_GEMM);
    cudaFuncSetAttribute(k_mma_gemm<1>, cudaFuncAttributeMaxDynamicSharedMemorySize, SMEM_GEMM);

    // ---- setup ----
    const int NB = (NN + 1023) / 1024;
    k_zero<<<(NN + 255) / 256, 256>>>();
    k_count<<<(NE + 255) / 256, 256>>>(ei);
    k_scan1<<<NB, 1024>>>();
    k_scan2<<<1, 64>>>();
    k_scan3<<<NB, 1024>>>();
    k_fill<<<(NE + 255) / 256, 256>>>(ei);
    k_xcvt<<<(NT * NN * HD / 4 + 255) / 256, 256>>>((const float4*)x);
    {
        int tot = NL * 256 * 256 + NL * 128 * 256 + NL * 256 + NL * 128 + NL * NN * HD / 4;
        k_init<<<(tot + 255) / 256, 256>>>(Wxz, Whz, Wxr, Whr, Wxh, Whh,
                                           bxz, bhz, bxr, bhr, bxh, bhh,
                                           (const float4*)h0);
    }

    // ---- recurrence ----
    const int spmm_blocks = (NN + 7) / 8;
    const int gM = (NN + 127) / 128;  // 391
    for (int t = 0; t < NT; ++t) {
        for (int l = 0; l < NL; ++l) {
            const __half* inp16 = (l == 0) ? (p_xf16 + (size_t)t * NN * HD) : p_hf16;
            __half* h16 = p_hf16 + (size_t)l * NN * HD;
            float*  h   = p_h   + (size_t)l * NN * HD;

            k_spmm2<<<spmm_blocks, 256>>>(inp16, h16, p_aX, p_aY);

            k_mma_gemm<0><<<dim3(gM, 2), 256, SMEM_GEMM>>>(
                p_aX, p_aY, p_Bzr + (size_t)l * 256 * 256,
                p_bzr + (size_t)l * 256, h, nullptr, p_z, p_rhf16, nullptr);

            k_spmm<<<spmm_blocks, 256>>>(p_rhf16, p_aR);

            float* out2 = (l == NL - 1) ? (out + (size_t)t * NN * HD) : nullptr;
            k_mma_gemm<1><<<dim3(gM, 1), 256, SMEM_GEMM>>>(
                p_aX, p_aR, p_Bh + (size_t)l * 128 * 256,
                p_bh + (size_t)l * 128, h, p_z, h, h16, out2);
        }
    }
}

// round 7
// speedup vs baseline: 3.2362x; 1.1403x over previous
#include <cuda_runtime.h>
#include <cuda_fp16.h>
#include <math.h>
#include <stdint.h>

#define NT 8
#define NN 50000
#define NE 800000
#define HD 128
#define NL 2

__device__ __forceinline__ uint32_t smem_u32(const void* p) {
    uint32_t a;
    asm("{ .reg .u64 t; cvta.to.shared.u64 t, %1; cvt.u32.u64 %0, t; }" : "=r"(a) : "l"(p));
    return a;
}
__device__ __forceinline__ float sigf(float x) { return 1.f / (1.f + __expf(-x)); }

__device__ __forceinline__ void mma16816(float* d, const uint32_t* a, const uint32_t* b) {
    asm volatile("mma.sync.aligned.m16n8k16.row.col.f32.f16.f16.f32 "
        "{%0,%1,%2,%3}, {%4,%5,%6,%7}, {%8,%9}, {%0,%1,%2,%3};"
        : "+f"(d[0]), "+f"(d[1]), "+f"(d[2]), "+f"(d[3])
        : "r"(a[0]), "r"(a[1]), "r"(a[2]), "r"(a[3]), "r"(b[0]), "r"(b[1]));
}
__device__ __forceinline__ void ldsm4(uint32_t* r, uint32_t addr) {
    asm volatile("ldmatrix.sync.aligned.m8n8.x4.shared.b16 {%0,%1,%2,%3}, [%4];"
        : "=r"(r[0]), "=r"(r[1]), "=r"(r[2]), "=r"(r[3]) : "r"(addr));
}
__device__ __forceinline__ void cpa16(uint32_t dst, const void* src, bool pred) {
    asm volatile("cp.async.cg.shared.global [%0], [%1], 16, %2;"
        :: "r"(dst), "l"(__cvta_generic_to_global(src)), "r"(pred ? 16 : 0) : "memory");
}
#define CP_COMMIT() asm volatile("cp.async.commit_group;" ::: "memory")
#define CP_WAIT1()  asm volatile("cp.async.wait_group 1;" ::: "memory")

__device__ __forceinline__ uint2 packh4(float4 a) {
    __half2 p0 = __float22half2_rn(make_float2(a.x, a.y));
    __half2 p1 = __float22half2_rn(make_float2(a.z, a.w));
    uint2 r;
    r.x = *(uint32_t*)&p0;
    r.y = *(uint32_t*)&p1;
    return r;
}
__device__ __forceinline__ void acc8(float* a, uint4 u, float w) {
    float2 f;
    f = __half22float2(*(__half2*)&u.x); a[0] += w * f.x; a[1] += w * f.y;
    f = __half22float2(*(__half2*)&u.y); a[2] += w * f.x; a[3] += w * f.y;
    f = __half22float2(*(__half2*)&u.z); a[4] += w * f.x; a[5] += w * f.y;
    f = __half22float2(*(__half2*)&u.w); a[6] += w * f.x; a[7] += w * f.y;
}
__device__ __forceinline__ uint4 pack8(const float* a) {
    uint4 r;
    __half2 h;
    h = __float22half2_rn(make_float2(a[0], a[1])); r.x = *(uint32_t*)&h;
    h = __float22half2_rn(make_float2(a[2], a[3])); r.y = *(uint32_t*)&h;
    h = __float22half2_rn(make_float2(a[4], a[5])); r.z = *(uint32_t*)&h;
    h = __float22half2_rn(make_float2(a[6], a[7])); r.w = *(uint32_t*)&h;
    return r;
}

// ================= static device scratch (all-fp16 state) =================
__device__ __align__(128) __half g_xf16[NT * NN * HD];
__device__ __align__(128) __half g_hf16[NL][NN * HD];   // hidden state (fp16 only)
__device__ __align__(128) __half g_zf16[NN * HD];       // z gate fp16
__device__ __align__(128) __half g_rhf16[NN * HD];      // r*h fp16
__device__ __align__(128) __half g_aX[NN * HD];
__device__ __align__(128) __half g_aY[NN * HD];
__device__ __align__(128) __half g_aH0[NN * HD];        // cached A@h0_t (reused next t)
__device__ __align__(128) __half g_aR[NN * HD];
__device__ int   g_cnt[NN];
__device__ int   g_cur[NN];
__device__ int   g_offs[NN + 1];
__device__ float g_dinv[NN];
__device__ int2  g_epack[NE];
__device__ int   g_bsum[64];
__device__ int   g_bbase[64];
__device__ __align__(128) __half g_Bzr[NL * 256 * 256];
__device__ __align__(128) __half g_Bh [NL * 128 * 256];
__device__ float g_bzr[NL][256];
__device__ float g_bh [NL][128];

// ================= setup kernels =================
__global__ void k_zero() {
    int i = blockIdx.x * blockDim.x + threadIdx.x;
    if (i < NN) { g_cnt[i] = 0; g_cur[i] = 0; }
}
__global__ void k_count(const int* __restrict__ ei) {
    int e = blockIdx.x * blockDim.x + threadIdx.x;
    if (e < NE) atomicAdd(&g_cnt[ei[e]], 1);
}
__global__ void k_scan1() {
    __shared__ int s[1024];
    int t = threadIdx.x;
    int i = blockIdx.x * 1024 + t;
    int v = (i < NN) ? g_cnt[i] : 0;
    if (i < NN) g_dinv[i] = rsqrtf((float)(v + 2));
    s[t] = v; __syncthreads();
    #pragma unroll
    for (int off = 1; off < 1024; off <<= 1) {
        int x = (t >= off) ? s[t - off] : 0;
        __syncthreads(); s[t] += x; __syncthreads();
    }
    if (i < NN) g_offs[i] = s[t] - v;
    if (t == 1023) g_bsum[blockIdx.x] = s[1023];
}
__global__ void k_scan2() {
    __shared__ int s[64];
    int t = threadIdx.x;
    const int NB = (NN + 1023) / 1024;
    int v = (t < NB) ? g_bsum[t] : 0;
    s[t] = v; __syncthreads();
    #pragma unroll
    for (int off = 1; off < 64; off <<= 1) {
        int x = (t >= off) ? s[t - off] : 0;
        __syncthreads(); s[t] += x; __syncthreads();
    }
    if (t < NB) g_bbase[t] = s[t] - v;
    if (t == 63) g_offs[NN] = s[63];
}
__global__ void k_scan3() {
    int i = blockIdx.x * 1024 + threadIdx.x;
    if (i < NN) g_offs[i] += g_bbase[blockIdx.x];
}
__global__ void k_fill(const int* __restrict__ ei) {
    int e = blockIdx.x * blockDim.x + threadIdx.x;
    if (e < NE) {
        int r = ei[e];
        int c = ei[NE + e];
        int pos = g_offs[r] + atomicAdd(&g_cur[r], 1);
        g_epack[pos] = make_int2(c, __float_as_int(g_dinv[r] * g_dinv[c]));
    }
}
__global__ void k_xcvt(const float4* __restrict__ x) {
    int i = blockIdx.x * blockDim.x + threadIdx.x;
    if (i < NT * NN * HD / 4)
        ((uint2*)&g_xf16[0])[i] = packh4(x[i]);
}
__global__ void k_init(const float* __restrict__ Wxz, const float* __restrict__ Whz,
                       const float* __restrict__ Wxr, const float* __restrict__ Whr,
                       const float* __restrict__ Wxh, const float* __restrict__ Whh,
                       const float* __restrict__ bxz, const float* __restrict__ bhz,
                       const float* __restrict__ bxr, const float* __restrict__ bhr,
                       const float* __restrict__ bxh, const float* __restrict__ bhh,
                       const float4* __restrict__ h0) {
    int i = blockIdx.x * blockDim.x + threadIdx.x;
    const int ZR = NL * 256 * 256;
    const int HS = NL * 128 * 256;
    const int B1 = ZR + HS;
    const int B2 = B1 + NL * 256;
    const int B3 = B2 + NL * 128;
    const int CP = NL * NN * HD / 4;
    if (i < ZR) {
        int l = i / (256 * 256);
        int nk = i % (256 * 256);
        int n = nk / 256, k = nk % 256;
        const float* W = (k < 128) ? ((n < 128) ? Wxz : Wxr)
                                   : ((n < 128) ? Whz : Whr);
        g_Bzr[l * 256 * 256 + nk] =
            __float2half_rn(W[l * HD * HD + (k & 127) * HD + (n & 127)]);
    } else if (i < B1) {
        int i2 = i - ZR;
        int l = i2 / (128 * 256);
        int nk = i2 % (128 * 256);
        int n = nk / 256, k = nk % 256;
        const float* W = (k < 128) ? Wxh : Whh;
        g_Bh[l * 128 * 256 + nk] =
            __float2half_rn(W[l * HD * HD + (k & 127) * HD + n]);
    } else if (i < B2) {
        int i2 = i - B1;
        int l = i2 / 256, j = i2 % 256;
        g_bzr[l][j] = (j < 128) ? (bxz[l * HD + j] + bhz[l * HD + j])
                                : (bxr[l * HD + j - 128] + bhr[l * HD + j - 128]);
    } else if (i < B3) {
        int i2 = i - B2;
        int l = i2 / 128, j = i2 % 128;
        g_bh[l][j] = bxh[l * HD + j] + bhh[l * HD + j];
    } else if (i - B3 < CP) {
        int j = i - B3;
        ((uint2*)&g_hf16[0][0])[j] = packh4(h0[j]);
    }
}

// ================= SpMM: half-warp per edge, 2 edges/warp/iter, unroll 4 =================
__global__ void __launch_bounds__(256) k_spmm2(
    const __half* __restrict__ srcA, const __half* __restrict__ srcB,
    __half* __restrict__ oA, __half* __restrict__ oB) {
    int row = (blockIdx.x * blockDim.x + threadIdx.x) >> 5;
    int lane = threadIdx.x & 31;
    if (row >= NN) return;
    int hw = lane >> 4, sl = lane & 15;
    const uint4* sA = (const uint4*)srcA;
    const uint4* sB = (const uint4*)srcB;
    float aA[8], aB[8];
    #pragma unroll
    for (int k = 0; k < 8; ++k) { aA[k] = 0.f; aB[k] = 0.f; }
    int e0 = g_offs[row], end = g_offs[row + 1];
    #pragma unroll 4
    for (int e = e0 + hw; e < end; e += 2) {
        int2 ew = g_epack[e];
        float w = __int_as_float(ew.y);
        uint4 u = sA[(size_t)ew.x * 16 + sl];
        uint4 v = sB[(size_t)ew.x * 16 + sl];
        acc8(aA, u, w);
        acc8(aB, v, w);
    }
    #pragma unroll
    for (int k = 0; k < 8; ++k) {
        aA[k] += __shfl_xor_sync(0xffffffff, aA[k], 16);
        aB[k] += __shfl_xor_sync(0xffffffff, aB[k], 16);
    }
    if (hw == 0) {
        float di = g_dinv[row];
        float ws = 2.f * di * di;
        acc8(aA, sA[(size_t)row * 16 + sl], ws);
        acc8(aB, sB[(size_t)row * 16 + sl], ws);
        ((uint4*)oA)[(size_t)row * 16 + sl] = pack8(aA);
        ((uint4*)oB)[(size_t)row * 16 + sl] = pack8(aB);
    }
}

__global__ void __launch_bounds__(256) k_spmm(const __half* __restrict__ src,
                                              __half* __restrict__ o) {
    int row = (blockIdx.x * blockDim.x + threadIdx.x) >> 5;
    int lane = threadIdx.x & 31;
    if (row >= NN) return;
    int hw = lane >> 4, sl = lane & 15;
    const uint4* s4 = (const uint4*)src;
    float a[8];
    #pragma unroll
    for (int k = 0; k < 8; ++k) a[k] = 0.f;
    int e0 = g_offs[row], end = g_offs[row + 1];
    #pragma unroll 4
    for (int e = e0 + hw; e < end; e += 2) {
        int2 ew = g_epack[e];
        float w = __int_as_float(ew.y);
        acc8(a, s4[(size_t)ew.x * 16 + sl], w);
    }
    #pragma unroll
    for (int k = 0; k < 8; ++k)
        a[k] += __shfl_xor_sync(0xffffffff, a[k], 16);
    if (hw == 0) {
        float di = g_dinv[row];
        acc8(a, s4[(size_t)row * 16 + sl], 2.f * di * di);
        ((uint4*)o)[(size_t)row * 16 + sl] = pack8(a);
    }
}

// ================= pipelined HMMA GEMM (fp16, single pass, fp16 state epilogue) ========
// MODE 0 (grid.y=2): n<128 -> z16=sigmoid(v); n>=128 -> rh16=sigmoid(v)*h16
// MODE 1 (grid.y=1): hn = z*h+(1-z)*tanh(v) -> h16 (in place), optional out fp32
#define STAGE_B 32768
#define SMEM_GEMM (65536 + 512)

template <int MODE>
__global__ void __launch_bounds__(256) k_mma_gemm(
    const __half* __restrict__ Ax, const __half* __restrict__ Ay,
    const __half* __restrict__ B, const float* __restrict__ bias,
    __half* __restrict__ hP, __half* __restrict__ zP,
    __half* __restrict__ rhP, float* __restrict__ outF) {

    extern __shared__ char smem[];
    uint32_t sb = smem_u32(smem);
    float* biasS = (float*)(smem + 65536);
    int tid = threadIdx.x;
    int lane = tid & 31, warp = tid >> 5;
    int wm = warp >> 2, wn = warp & 3;
    int rowBase = blockIdx.x * 128;
    int nTile = blockIdx.y * 128;

    if (tid < 128) biasS[tid] = bias[nTile + tid];

    float acc[4][4][4];
    #pragma unroll
    for (int i = 0; i < 4; ++i)
        #pragma unroll
        for (int j = 0; j < 4; ++j)
            #pragma unroll
            for (int q = 0; q < 4; ++q) acc[i][j][q] = 0.f;

    const uint32_t swx = (uint32_t)(lane & 7) << 4;

    auto prefetch = [&](int s, int b) {
        const __half* Ap = (s < 2) ? Ax : Ay;
        int ka = (s & 1) * 64;
        int kb = s * 64;
        uint32_t base = sb + (uint32_t)b * STAGE_B;
        #pragma unroll
        for (int u = 0; u < 4; ++u) {
            int idx = u * 256 + tid;
            int row = idx >> 3, c = idx & 7;
            uint32_t soff = (uint32_t)row * 128 +
                            (((uint32_t)c * 16) ^ (((uint32_t)row & 7) << 4));
            int gm = rowBase + row;
            cpa16(base + soff, Ap + (size_t)gm * HD + ka + c * 8, gm < NN);
            int gn = nTile + row;
            cpa16(base + 16384 + soff, B + (size_t)gn * 256 + kb + c * 8, true);
        }
    };

    prefetch(0, 0); CP_COMMIT();
    prefetch(1, 1); CP_COMMIT();

    #pragma unroll 1
    for (int s = 0; s < 4; ++s) {
        CP_WAIT1();
        __syncthreads();
        uint32_t aBase = sb + (uint32_t)(s & 1) * STAGE_B;
        #pragma unroll
        for (int kk = 0; kk < 4; ++kk) {
            uint32_t a[4][4], bf[4][2];
            #pragma unroll
            for (int i = 0; i < 4; ++i) {
                uint32_t m = (uint32_t)(wm * 64 + i * 16 + (lane & 15));
                uint32_t k2 = (uint32_t)(kk * 16 + ((lane & 16) >> 1)) * 2;
                ldsm4(a[i], aBase + m * 128 + (k2 ^ swx));
            }
            #pragma unroll
            for (int jj = 0; jj < 2; ++jj) {
                uint32_t n = (uint32_t)(wn * 32 + jj * 16 + (lane & 7) + ((lane & 16) >> 1));
                uint32_t k2 = (uint32_t)(kk * 16 + (lane & 8)) * 2;
                uint32_t r[4];
                ldsm4(r, aBase + 16384 + n * 128 + (k2 ^ swx));
                bf[jj * 2][0] = r[0]; bf[jj * 2][1] = r[1];
                bf[jj * 2 + 1][0] = r[2]; bf[jj * 2 + 1][1] = r[3];
            }
            #pragma unroll
            for (int i = 0; i < 4; ++i)
                #pragma unroll
                for (int j = 0; j < 4; ++j)
                    mma16816(acc[i][j], a[i], bf[j]);
        }
        __syncthreads();
        if (s < 2) prefetch(s + 2, s & 1);
        CP_COMMIT();
    }

    // ---------- fused epilogue (fp16 state) ----------
    #pragma unroll
    for (int i = 0; i < 4; ++i) {
        #pragma unroll
        for (int j = 0; j < 4; ++j) {
            int cl = wn * 32 + j * 8 + (lane & 3) * 2;
            int c0 = nTile + cl;
            float bs0 = biasS[cl], bs1 = biasS[cl + 1];
            #pragma unroll
            for (int half = 0; half < 2; ++half) {
                int m0 = rowBase + wm * 64 + i * 16 + (lane >> 2) + half * 8;
                if (m0 >= NN) continue;
                float v0 = acc[i][j][half * 2 + 0] + bs0;
                float v1 = acc[i][j][half * 2 + 1] + bs1;
                if (MODE == 0) {
                    if (c0 < 128) {
                        *(__half2*)(zP + (size_t)m0 * HD + c0) =
                            __float22half2_rn(make_float2(sigf(v0), sigf(v1)));
                    } else {
                        int n2 = c0 - 128;
                        float2 hv = __half22float2(*(__half2*)(hP + (size_t)m0 * HD + n2));
                        *(__half2*)(rhP + (size_t)m0 * HD + n2) =
                            __float22half2_rn(make_float2(sigf(v0) * hv.x, sigf(v1) * hv.y));
                    }
                } else {
                    float2 hv = __half22float2(*(__half2*)(hP + (size_t)m0 * HD + c0));
                    float2 zv = __half22float2(*(__half2*)(zP + (size_t)m0 * HD + c0));
                    float o0 = zv.x * hv.x + (1.f - zv.x) * tanhf(v0);
                    float o1 = zv.y * hv.y + (1.f - zv.y) * tanhf(v1);
                    *(__half2*)(hP + (size_t)m0 * HD + c0) =
                        __float22half2_rn(make_float2(o0, o1));
                    if (outF)
                        *(float2*)(outF + (size_t)m0 * HD + c0) = make_float2(o0, o1);
                }
            }
        }
    }
}

// ================= host =================
extern "C" void kernel_launch(void* const* d_in, const int* in_sizes, int n_in,
                              void* d_out, int out_size) {
    if (n_in < 15) return;
    const float* x   = (const float*)d_in[0];
    const float* h0  = (const float*)d_in[1];
    const int*   ei  = (const int*)  d_in[2];
    const float* Wxz = (const float*)d_in[3];
    const float* Whz = (const float*)d_in[4];
    const float* Wxr = (const float*)d_in[5];
    const float* Whr = (const float*)d_in[6];
    const float* Wxh = (const float*)d_in[7];
    const float* Whh = (const float*)d_in[8];
    const float* bxz = (const float*)d_in[9];
    const float* bhz = (const float*)d_in[10];
    const float* bxr = (const float*)d_in[11];
    const float* bhr = (const float*)d_in[12];
    const float* bxh = (const float*)d_in[13];
    const float* bhh = (const float*)d_in[14];
    float* out = (float*)d_out;

    float *p_bzr, *p_bh;
    __half *p_xf16, *p_hf16, *p_zf16, *p_rhf16, *p_aX, *p_aY, *p_aH0, *p_aR, *p_Bzr, *p_Bh;
    cudaGetSymbolAddress((void**)&p_xf16,  g_xf16);
    cudaGetSymbolAddress((void**)&p_hf16,  g_hf16);
    cudaGetSymbolAddress((void**)&p_zf16,  g_zf16);
    cudaGetSymbolAddress((void**)&p_rhf16, g_rhf16);
    cudaGetSymbolAddress((void**)&p_aX,    g_aX);
    cudaGetSymbolAddress((void**)&p_aY,    g_aY);
    cudaGetSymbolAddress((void**)&p_aH0,   g_aH0);
    cudaGetSymbolAddress((void**)&p_aR,    g_aR);
    cudaGetSymbolAddress((void**)&p_Bzr,   g_Bzr);
    cudaGetSymbolAddress((void**)&p_Bh,    g_Bh);
    cudaGetSymbolAddress((void**)&p_bzr,   g_bzr);
    cudaGetSymbolAddress((void**)&p_bh,    g_bh);

    cudaFuncSetAttribute(k_mma_gemm<0>, cudaFuncAttributeMaxDynamicSharedMemorySize, SMEM_GEMM);
    cudaFuncSetAttribute(k_mma_gemm<1>, cudaFuncAttributeMaxDynamicSharedMemorySize, SMEM_GEMM);

    // ---- setup ----
    const int NB = (NN + 1023) / 1024;
    k_zero<<<(NN + 255) / 256, 256>>>();
    k_count<<<(NE + 255) / 256, 256>>>(ei);
    k_scan1<<<NB, 1024>>>();
    k_scan2<<<1, 64>>>();
    k_scan3<<<NB, 1024>>>();
    k_fill<<<(NE + 255) / 256, 256>>>(ei);
    k_xcvt<<<(NT * NN * HD / 4 + 255) / 256, 256>>>((const float4*)x);
    {
        int tot = NL * 256 * 256 + NL * 128 * 256 + NL * 256 + NL * 128 + NL * NN * HD / 4;
        k_init<<<(tot + 255) / 256, 256>>>(Wxz, Whz, Wxr, Whr, Wxh, Whh,
                                           bxz, bhz, bxr, bhr, bxh, bhh,
                                           (const float4*)h0);
    }

    // ---- recurrence ----
    const int spmm_blocks = (NN + 7) / 8;
    const int gM = (NN + 127) / 128;  // 391
    __half* h0_16 = p_hf16;
    __half* h1_16 = p_hf16 + (size_t)NN * HD;
    for (int t = 0; t < NT; ++t) {
        // ---- layer 0 ----
        const __half* x16 = p_xf16 + (size_t)t * NN * HD;
        const __half* Ay0;
        if (t == 0) {
            k_spmm2<<<spmm_blocks, 256>>>(x16, h0_16, p_aX, p_aY);
            Ay0 = p_aY;
        } else {
            k_spmm<<<spmm_blocks, 256>>>(x16, p_aX);   // A@h0 cached in p_aH0
            Ay0 = p_aH0;
        }
        k_mma_gemm<0><<<dim3(gM, 2), 256, SMEM_GEMM>>>(
            p_aX, Ay0, p_Bzr, p_bzr, h0_16, p_zf16, p_rhf16, nullptr);
        k_spmm<<<spmm_blocks, 256>>>(p_rhf16, p_aR);
        k_mma_gemm<1><<<dim3(gM, 1), 256, SMEM_GEMM>>>(
            p_aX, p_aR, p_Bh, p_bh, h0_16, p_zf16, nullptr, nullptr);

        // ---- layer 1 ----
        k_spmm2<<<spmm_blocks, 256>>>(h0_16, h1_16, p_aH0, p_aY);
        k_mma_gemm<0><<<dim3(gM, 2), 256, SMEM_GEMM>>>(
            p_aH0, p_aY, p_Bzr + 256 * 256, p_bzr + 256,
            h1_16, p_zf16, p_rhf16, nullptr);
        k_spmm<<<spmm_blocks, 256>>>(p_rhf16, p_aR);
        k_mma_gemm<1><<<dim3(gM, 1), 256, SMEM_GEMM>>>(
            p_aH0, p_aR, p_Bh + 128 * 256, p_bh + 128,
            h1_16, p_zf16, nullptr, out + (size_t)t * NN * HD);
    }
}

// round 8
// speedup vs baseline: 3.2984x; 1.0192x over previous
#include <cuda_runtime.h>
#include <cuda_fp16.h>
#include <math.h>
#include <stdint.h>

#define NT 8
#define NN 50000
#define NE 800000
#define HD 128
#define NL 2

__device__ __forceinline__ uint32_t smem_u32(const void* p) {
    uint32_t a;
    asm("{ .reg .u64 t; cvta.to.shared.u64 t, %1; cvt.u32.u64 %0, t; }" : "=r"(a) : "l"(p));
    return a;
}
__device__ __forceinline__ float sigf(float x) { return 1.f / (1.f + __expf(-x)); }

__device__ __forceinline__ void mma16816(float* d, const uint32_t* a, const uint32_t* b) {
    asm volatile("mma.sync.aligned.m16n8k16.row.col.f32.f16.f16.f32 "
        "{%0,%1,%2,%3}, {%4,%5,%6,%7}, {%8,%9}, {%0,%1,%2,%3};"
        : "+f"(d[0]), "+f"(d[1]), "+f"(d[2]), "+f"(d[3])
        : "r"(a[0]), "r"(a[1]), "r"(a[2]), "r"(a[3]), "r"(b[0]), "r"(b[1]));
}
__device__ __forceinline__ void ldsm4(uint32_t* r, uint32_t addr) {
    asm volatile("ldmatrix.sync.aligned.m8n8.x4.shared.b16 {%0,%1,%2,%3}, [%4];"
        : "=r"(r[0]), "=r"(r[1]), "=r"(r[2]), "=r"(r[3]) : "r"(addr));
}
__device__ __forceinline__ void cpa16(uint32_t dst, const void* src, bool pred) {
    asm volatile("cp.async.cg.shared.global [%0], [%1], 16, %2;"
        :: "r"(dst), "l"(__cvta_generic_to_global(src)), "r"(pred ? 16 : 0) : "memory");
}
#define CP_COMMIT() asm volatile("cp.async.commit_group;" ::: "memory")
#define CP_WAIT1()  asm volatile("cp.async.wait_group 1;" ::: "memory")

__device__ __forceinline__ uint2 packh4(float4 a) {
    __half2 p0 = __float22half2_rn(make_float2(a.x, a.y));
    __half2 p1 = __float22half2_rn(make_float2(a.z, a.w));
    uint2 r;
    r.x = *(uint32_t*)&p0;
    r.y = *(uint32_t*)&p1;
    return r;
}
__device__ __forceinline__ void acc8(float* a, uint4 u, float w) {
    float2 f;
    f = __half22float2(*(__half2*)&u.x); a[0] += w * f.x; a[1] += w * f.y;
    f = __half22float2(*(__half2*)&u.y); a[2] += w * f.x; a[3] += w * f.y;
    f = __half22float2(*(__half2*)&u.z); a[4] += w * f.x; a[5] += w * f.y;
    f = __half22float2(*(__half2*)&u.w); a[6] += w * f.x; a[7] += w * f.y;
}
__device__ __forceinline__ uint4 pack8(const float* a) {
    uint4 r;
    __half2 h;
    h = __float22half2_rn(make_float2(a[0], a[1])); r.x = *(uint32_t*)&h;
    h = __float22half2_rn(make_float2(a[2], a[3])); r.y = *(uint32_t*)&h;
    h = __float22half2_rn(make_float2(a[4], a[5])); r.z = *(uint32_t*)&h;
    h = __float22half2_rn(make_float2(a[6], a[7])); r.w = *(uint32_t*)&h;
    return r;
}

// ================= static device scratch (all-fp16 state) =================
__device__ __align__(128) __half g_xf16[NT * NN * HD];
__device__ __align__(128) __half g_hf16[NL][NN * HD];
__device__ __align__(128) __half g_zf16[NN * HD];
__device__ __align__(128) __half g_rhf16[NN * HD];
__device__ __align__(128) __half g_aX[NN * HD];
__device__ __align__(128) __half g_aY[NN * HD];
__device__ __align__(128) __half g_aH0[NN * HD];
__device__ __align__(128) __half g_aR[NN * HD];
__device__ int   g_cnt[NN];
__device__ int   g_cur[NN];
__device__ int   g_offs[NN + 1];
__device__ float g_dinv[NN];
__device__ int2  g_epack[NE];
__device__ int   g_bsum[64];
__device__ int   g_bbase[64];
__device__ __align__(128) __half g_Bzr[NL * 256 * 256];
__device__ __align__(128) __half g_Bh [NL * 128 * 256];
__device__ float g_bzr[NL][256];
__device__ float g_bh [NL][128];

// ================= setup kernels =================
__global__ void k_zero() {
    int i = blockIdx.x * blockDim.x + threadIdx.x;
    if (i < NN) { g_cnt[i] = 0; g_cur[i] = 0; }
}
__global__ void k_count(const int* __restrict__ ei) {
    int e = blockIdx.x * blockDim.x + threadIdx.x;
    if (e < NE) atomicAdd(&g_cnt[ei[e]], 1);
}
__global__ void k_scan1() {
    __shared__ int s[1024];
    int t = threadIdx.x;
    int i = blockIdx.x * 1024 + t;
    int v = (i < NN) ? g_cnt[i] : 0;
    if (i < NN) g_dinv[i] = rsqrtf((float)(v + 2));
    s[t] = v; __syncthreads();
    #pragma unroll
    for (int off = 1; off < 1024; off <<= 1) {
        int x = (t >= off) ? s[t - off] : 0;
        __syncthreads(); s[t] += x; __syncthreads();
    }
    if (i < NN) g_offs[i] = s[t] - v;
    if (t == 1023) g_bsum[blockIdx.x] = s[1023];
}
__global__ void k_scan2() {
    __shared__ int s[64];
    int t = threadIdx.x;
    const int NB = (NN + 1023) / 1024;
    int v = (t < NB) ? g_bsum[t] : 0;
    s[t] = v; __syncthreads();
    #pragma unroll
    for (int off = 1; off < 64; off <<= 1) {
        int x = (t >= off) ? s[t - off] : 0;
        __syncthreads(); s[t] += x; __syncthreads();
    }
    if (t < NB) g_bbase[t] = s[t] - v;
    if (t == 63) g_offs[NN] = s[63];
}
__global__ void k_scan3() {
    int i = blockIdx.x * 1024 + threadIdx.x;
    if (i < NN) g_offs[i] += g_bbase[blockIdx.x];
}
__global__ void k_fill(const int* __restrict__ ei) {
    int e = blockIdx.x * blockDim.x + threadIdx.x;
    if (e < NE) {
        int r = ei[e];
        int c = ei[NE + e];
        int pos = g_offs[r] + atomicAdd(&g_cur[r], 1);
        g_epack[pos] = make_int2(c, __float_as_int(g_dinv[r] * g_dinv[c]));
    }
}
// weights fp16 [N][K], biases, h0->fp16, x->fp16 — one kernel
__global__ void k_init(const float* __restrict__ Wxz, const float* __restrict__ Whz,
                       const float* __restrict__ Wxr, const float* __restrict__ Whr,
                       const float* __restrict__ Wxh, const float* __restrict__ Whh,
                       const float* __restrict__ bxz, const float* __restrict__ bhz,
                       const float* __restrict__ bxr, const float* __restrict__ bhr,
                       const float* __restrict__ bxh, const float* __restrict__ bhh,
                       const float4* __restrict__ h0, const float4* __restrict__ x) {
    int i = blockIdx.x * blockDim.x + threadIdx.x;
    const int ZR = NL * 256 * 256;
    const int HS = NL * 128 * 256;
    const int B1 = ZR + HS;
    const int B2 = B1 + NL * 256;
    const int B3 = B2 + NL * 128;
    const int CP = NL * NN * HD / 4;
    const int B4 = B3 + CP;
    const int XC = NT * NN * HD / 4;
    if (i < ZR) {
        int l = i / (256 * 256);
        int nk = i % (256 * 256);
        int n = nk / 256, k = nk % 256;
        const float* W = (k < 128) ? ((n < 128) ? Wxz : Wxr)
                                   : ((n < 128) ? Whz : Whr);
        g_Bzr[l * 256 * 256 + nk] =
            __float2half_rn(W[l * HD * HD + (k & 127) * HD + (n & 127)]);
    } else if (i < B1) {
        int i2 = i - ZR;
        int l = i2 / (128 * 256);
        int nk = i2 % (128 * 256);
        int n = nk / 256, k = nk % 256;
        const float* W = (k < 128) ? Wxh : Whh;
        g_Bh[l * 128 * 256 + nk] =
            __float2half_rn(W[l * HD * HD + (k & 127) * HD + n]);
    } else if (i < B2) {
        int i2 = i - B1;
        int l = i2 / 256, j = i2 % 256;
        g_bzr[l][j] = (j < 128) ? (bxz[l * HD + j] + bhz[l * HD + j])
                                : (bxr[l * HD + j - 128] + bhr[l * HD + j - 128]);
    } else if (i < B3) {
        int i2 = i - B2;
        int l = i2 / 128, j = i2 % 128;
        g_bh[l][j] = bxh[l * HD + j] + bhh[l * HD + j];
    } else if (i < B4) {
        int j = i - B3;
        ((uint2*)&g_hf16[0][0])[j] = packh4(h0[j]);
    } else if (i - B4 < XC) {
        int j = i - B4;
        ((uint2*)&g_xf16[0])[j] = packh4(x[j]);
    }
}

// ================= SpMM: half-warp per edge, 2 edges/warp/iter =================
__global__ void __launch_bounds__(256) k_spmm2(
    const __half* __restrict__ srcA, const __half* __restrict__ srcB,
    __half* __restrict__ oA, __half* __restrict__ oB) {
    int row = (blockIdx.x * blockDim.x + threadIdx.x) >> 5;
    int lane = threadIdx.x & 31;
    if (row >= NN) return;
    int hw = lane >> 4, sl = lane & 15;
    const uint4* sA = (const uint4*)srcA;
    const uint4* sB = (const uint4*)srcB;
    float aA[8], aB[8];
    #pragma unroll
    for (int k = 0; k < 8; ++k) { aA[k] = 0.f; aB[k] = 0.f; }
    int e0 = g_offs[row], end = g_offs[row + 1];
    #pragma unroll 4
    for (int e = e0 + hw; e < end; e += 2) {
        int2 ew = g_epack[e];
        float w = __int_as_float(ew.y);
        uint4 u = sA[(size_t)ew.x * 16 + sl];
        uint4 v = sB[(size_t)ew.x * 16 + sl];
        acc8(aA, u, w);
        acc8(aB, v, w);
    }
    #pragma unroll
    for (int k = 0; k < 8; ++k) {
        aA[k] += __shfl_xor_sync(0xffffffff, aA[k], 16);
        aB[k] += __shfl_xor_sync(0xffffffff, aB[k], 16);
    }
    if (hw == 0) {
        float di = g_dinv[row];
        float ws = 2.f * di * di;
        acc8(aA, sA[(size_t)row * 16 + sl], ws);
        acc8(aB, sB[(size_t)row * 16 + sl], ws);
        ((uint4*)oA)[(size_t)row * 16 + sl] = pack8(aA);
        ((uint4*)oB)[(size_t)row * 16 + sl] = pack8(aB);
    }
}

__global__ void __launch_bounds__(256) k_spmm(const __half* __restrict__ src,
                                              __half* __restrict__ o) {
    int row = (blockIdx.x * blockDim.x + threadIdx.x) >> 5;
    int lane = threadIdx.x & 31;
    if (row >= NN) return;
    int hw = lane >> 4, sl = lane & 15;
    const uint4* s4 = (const uint4*)src;
    float a[8];
    #pragma unroll
    for (int k = 0; k < 8; ++k) a[k] = 0.f;
    int e0 = g_offs[row], end = g_offs[row + 1];
    #pragma unroll 4
    for (int e = e0 + hw; e < end; e += 2) {
        int2 ew = g_epack[e];
        float w = __int_as_float(ew.y);
        acc8(a, s4[(size_t)ew.x * 16 + sl], w);
    }
    #pragma unroll
    for (int k = 0; k < 8; ++k)
        a[k] += __shfl_xor_sync(0xffffffff, a[k], 16);
    if (hw == 0) {
        float di = g_dinv[row];
        acc8(a, s4[(size_t)row * 16 + sl], 2.f * di * di);
        ((uint4*)o)[(size_t)row * 16 + sl] = pack8(a);
    }
}

// ================= pipelined HMMA GEMM, templated N-tile =================
// MODE 0 (NCOL=128, grid.y=2): n<128 -> z16=sigmoid(v); n>=128 -> rh16=sigmoid(v)*h16
// MODE 1 (NCOL=64,  grid.y=2): hn = z*h+(1-z)*tanh(v) -> h16, optional out fp32
template <int MODE, int NCOL>
__global__ void __launch_bounds__(256) k_mma_gemm(
    const __half* __restrict__ Ax, const __half* __restrict__ Ay,
    const __half* __restrict__ B, const float* __restrict__ bias,
    __half* __restrict__ hP, __half* __restrict__ zP,
    __half* __restrict__ rhP, float* __restrict__ outF) {

    constexpr int STAGE = 16384 + NCOL * 128;   // A tile 16KB + B tile
    constexpr int WN = NCOL / 4;                // warp n-extent
    constexpr int JW = WN / 8;                  // j iterations
    constexpr int BJJ = WN / 16;                // B ldsm count per kk

    extern __shared__ char smem[];
    uint32_t sb = smem_u32(smem);
    int tid = threadIdx.x;
    int lane = tid & 31, warp = tid >> 5;
    int wm = warp >> 2, wn = warp & 3;          // 2x4 warps; warp tile 64 x WN
    int rowBase = blockIdx.x * 128;
    int nTile = blockIdx.y * NCOL;

    float acc[4][JW][4];
    #pragma unroll
    for (int i = 0; i < 4; ++i)
        #pragma unroll
        for (int j = 0; j < JW; ++j)
            #pragma unroll
            for (int q = 0; q < 4; ++q) acc[i][j][q] = 0.f;

    const uint32_t swx = (uint32_t)(lane & 7) << 4;

    auto prefetch = [&](int s, int b) {
        const __half* Ap = (s < 2) ? Ax : Ay;
        int ka = (s & 1) * 64;
        int kb = s * 64;
        uint32_t base = sb + (uint32_t)b * STAGE;
        #pragma unroll
        for (int u = 0; u < 4; ++u) {
            int idx = u * 256 + tid;
            int row = idx >> 3, c = idx & 7;
            uint32_t soff = (uint32_t)row * 128 +
                            (((uint32_t)c * 16) ^ (((uint32_t)row & 7) << 4));
            int gm = rowBase + row;
            cpa16(base + soff, Ap + (size_t)gm * HD + ka + c * 8, gm < NN);
        }
        #pragma unroll
        for (int u = 0; u < NCOL * 8 / 256; ++u) {
            int idx = u * 256 + tid;
            int row = idx >> 3, c = idx & 7;
            uint32_t soff = (uint32_t)row * 128 +
                            (((uint32_t)c * 16) ^ (((uint32_t)row & 7) << 4));
            int gn = nTile + row;
            cpa16(base + 16384 + soff, B + (size_t)gn * 256 + kb + c * 8, true);
        }
    };

    prefetch(0, 0); CP_COMMIT();
    prefetch(1, 1); CP_COMMIT();

    #pragma unroll 1
    for (int s = 0; s < 4; ++s) {
        CP_WAIT1();
        __syncthreads();
        uint32_t aBase = sb + (uint32_t)(s & 1) * STAGE;
        #pragma unroll
        for (int kk = 0; kk < 4; ++kk) {
            uint32_t a[4][4], bf[JW][2];
            #pragma unroll
            for (int i = 0; i < 4; ++i) {
                uint32_t m = (uint32_t)(wm * 64 + i * 16 + (lane & 15));
                uint32_t k2 = (uint32_t)(kk * 16 + ((lane & 16) >> 1)) * 2;
                ldsm4(a[i], aBase + m * 128 + (k2 ^ swx));
            }
            #pragma unroll
            for (int jj = 0; jj < BJJ; ++jj) {
                uint32_t n = (uint32_t)(wn * WN + jj * 16 + (lane & 7) + ((lane & 16) >> 1));
                uint32_t k2 = (uint32_t)(kk * 16 + (lane & 8)) * 2;
                uint32_t r[4];
                ldsm4(r, aBase + 16384 + n * 128 + (k2 ^ swx));
                bf[jj * 2][0] = r[0]; bf[jj * 2][1] = r[1];
                bf[jj * 2 + 1][0] = r[2]; bf[jj * 2 + 1][1] = r[3];
            }
            #pragma unroll
            for (int i = 0; i < 4; ++i)
                #pragma unroll
                for (int j = 0; j < JW; ++j)
                    mma16816(acc[i][j], a[i], bf[j]);
        }
        __syncthreads();
        if (s < 2) prefetch(s + 2, s & 1);
        CP_COMMIT();
    }

    // ---------- fused epilogue (fp16 state; bias from L2) ----------
    #pragma unroll
    for (int j = 0; j < JW; ++j) {
        int cl = wn * WN + j * 8 + (lane & 3) * 2;
        int c0 = nTile + cl;
        float bs0 = bias[c0], bs1 = bias[c0 + 1];
        #pragma unroll
        for (int i = 0; i < 4; ++i) {
            #pragma unroll
            for (int half = 0; half < 2; ++half) {
                int m0 = rowBase + wm * 64 + i * 16 + (lane >> 2) + half * 8;
                if (m0 >= NN) continue;
                float v0 = acc[i][j][half * 2 + 0] + bs0;
                float v1 = acc[i][j][half * 2 + 1] + bs1;
                if (MODE == 0) {
                    if (c0 < 128) {
                        *(__half2*)(zP + (size_t)m0 * HD + c0) =
                            __float22half2_rn(make_float2(sigf(v0), sigf(v1)));
                    } else {
                        int n2 = c0 - 128;
                        float2 hv = __half22float2(*(__half2*)(hP + (size_t)m0 * HD + n2));
                        *(__half2*)(rhP + (size_t)m0 * HD + n2) =
                            __float22half2_rn(make_float2(sigf(v0) * hv.x, sigf(v1) * hv.y));
                    }
                } else {
                    float2 hv = __half22float2(*(__half2*)(hP + (size_t)m0 * HD + c0));
                    float2 zv = __half22float2(*(__half2*)(zP + (size_t)m0 * HD + c0));
                    float o0 = zv.x * hv.x + (1.f - zv.x) * tanhf(v0);
                    float o1 = zv.y * hv.y + (1.f - zv.y) * tanhf(v1);
                    *(__half2*)(hP + (size_t)m0 * HD + c0) =
                        __float22half2_rn(make_float2(o0, o1));
                    if (outF)
                        *(float2*)(outF + (size_t)m0 * HD + c0) = make_float2(o0, o1);
                }
            }
        }
    }
}

// ================= host =================
extern "C" void kernel_launch(void* const* d_in, const int* in_sizes, int n_in,
                              void* d_out, int out_size) {
    if (n_in < 15) return;
    const float* x   = (const float*)d_in[0];
    const float* h0  = (const float*)d_in[1];
    const int*   ei  = (const int*)  d_in[2];
    const float* Wxz = (const float*)d_in[3];
    const float* Whz = (const float*)d_in[4];
    const float* Wxr = (const float*)d_in[5];
    const float* Whr = (const float*)d_in[6];
    const float* Wxh = (const float*)d_in[7];
    const float* Whh = (const float*)d_in[8];
    const float* bxz = (const float*)d_in[9];
    const float* bhz = (const float*)d_in[10];
    const float* bxr = (const float*)d_in[11];
    const float* bhr = (const float*)d_in[12];
    const float* bxh = (const float*)d_in[13];
    const float* bhh = (const float*)d_in[14];
    float* out = (float*)d_out;

    float *p_bzr, *p_bh;
    __half *p_xf16, *p_hf16, *p_zf16, *p_rhf16, *p_aX, *p_aY, *p_aH0, *p_aR, *p_Bzr, *p_Bh;
    cudaGetSymbolAddress((void**)&p_xf16,  g_xf16);
    cudaGetSymbolAddress((void**)&p_hf16,  g_hf16);
    cudaGetSymbolAddress((void**)&p_zf16,  g_zf16);
    cudaGetSymbolAddress((void**)&p_rhf16, g_rhf16);
    cudaGetSymbolAddress((void**)&p_aX,    g_aX);
    cudaGetSymbolAddress((void**)&p_aY,    g_aY);
    cudaGetSymbolAddress((void**)&p_aH0,   g_aH0);
    cudaGetSymbolAddress((void**)&p_aR,    g_aR);
    cudaGetSymbolAddress((void**)&p_Bzr,   g_Bzr);
    cudaGetSymbolAddress((void**)&p_Bh,    g_Bh);
    cudaGetSymbolAddress((void**)&p_bzr,   g_bzr);
    cudaGetSymbolAddress((void**)&p_bh,    g_bh);

    const int SMEM0 = 2 * (16384 + 128 * 128);   // 65536
    const int SMEM1 = 2 * (16384 + 64 * 128);    // 49152
    cudaFuncSetAttribute((const void*)k_mma_gemm<0, 128>,
                         cudaFuncAttributeMaxDynamicSharedMemorySize, SMEM0);
    cudaFuncSetAttribute((const void*)k_mma_gemm<1, 64>,
                         cudaFuncAttributeMaxDynamicSharedMemorySize, SMEM1);

    // ---- setup ----
    const int NB = (NN + 1023) / 1024;
    k_zero<<<(NN + 255) / 256, 256>>>();
    k_count<<<(NE + 255) / 256, 256>>>(ei);
    k_scan1<<<NB, 1024>>>();
    k_scan2<<<1, 64>>>();
    k_scan3<<<NB, 1024>>>();
    k_fill<<<(NE + 255) / 256, 256>>>(ei);
    {
        int tot = NL * 256 * 256 + NL * 128 * 256 + NL * 256 + NL * 128
                + NL * NN * HD / 4 + NT * NN * HD / 4;
        k_init<<<(tot + 255) / 256, 256>>>(Wxz, Whz, Wxr, Whr, Wxh, Whh,
                                           bxz, bhz, bxr, bhr, bxh, bhh,
                                           (const float4*)h0, (const float4*)x);
    }

    // ---- recurrence ----
    const int spmm_blocks = (NN + 7) / 8;
    const int gM = (NN + 127) / 128;  // 391
    __half* h0_16 = p_hf16;
    __half* h1_16 = p_hf16 + (size_t)NN * HD;

    // prologue: aX = A@x_0, aH0 = A@h0_init
    k_spmm2<<<spmm_blocks, 256>>>(p_xf16, h0_16, p_aX, p_aH0);

    for (int t = 0; t < NT; ++t) {
        // ---- layer 0 (aX = A@x_t, aH0 = A@h0_state) ----
        k_mma_gemm<0, 128><<<dim3(gM, 2), 256, SMEM0>>>(
            p_aX, p_aH0, p_Bzr, p_bzr, h0_16, p_zf16, p_rhf16, nullptr);
        k_spmm<<<spmm_blocks, 256>>>(p_rhf16, p_aR);
        k_mma_gemm<1, 64><<<dim3(gM, 2), 256, SMEM1>>>(
            p_aX, p_aR, p_Bh, p_bh, h0_16, p_zf16, nullptr, nullptr);

        // ---- layer 1 (aH0 = A@h0_t doubles as next t's L0 aggH) ----
        k_spmm2<<<spmm_blocks, 256>>>(h0_16, h1_16, p_aH0, p_aY);
        k_mma_gemm<0, 128><<<dim3(gM, 2), 256, SMEM0>>>(
            p_aH0, p_aY, p_Bzr + 256 * 256, p_bzr + 256,
            h1_16, p_zf16, p_rhf16, nullptr);
        if (t + 1 < NT) {
            // fold A@x_{t+1} into this edge pass
            k_spmm2<<<spmm_blocks, 256>>>(p_rhf16, p_xf16 + (size_t)(t + 1) * NN * HD,
                                          p_aR, p_aX);
        } else {
            k_spmm<<<spmm_blocks, 256>>>(p_rhf16, p_aR);
        }
        k_mma_gemm<1, 64><<<dim3(gM, 2), 256, SMEM1>>>(
            p_aH0, p_aR, p_Bh + 128 * 256, p_bh + 128,
            h1_16, p_zf16, nullptr, out + (size_t)t * NN * HD);
    }
}

// round 9
// speedup vs baseline: 3.3623x; 1.0194x over previous
#include <cuda_runtime.h>
#include <cuda_fp16.h>
#include <math.h>
#include <stdint.h>

#define NT 8
#define NN 50000
#define NE 800000
#define HD 128
#define NL 2

__device__ __forceinline__ uint32_t smem_u32(const void* p) {
    uint32_t a;
    asm("{ .reg .u64 t; cvta.to.shared.u64 t, %1; cvt.u32.u64 %0, t; }" : "=r"(a) : "l"(p));
    return a;
}
__device__ __forceinline__ float sigf(float x) { return 1.f / (1.f + __expf(-x)); }

__device__ __forceinline__ void mma16816(float* d, const uint32_t* a, const uint32_t* b) {
    asm volatile("mma.sync.aligned.m16n8k16.row.col.f32.f16.f16.f32 "
        "{%0,%1,%2,%3}, {%4,%5,%6,%7}, {%8,%9}, {%0,%1,%2,%3};"
        : "+f"(d[0]), "+f"(d[1]), "+f"(d[2]), "+f"(d[3])
        : "r"(a[0]), "r"(a[1]), "r"(a[2]), "r"(a[3]), "r"(b[0]), "r"(b[1]));
}
__device__ __forceinline__ void ldsm4(uint32_t* r, uint32_t addr) {
    asm volatile("ldmatrix.sync.aligned.m8n8.x4.shared.b16 {%0,%1,%2,%3}, [%4];"
        : "=r"(r[0]), "=r"(r[1]), "=r"(r[2]), "=r"(r[3]) : "r"(addr));
}
__device__ __forceinline__ void cpa16(uint32_t dst, const void* src, bool pred) {
    asm volatile("cp.async.cg.shared.global [%0], [%1], 16, %2;"
        :: "r"(dst), "l"(__cvta_generic_to_global(src)), "r"(pred ? 16 : 0) : "memory");
}
#define CP_COMMIT() asm volatile("cp.async.commit_group;" ::: "memory")
#define CP_WAIT1()  asm volatile("cp.async.wait_group 1;" ::: "memory")

__device__ __forceinline__ uint2 packh4(float4 a) {
    __half2 p0 = __float22half2_rn(make_float2(a.x, a.y));
    __half2 p1 = __float22half2_rn(make_float2(a.z, a.w));
    uint2 r;
    r.x = *(uint32_t*)&p0;
    r.y = *(uint32_t*)&p1;
    return r;
}
__device__ __forceinline__ void acc8(float* a, uint4 u, float w) {
    float2 f;
    f = __half22float2(*(__half2*)&u.x); a[0] += w * f.x; a[1] += w * f.y;
    f = __half22float2(*(__half2*)&u.y); a[2] += w * f.x; a[3] += w * f.y;
    f = __half22float2(*(__half2*)&u.z); a[4] += w * f.x; a[5] += w * f.y;
    f = __half22float2(*(__half2*)&u.w); a[6] += w * f.x; a[7] += w * f.y;
}
__device__ __forceinline__ uint4 pack8(const float* a) {
    uint4 r;
    __half2 h;
    h = __float22half2_rn(make_float2(a[0], a[1])); r.x = *(uint32_t*)&h;
    h = __float22half2_rn(make_float2(a[2], a[3])); r.y = *(uint32_t*)&h;
    h = __float22half2_rn(make_float2(a[4], a[5])); r.z = *(uint32_t*)&h;
    h = __float22half2_rn(make_float2(a[6], a[7])); r.w = *(uint32_t*)&h;
    return r;
}

// ================= static device scratch (all-fp16 state) =================
__device__ __align__(128) __half g_xf16[NT * NN * HD];
__device__ __align__(128) __half g_hf16[NL][NN * HD];
__device__ __align__(128) __half g_z0[NN * HD];        // z gate, layer 0
__device__ __align__(128) __half g_z1[NN * HD];        // z gate, layer 1
__device__ __align__(128) __half g_rhf16[NN * HD];
__device__ __align__(128) __half g_aX[NN * HD];
__device__ __align__(128) __half g_aY[NN * HD];
__device__ __align__(128) __half g_aH0[NN * HD];
__device__ __align__(128) __half g_aR[NN * HD];
__device__ int   g_cnt[NN];
__device__ int   g_cur[NN];
__device__ int   g_offs[NN + 1];
__device__ float g_dinv[NN];
__device__ int2  g_epack[NE];
__device__ int   g_bsum[64];
__device__ int   g_bbase[64];
__device__ __align__(128) __half g_Bzr[NL * 256 * 256];
__device__ __align__(128) __half g_Bh [NL * 128 * 256];
__device__ float g_bzr[NL][256];
__device__ float g_bh [NL][128];

// ================= setup kernels =================
__global__ void k_zero() {
    int i = blockIdx.x * blockDim.x + threadIdx.x;
    if (i < NN) { g_cnt[i] = 0; g_cur[i] = 0; }
}
__global__ void k_count(const int* __restrict__ ei) {
    int e = blockIdx.x * blockDim.x + threadIdx.x;
    if (e < NE) atomicAdd(&g_cnt[ei[e]], 1);
}
__global__ void k_scan1() {
    __shared__ int s[1024];
    int t = threadIdx.x;
    int i = blockIdx.x * 1024 + t;
    int v = (i < NN) ? g_cnt[i] : 0;
    if (i < NN) g_dinv[i] = rsqrtf((float)(v + 2));
    s[t] = v; __syncthreads();
    #pragma unroll
    for (int off = 1; off < 1024; off <<= 1) {
        int x = (t >= off) ? s[t - off] : 0;
        __syncthreads(); s[t] += x; __syncthreads();
    }
    if (i < NN) g_offs[i] = s[t] - v;
    if (t == 1023) g_bsum[blockIdx.x] = s[1023];
}
__global__ void k_scan2() {
    __shared__ int s[64];
    int t = threadIdx.x;
    const int NB = (NN + 1023) / 1024;
    int v = (t < NB) ? g_bsum[t] : 0;
    s[t] = v; __syncthreads();
    #pragma unroll
    for (int off = 1; off < 64; off <<= 1) {
        int x = (t >= off) ? s[t - off] : 0;
        __syncthreads(); s[t] += x; __syncthreads();
    }
    if (t < NB) g_bbase[t] = s[t] - v;
    if (t == 63) g_offs[NN] = s[63];
}
__global__ void k_scan3() {
    int i = blockIdx.x * 1024 + threadIdx.x;
    if (i < NN) g_offs[i] += g_bbase[blockIdx.x];
}
__global__ void k_fill(const int* __restrict__ ei) {
    int e = blockIdx.x * blockDim.x + threadIdx.x;
    if (e < NE) {
        int r = ei[e];
        int c = ei[NE + e];
        int pos = g_offs[r] + atomicAdd(&g_cur[r], 1);
        g_epack[pos] = make_int2(c, __float_as_int(g_dinv[r] * g_dinv[c]));
    }
}
__global__ void k_init(const float* __restrict__ Wxz, const float* __restrict__ Whz,
                       const float* __restrict__ Wxr, const float* __restrict__ Whr,
                       const float* __restrict__ Wxh, const float* __restrict__ Whh,
                       const float* __restrict__ bxz, const float* __restrict__ bhz,
                       const float* __restrict__ bxr, const float* __restrict__ bhr,
                       const float* __restrict__ bxh, const float* __restrict__ bhh,
                       const float4* __restrict__ h0, const float4* __restrict__ x) {
    int i = blockIdx.x * blockDim.x + threadIdx.x;
    const int ZR = NL * 256 * 256;
    const int HS = NL * 128 * 256;
    const int B1 = ZR + HS;
    const int B2 = B1 + NL * 256;
    const int B3 = B2 + NL * 128;
    const int CP = NL * NN * HD / 4;
    const int B4 = B3 + CP;
    const int XC = NT * NN * HD / 4;
    if (i < ZR) {
        int l = i / (256 * 256);
        int nk = i % (256 * 256);
        int n = nk / 256, k = nk % 256;
        const float* W = (k < 128) ? ((n < 128) ? Wxz : Wxr)
                                   : ((n < 128) ? Whz : Whr);
        g_Bzr[l * 256 * 256 + nk] =
            __float2half_rn(W[l * HD * HD + (k & 127) * HD + (n & 127)]);
    } else if (i < B1) {
        int i2 = i - ZR;
        int l = i2 / (128 * 256);
        int nk = i2 % (128 * 256);
        int n = nk / 256, k = nk % 256;
        const float* W = (k < 128) ? Wxh : Whh;
        g_Bh[l * 128 * 256 + nk] =
            __float2half_rn(W[l * HD * HD + (k & 127) * HD + n]);
    } else if (i < B2) {
        int i2 = i - B1;
        int l = i2 / 256, j = i2 % 256;
        g_bzr[l][j] = (j < 128) ? (bxz[l * HD + j] + bhz[l * HD + j])
                                : (bxr[l * HD + j - 128] + bhr[l * HD + j - 128]);
    } else if (i < B3) {
        int i2 = i - B2;
        int l = i2 / 128, j = i2 % 128;
        g_bh[l][j] = bxh[l * HD + j] + bhh[l * HD + j];
    } else if (i < B4) {
        int j = i - B3;
        ((uint2*)&g_hf16[0][0])[j] = packh4(h0[j]);
    } else if (i - B4 < XC) {
        int j = i - B4;
        ((uint2*)&g_xf16[0])[j] = packh4(x[j]);
    }
}

// ================= SpMM: half-warp per edge, 2 edges/warp/iter =================
__global__ void __launch_bounds__(256) k_spmm2(
    const __half* __restrict__ srcA, const __half* __restrict__ srcB,
    __half* __restrict__ oA, __half* __restrict__ oB) {
    int row = (blockIdx.x * blockDim.x + threadIdx.x) >> 5;
    int lane = threadIdx.x & 31;
    if (row >= NN) return;
    int hw = lane >> 4, sl = lane & 15;
    const uint4* sA = (const uint4*)srcA;
    const uint4* sB = (const uint4*)srcB;
    float aA[8], aB[8];
    #pragma unroll
    for (int k = 0; k < 8; ++k) { aA[k] = 0.f; aB[k] = 0.f; }
    int e0 = g_offs[row], end = g_offs[row + 1];
    #pragma unroll 4
    for (int e = e0 + hw; e < end; e += 2) {
        int2 ew = g_epack[e];
        float w = __int_as_float(ew.y);
        uint4 u = sA[(size_t)ew.x * 16 + sl];
        uint4 v = sB[(size_t)ew.x * 16 + sl];
        acc8(aA, u, w);
        acc8(aB, v, w);
    }
    #pragma unroll
    for (int k = 0; k < 8; ++k) {
        aA[k] += __shfl_xor_sync(0xffffffff, aA[k], 16);
        aB[k] += __shfl_xor_sync(0xffffffff, aB[k], 16);
    }
    if (hw == 0) {
        float di = g_dinv[row];
        float ws = 2.f * di * di;
        acc8(aA, sA[(size_t)row * 16 + sl], ws);
        acc8(aB, sB[(size_t)row * 16 + sl], ws);
        ((uint4*)oA)[(size_t)row * 16 + sl] = pack8(aA);
        ((uint4*)oB)[(size_t)row * 16 + sl] = pack8(aB);
    }
}

__global__ void __launch_bounds__(256) k_spmm(const __half* __restrict__ src,
                                              __half* __restrict__ o) {
    int row = (blockIdx.x * blockDim.x + threadIdx.x) >> 5;
    int lane = threadIdx.x & 31;
    if (row >= NN) return;
    int hw = lane >> 4, sl = lane & 15;
    const uint4* s4 = (const uint4*)src;
    float a[8];
    #pragma unroll
    for (int k = 0; k < 8; ++k) a[k] = 0.f;
    int e0 = g_offs[row], end = g_offs[row + 1];
    #pragma unroll 4
    for (int e = e0 + hw; e < end; e += 2) {
        int2 ew = g_epack[e];
        float w = __int_as_float(ew.y);
        acc8(a, s4[(size_t)ew.x * 16 + sl], w);
    }
    #pragma unroll
    for (int k = 0; k < 8; ++k)
        a[k] += __shfl_xor_sync(0xffffffff, a[k], 16);
    if (hw == 0) {
        float di = g_dinv[row];
        acc8(a, s4[(size_t)row * 16 + sl], 2.f * di * di);
        ((uint4*)o)[(size_t)row * 16 + sl] = pack8(a);
    }
}

// ================= pipelined HMMA GEMM, templated N-tile =================
template <int MODE, int NCOL>
__global__ void __launch_bounds__(256) k_mma_gemm(
    const __half* __restrict__ Ax, const __half* __restrict__ Ay,
    const __half* __restrict__ B, const float* __restrict__ bias,
    __half* __restrict__ hP, __half* __restrict__ zP,
    __half* __restrict__ rhP, float* __restrict__ outF) {

    constexpr int STAGE = 16384 + NCOL * 128;
    constexpr int WN = NCOL / 4;
    constexpr int JW = WN / 8;
    constexpr int BJJ = WN / 16;

    extern __shared__ char smem[];
    uint32_t sb = smem_u32(smem);
    int tid = threadIdx.x;
    int lane = tid & 31, warp = tid >> 5;
    int wm = warp >> 2, wn = warp & 3;
    int rowBase = blockIdx.x * 128;
    int nTile = blockIdx.y * NCOL;

    float acc[4][JW][4];
    #pragma unroll
    for (int i = 0; i < 4; ++i)
        #pragma unroll
        for (int j = 0; j < JW; ++j)
            #pragma unroll
            for (int q = 0; q < 4; ++q) acc[i][j][q] = 0.f;

    const uint32_t swx = (uint32_t)(lane & 7) << 4;

    auto prefetch = [&](int s, int b) {
        const __half* Ap = (s < 2) ? Ax : Ay;
        int ka = (s & 1) * 64;
        int kb = s * 64;
        uint32_t base = sb + (uint32_t)b * STAGE;
        #pragma unroll
        for (int u = 0; u < 4; ++u) {
            int idx = u * 256 + tid;
            int row = idx >> 3, c = idx & 7;
            uint32_t soff = (uint32_t)row * 128 +
                            (((uint32_t)c * 16) ^ (((uint32_t)row & 7) << 4));
            int gm = rowBase + row;
            cpa16(base + soff, Ap + (size_t)gm * HD + ka + c * 8, gm < NN);
        }
        #pragma unroll
        for (int u = 0; u < NCOL * 8 / 256; ++u) {
            int idx = u * 256 + tid;
            int row = idx >> 3, c = idx & 7;
            uint32_t soff = (uint32_t)row * 128 +
                            (((uint32_t)c * 16) ^ (((uint32_t)row & 7) << 4));
            int gn = nTile + row;
            cpa16(base + 16384 + soff, B + (size_t)gn * 256 + kb + c * 8, true);
        }
    };

    prefetch(0, 0); CP_COMMIT();
    prefetch(1, 1); CP_COMMIT();

    #pragma unroll 1
    for (int s = 0; s < 4; ++s) {
        CP_WAIT1();
        __syncthreads();
        uint32_t aBase = sb + (uint32_t)(s & 1) * STAGE;
        #pragma unroll
        for (int kk = 0; kk < 4; ++kk) {
            uint32_t a[4][4], bf[JW][2];
            #pragma unroll
            for (int i = 0; i < 4; ++i) {
                uint32_t m = (uint32_t)(wm * 64 + i * 16 + (lane & 15));
                uint32_t k2 = (uint32_t)(kk * 16 + ((lane & 16) >> 1)) * 2;
                ldsm4(a[i], aBase + m * 128 + (k2 ^ swx));
            }
            #pragma unroll
            for (int jj = 0; jj < BJJ; ++jj) {
                uint32_t n = (uint32_t)(wn * WN + jj * 16 + (lane & 7) + ((lane & 16) >> 1));
                uint32_t k2 = (uint32_t)(kk * 16 + (lane & 8)) * 2;
                uint32_t r[4];
                ldsm4(r, aBase + 16384 + n * 128 + (k2 ^ swx));
                bf[jj * 2][0] = r[0]; bf[jj * 2][1] = r[1];
                bf[jj * 2 + 1][0] = r[2]; bf[jj * 2 + 1][1] = r[3];
            }
            #pragma unroll
            for (int i = 0; i < 4; ++i)
                #pragma unroll
                for (int j = 0; j < JW; ++j)
                    mma16816(acc[i][j], a[i], bf[j]);
        }
        __syncthreads();
        if (s < 2) prefetch(s + 2, s & 1);
        CP_COMMIT();
    }

    // ---------- fused epilogue ----------
    #pragma unroll
    for (int j = 0; j < JW; ++j) {
        int cl = wn * WN + j * 8 + (lane & 3) * 2;
        int c0 = nTile + cl;
        float bs0 = bias[c0], bs1 = bias[c0 + 1];
        #pragma unroll
        for (int i = 0; i < 4; ++i) {
            #pragma unroll
            for (int half = 0; half < 2; ++half) {
                int m0 = rowBase + wm * 64 + i * 16 + (lane >> 2) + half * 8;
                if (m0 >= NN) continue;
                float v0 = acc[i][j][half * 2 + 0] + bs0;
                float v1 = acc[i][j][half * 2 + 1] + bs1;
                if (MODE == 0) {
                    if (c0 < 128) {
                        *(__half2*)(zP + (size_t)m0 * HD + c0) =
                            __float22half2_rn(make_float2(sigf(v0), sigf(v1)));
                    } else {
                        int n2 = c0 - 128;
                        float2 hv = __half22float2(*(__half2*)(hP + (size_t)m0 * HD + n2));
                        *(__half2*)(rhP + (size_t)m0 * HD + n2) =
                            __float22half2_rn(make_float2(sigf(v0) * hv.x, sigf(v1) * hv.y));
                    }
                } else {
                    float2 hv = __half22float2(*(__half2*)(hP + (size_t)m0 * HD + c0));
                    float2 zv = __half22float2(*(__half2*)(zP + (size_t)m0 * HD + c0));
                    float o0 = zv.x * hv.x + (1.f - zv.x) * tanhf(v0);
                    float o1 = zv.y * hv.y + (1.f - zv.y) * tanhf(v1);
                    *(__half2*)(hP + (size_t)m0 * HD + c0) =
                        __float22half2_rn(make_float2(o0, o1));
                    if (outF)
                        *(float2*)(outF + (size_t)m0 * HD + c0) = make_float2(o0, o1);
                }
            }
        }
    }
}

// ================= host =================
extern "C" void kernel_launch(void* const* d_in, const int* in_sizes, int n_in,
                              void* d_out, int out_size) {
    if (n_in < 15) return;
    const float* x   = (const float*)d_in[0];
    const float* h0  = (const float*)d_in[1];
    const int*   ei  = (const int*)  d_in[2];
    const float* Wxz = (const float*)d_in[3];
    const float* Whz = (const float*)d_in[4];
    const float* Wxr = (const float*)d_in[5];
    const float* Whr = (const float*)d_in[6];
    const float* Wxh = (const float*)d_in[7];
    const float* Whh = (const float*)d_in[8];
    const float* bxz = (const float*)d_in[9];
    const float* bhz = (const float*)d_in[10];
    const float* bxr = (const float*)d_in[11];
    const float* bhr = (const float*)d_in[12];
    const float* bxh = (const float*)d_in[13];
    const float* bhh = (const float*)d_in[14];
    float* out = (float*)d_out;

    float *p_bzr, *p_bh;
    __half *p_xf16, *p_hf16, *p_z0, *p_z1, *p_rhf16, *p_aX, *p_aY, *p_aH0, *p_aR, *p_Bzr, *p_Bh;
    cudaGetSymbolAddress((void**)&p_xf16,  g_xf16);
    cudaGetSymbolAddress((void**)&p_hf16,  g_hf16);
    cudaGetSymbolAddress((void**)&p_z0,    g_z0);
    cudaGetSymbolAddress((void**)&p_z1,    g_z1);
    cudaGetSymbolAddress((void**)&p_rhf16, g_rhf16);
    cudaGetSymbolAddress((void**)&p_aX,    g_aX);
    cudaGetSymbolAddress((void**)&p_aY,    g_aY);
    cudaGetSymbolAddress((void**)&p_aH0,   g_aH0);
    cudaGetSymbolAddress((void**)&p_aR,    g_aR);
    cudaGetSymbolAddress((void**)&p_Bzr,   g_Bzr);
    cudaGetSymbolAddress((void**)&p_Bh,    g_Bh);
    cudaGetSymbolAddress((void**)&p_bzr,   g_bzr);
    cudaGetSymbolAddress((void**)&p_bh,    g_bh);

    const int SMEM0 = 2 * (16384 + 128 * 128);   // 65536
    const int SMEM1 = 2 * (16384 + 64 * 128);    // 49152
    cudaFuncSetAttribute((const void*)k_mma_gemm<0, 128>,
                         cudaFuncAttributeMaxDynamicSharedMemorySize, SMEM0);
    cudaFuncSetAttribute((const void*)k_mma_gemm<1, 64>,
                         cudaFuncAttributeMaxDynamicSharedMemorySize, SMEM1);

    // one-time stream/event resources (host-side only; identical work every call)
    static cudaStream_t s2 = nullptr;
    static cudaEvent_t evS = nullptr, evI = nullptr, evF = nullptr, evG = nullptr;
    if (!s2) {
        cudaStreamCreateWithFlags(&s2, cudaStreamNonBlocking);
        cudaEventCreateWithFlags(&evS, cudaEventDisableTiming);
        cudaEventCreateWithFlags(&evI, cudaEventDisableTiming);
        cudaEventCreateWithFlags(&evF, cudaEventDisableTiming);
        cudaEventCreateWithFlags(&evG, cudaEventDisableTiming);
    }

    const int NB = (NN + 1023) / 1024;
    const int spmm_blocks = (NN + 7) / 8;
    const int gM = (NN + 127) / 128;  // 391

    // ---- fork: k_init on s2, CSR build on stream 0 ----
    k_zero<<<(NN + 255) / 256, 256>>>();
    cudaEventRecord(evS, 0);
    cudaStreamWaitEvent(s2, evS, 0);
    {
        int tot = NL * 256 * 256 + NL * 128 * 256 + NL * 256 + NL * 128
                + NL * NN * HD / 4 + NT * NN * HD / 4;
        k_init<<<(tot + 255) / 256, 256, 0, s2>>>(Wxz, Whz, Wxr, Whr, Wxh, Whh,
                                                  bxz, bhz, bxr, bhr, bxh, bhh,
                                                  (const float4*)h0, (const float4*)x);
    }
    cudaEventRecord(evI, s2);
    k_count<<<(NE + 255) / 256, 256>>>(ei);
    k_scan1<<<NB, 1024>>>();
    k_scan2<<<1, 64>>>();
    k_scan3<<<NB, 1024>>>();
    k_fill<<<(NE + 255) / 256, 256>>>(ei);
    cudaStreamWaitEvent(0, evI, 0);   // join k_init before first gather

    __half* h0_16 = p_hf16;
    __half* h1_16 = p_hf16 + (size_t)NN * HD;

    // prologue: aX = A@x_0, aH0 = A@h0_init
    k_spmm2<<<spmm_blocks, 256>>>(p_xf16, h0_16, p_aX, p_aH0);

    for (int t = 0; t < NT; ++t) {
        // A: gemm0 L0 (concurrent with G(t-1) on s2; buffers disjoint: z0 vs z1)
        k_mma_gemm<0, 128><<<dim3(gM, 2), 256, SMEM0>>>(
            p_aX, p_aH0, p_Bzr, p_bzr, h0_16, p_z0, p_rhf16, nullptr);
        // B: spmm(rh)->aR  — must wait for G(t-1), which reads aR
        if (t > 0) cudaStreamWaitEvent(0, evG, 0);
        k_spmm<<<spmm_blocks, 256>>>(p_rhf16, p_aR);
        // C: gemm1 L0 -> h0
        k_mma_gemm<1, 64><<<dim3(gM, 2), 256, SMEM1>>>(
            p_aX, p_aR, p_Bh, p_bh, h0_16, p_z0, nullptr, nullptr);
        // D: spmm2(h0, h1) -> aH0 (next-step L0 aggH + this-step L1 aggX), aY
        k_spmm2<<<spmm_blocks, 256>>>(h0_16, h1_16, p_aH0, p_aY);
        // E: gemm0 L1
        k_mma_gemm<0, 128><<<dim3(gM, 2), 256, SMEM0>>>(
            p_aH0, p_aY, p_Bzr + 256 * 256, p_bzr + 256,
            h1_16, p_z1, p_rhf16, nullptr);
        // F: spmm2(rh, x_{t+1}) -> aR, aX' (fold next-step x aggregation)
        if (t + 1 < NT) {
            k_spmm2<<<spmm_blocks, 256>>>(p_rhf16, p_xf16 + (size_t)(t + 1) * NN * HD,
                                          p_aR, p_aX);
        } else {
            k_spmm<<<spmm_blocks, 256>>>(p_rhf16, p_aR);
        }
        // G: gemm1 L1 -> h1, out — forked to s2, overlaps A(t+1)
        cudaEventRecord(evF, 0);
        cudaStreamWaitEvent(s2, evF, 0);
        k_mma_gemm<1, 64><<<dim3(gM, 2), 256, SMEM1, s2>>>(
            p_aH0, p_aR, p_Bh + 128 * 256, p_bh + 128,
            h1_16, p_z1, nullptr, out + (size_t)t * NN * HD);
        cudaEventRecord(evG, s2);
    }
    // join the fork before returning (required for valid capture)
    cudaStreamWaitEvent(0, evG, 0);
}

// round 10
// speedup vs baseline: 3.7084x; 1.1029x over previous
#include <cuda_runtime.h>
#include <cuda_fp16.h>
#include <math.h>
#include <stdint.h>

#define NT 8
#define NN 50000
#define NE 800000
#define HD 128
#define NL 2

__device__ __forceinline__ uint32_t smem_u32(const void* p) {
    uint32_t a;
    asm("{ .reg .u64 t; cvta.to.shared.u64 t, %1; cvt.u32.u64 %0, t; }" : "=r"(a) : "l"(p));
    return a;
}
__device__ __forceinline__ float sigf(float x) { return 1.f / (1.f + __expf(-x)); }

__device__ __forceinline__ void mma16816(float* d, const uint32_t* a, const uint32_t* b) {
    asm volatile("mma.sync.aligned.m16n8k16.row.col.f32.f16.f16.f32 "
        "{%0,%1,%2,%3}, {%4,%5,%6,%7}, {%8,%9}, {%0,%1,%2,%3};"
        : "+f"(d[0]), "+f"(d[1]), "+f"(d[2]), "+f"(d[3])
        : "r"(a[0]), "r"(a[1]), "r"(a[2]), "r"(a[3]), "r"(b[0]), "r"(b[1]));
}
__device__ __forceinline__ void ldsm4(uint32_t* r, uint32_t addr) {
    asm volatile("ldmatrix.sync.aligned.m8n8.x4.shared.b16 {%0,%1,%2,%3}, [%4];"
        : "=r"(r[0]), "=r"(r[1]), "=r"(r[2]), "=r"(r[3]) : "r"(addr));
}
__device__ __forceinline__ void cpa16(uint32_t dst, const void* src, bool pred) {
    asm volatile("cp.async.cg.shared.global [%0], [%1], 16, %2;"
        :: "r"(dst), "l"(__cvta_generic_to_global(src)), "r"(pred ? 16 : 0) : "memory");
}
#define CP_COMMIT() asm volatile("cp.async.commit_group;" ::: "memory")
#define CP_WAIT1()  asm volatile("cp.async.wait_group 1;" ::: "memory")

__device__ __forceinline__ uint2 packh4(float4 a) {
    __half2 p0 = __float22half2_rn(make_float2(a.x, a.y));
    __half2 p1 = __float22half2_rn(make_float2(a.z, a.w));
    uint2 r;
    r.x = *(uint32_t*)&p0;
    r.y = *(uint32_t*)&p1;
    return r;
}
__device__ __forceinline__ void acc8(float* a, uint4 u, float w) {
    float2 f;
    f = __half22float2(*(__half2*)&u.x); a[0] += w * f.x; a[1] += w * f.y;
    f = __half22float2(*(__half2*)&u.y); a[2] += w * f.x; a[3] += w * f.y;
    f = __half22float2(*(__half2*)&u.z); a[4] += w * f.x; a[5] += w * f.y;
    f = __half22float2(*(__half2*)&u.w); a[6] += w * f.x; a[7] += w * f.y;
}
__device__ __forceinline__ uint4 pack8(const float* a) {
    uint4 r;
    __half2 h;
    h = __float22half2_rn(make_float2(a[0], a[1])); r.x = *(uint32_t*)&h;
    h = __float22half2_rn(make_float2(a[2], a[3])); r.y = *(uint32_t*)&h;
    h = __float22half2_rn(make_float2(a[4], a[5])); r.z = *(uint32_t*)&h;
    h = __float22half2_rn(make_float2(a[6], a[7])); r.w = *(uint32_t*)&h;
    return r;
}

// ================= static device scratch =================
__device__ __align__(128) __half g_xf16[NT * NN * HD];
__device__ __align__(128) __half g_hf16[NL][NN * HD];
__device__ __align__(128) __half g_z0[NN * HD];
__device__ __align__(128) __half g_z1[NN * HD];
__device__ __align__(128) __half g_rhf16[NN * HD];
__device__ __align__(128) __half g_aX[NN * HD];
__device__ __align__(128) __half g_aY[NN * HD];
__device__ __align__(128) __half g_aH0[NN * HD];
__device__ __align__(128) __half g_aR[NN * HD];
__device__ int   g_cnt[NN];
__device__ int   g_cur[NN];
__device__ int   g_offs[NN + 1];
__device__ float g_dinv[NN];
__device__ int2  g_epack[NE];
__device__ int   g_bsum[64];
__device__ int   g_bbase[64];
__device__ __align__(128) __half g_Bzr[NL * 256 * 256];
__device__ __align__(128) __half g_Bh [NL * 128 * 256];
__device__ float g_bzr[NL][256];
__device__ float g_bh [NL][128];

// ================= setup kernels =================
__global__ void k_zero() {
    int i = blockIdx.x * blockDim.x + threadIdx.x;
    if (i < NN) { g_cnt[i] = 0; g_cur[i] = 0; }
}
__global__ void k_count(const int* __restrict__ ei) {
    int e = blockIdx.x * blockDim.x + threadIdx.x;
    if (e < NE) atomicAdd(&g_cnt[ei[e]], 1);
}
__global__ void k_scan1() {
    __shared__ int s[1024];
    int t = threadIdx.x;
    int i = blockIdx.x * 1024 + t;
    int v = (i < NN) ? g_cnt[i] : 0;
    if (i < NN) g_dinv[i] = rsqrtf((float)(v + 2));
    s[t] = v; __syncthreads();
    #pragma unroll
    for (int off = 1; off < 1024; off <<= 1) {
        int x = (t >= off) ? s[t - off] : 0;
        __syncthreads(); s[t] += x; __syncthreads();
    }
    if (i < NN) g_offs[i] = s[t] - v;
    if (t == 1023) g_bsum[blockIdx.x] = s[1023];
}
__global__ void k_scan2() {
    __shared__ int s[64];
    int t = threadIdx.x;
    const int NB = (NN + 1023) / 1024;
    int v = (t < NB) ? g_bsum[t] : 0;
    s[t] = v; __syncthreads();
    #pragma unroll
    for (int off = 1; off < 64; off <<= 1) {
        int x = (t >= off) ? s[t - off] : 0;
        __syncthreads(); s[t] += x; __syncthreads();
    }
    if (t < NB) g_bbase[t] = s[t] - v;
    if (t == 63) g_offs[NN] = s[63];
}
__global__ void k_scan3() {
    int i = blockIdx.x * 1024 + threadIdx.x;
    if (i < NN) g_offs[i] += g_bbase[blockIdx.x];
}
__global__ void k_fill(const int* __restrict__ ei) {
    int e = blockIdx.x * blockDim.x + threadIdx.x;
    if (e < NE) {
        int r = ei[e];
        int c = ei[NE + e];
        int pos = g_offs[r] + atomicAdd(&g_cur[r], 1);
        g_epack[pos] = make_int2(c, __float_as_int(g_dinv[r] * g_dinv[c]));
    }
}
__global__ void k_init(const float* __restrict__ Wxz, const float* __restrict__ Whz,
                       const float* __restrict__ Wxr, const float* __restrict__ Whr,
                       const float* __restrict__ Wxh, const float* __restrict__ Whh,
                       const float* __restrict__ bxz, const float* __restrict__ bhz,
                       const float* __restrict__ bxr, const float* __restrict__ bhr,
                       const float* __restrict__ bxh, const float* __restrict__ bhh,
                       const float4* __restrict__ h0, const float4* __restrict__ x) {
    int i = blockIdx.x * blockDim.x + threadIdx.x;
    const int ZR = NL * 256 * 256;
    const int HS = NL * 128 * 256;
    const int B1 = ZR + HS;
    const int B2 = B1 + NL * 256;
    const int B3 = B2 + NL * 128;
    const int CP = NL * NN * HD / 4;
    const int B4 = B3 + CP;
    const int XC = NT * NN * HD / 4;
    if (i < ZR) {
        int l = i / (256 * 256);
        int nk = i % (256 * 256);
        int n = nk / 256, k = nk % 256;
        const float* W = (k < 128) ? ((n < 128) ? Wxz : Wxr)
                                   : ((n < 128) ? Whz : Whr);
        g_Bzr[l * 256 * 256 + nk] =
            __float2half_rn(W[l * HD * HD + (k & 127) * HD + (n & 127)]);
    } else if (i < B1) {
        int i2 = i - ZR;
        int l = i2 / (128 * 256);
        int nk = i2 % (128 * 256);
        int n = nk / 256, k = nk % 256;
        const float* W = (k < 128) ? Wxh : Whh;
        g_Bh[l * 128 * 256 + nk] =
            __float2half_rn(W[l * HD * HD + (k & 127) * HD + n]);
    } else if (i < B2) {
        int i2 = i - B1;
        int l = i2 / 256, j = i2 % 256;
        g_bzr[l][j] = (j < 128) ? (bxz[l * HD + j] + bhz[l * HD + j])
                                : (bxr[l * HD + j - 128] + bhr[l * HD + j - 128]);
    } else if (i < B3) {
        int i2 = i - B2;
        int l = i2 / 128, j = i2 % 128;
        g_bh[l][j] = bxh[l * HD + j] + bhh[l * HD + j];
    } else if (i < B4) {
        int j = i - B3;
        ((uint2*)&g_hf16[0][0])[j] = packh4(h0[j]);
    } else if (i - B4 < XC) {
        int j = i - B4;
        ((uint2*)&g_xf16[0])[j] = packh4(x[j]);
    }
}

// ================= SpMM: half-warp per edge, 2 edges/warp/iter =================
__global__ void __launch_bounds__(256) k_spmm2(
    const __half* __restrict__ srcA, const __half* __restrict__ srcB,
    __half* __restrict__ oA, __half* __restrict__ oB) {
    int row = (blockIdx.x * blockDim.x + threadIdx.x) >> 5;
    int lane = threadIdx.x & 31;
    if (row >= NN) return;
    int hw = lane >> 4, sl = lane & 15;
    const uint4* sA = (const uint4*)srcA;
    const uint4* sB = (const uint4*)srcB;
    float aA[8], aB[8];
    #pragma unroll
    for (int k = 0; k < 8; ++k) { aA[k] = 0.f; aB[k] = 0.f; }
    int e0 = g_offs[row], end = g_offs[row + 1];
    #pragma unroll 4
    for (int e = e0 + hw; e < end; e += 2) {
        int2 ew = g_epack[e];
        float w = __int_as_float(ew.y);
        uint4 u = sA[(size_t)ew.x * 16 + sl];
        uint4 v = sB[(size_t)ew.x * 16 + sl];
        acc8(aA, u, w);
        acc8(aB, v, w);
    }
    #pragma unroll
    for (int k = 0; k < 8; ++k) {
        aA[k] += __shfl_xor_sync(0xffffffff, aA[k], 16);
        aB[k] += __shfl_xor_sync(0xffffffff, aB[k], 16);
    }
    if (hw == 0) {
        float di = g_dinv[row];
        float ws = 2.f * di * di;
        acc8(aA, sA[(size_t)row * 16 + sl], ws);
        acc8(aB, sB[(size_t)row * 16 + sl], ws);
        ((uint4*)oA)[(size_t)row * 16 + sl] = pack8(aA);
        ((uint4*)oB)[(size_t)row * 16 + sl] = pack8(aB);
    }
}

__global__ void __launch_bounds__(256) k_spmm(const __half* __restrict__ src,
                                              __half* __restrict__ o) {
    int row = (blockIdx.x * blockDim.x + threadIdx.x) >> 5;
    int lane = threadIdx.x & 31;
    if (row >= NN) return;
    int hw = lane >> 4, sl = lane & 15;
    const uint4* s4 = (const uint4*)src;
    float a[8];
    #pragma unroll
    for (int k = 0; k < 8; ++k) a[k] = 0.f;
    int e0 = g_offs[row], end = g_offs[row + 1];
    #pragma unroll 4
    for (int e = e0 + hw; e < end; e += 2) {
        int2 ew = g_epack[e];
        float w = __int_as_float(ew.y);
        acc8(a, s4[(size_t)ew.x * 16 + sl], w);
    }
    #pragma unroll
    for (int k = 0; k < 8; ++k)
        a[k] += __shfl_xor_sync(0xffffffff, a[k], 16);
    if (hw == 0) {
        float di = g_dinv[row];
        acc8(a, s4[(size_t)row * 16 + sl], 2.f * di * di);
        ((uint4*)o)[(size_t)row * 16 + sl] = pack8(a);
    }
}

// ================= pipelined HMMA GEMM, NCOL=64 tiles, 4x2 warp grid =================
// M tile 128, N tile 64; warp tile 32x32; acc 32 regs/thread -> 3 blocks/SM.
// nBase selects the output-column window: nTile = nBase + blockIdx.y*64.
// MODE 0: c0<128 -> z16 = sigmoid(v); c0>=128 -> rh16 = sigmoid(v)*h16
// MODE 1: hn = z*h+(1-z)*tanh(v) -> h16, optional out fp32
#define STAGE_SZ 24576
#define SMEM_GEMM (2 * STAGE_SZ)

template <int MODE>
__global__ void __launch_bounds__(256) k_mma_gemm(
    const __half* __restrict__ Ax, const __half* __restrict__ Ay,
    const __half* __restrict__ B, const float* __restrict__ bias,
    __half* __restrict__ hP, __half* __restrict__ zP,
    __half* __restrict__ rhP, float* __restrict__ outF, int nBase) {

    extern __shared__ char smem[];
    uint32_t sb = smem_u32(smem);
    int tid = threadIdx.x;
    int lane = tid & 31, warp = tid >> 5;
    int wm = warp >> 1;                  // 0..3, 32-row strip
    int wn = warp & 1;                   // 0..1, 32-col strip
    int rowBase = blockIdx.x * 128;
    int nTile = nBase + blockIdx.y * 64;

    float acc[2][4][4];
    #pragma unroll
    for (int i = 0; i < 2; ++i)
        #pragma unroll
        for (int j = 0; j < 4; ++j)
            #pragma unroll
            for (int q = 0; q < 4; ++q) acc[i][j][q] = 0.f;

    const uint32_t swx = (uint32_t)(lane & 7) << 4;

    auto prefetch = [&](int s, int b) {
        const __half* Ap = (s < 2) ? Ax : Ay;
        int ka = (s & 1) * 64;
        int kb = s * 64;
        uint32_t base = sb + (uint32_t)b * STAGE_SZ;
        #pragma unroll
        for (int u = 0; u < 4; ++u) {               // A: 128 rows x 64 k
            int idx = u * 256 + tid;
            int row = idx >> 3, c = idx & 7;
            uint32_t soff = (uint32_t)row * 128 +
                            (((uint32_t)c * 16) ^ (((uint32_t)row & 7) << 4));
            int gm = rowBase + row;
            cpa16(base + soff, Ap + (size_t)gm * HD + ka + c * 8, gm < NN);
        }
        #pragma unroll
        for (int u = 0; u < 2; ++u) {               // B: 64 rows x 64 k
            int idx = u * 256 + tid;
            int row = idx >> 3, c = idx & 7;
            uint32_t soff = (uint32_t)row * 128 +
                            (((uint32_t)c * 16) ^ (((uint32_t)row & 7) << 4));
            int gn = nTile + row;
            cpa16(base + 16384 + soff, B + (size_t)gn * 256 + kb + c * 8, true);
        }
    };

    prefetch(0, 0); CP_COMMIT();
    prefetch(1, 1); CP_COMMIT();

    #pragma unroll 1
    for (int s = 0; s < 4; ++s) {
        CP_WAIT1();
        __syncthreads();
        uint32_t aBase = sb + (uint32_t)(s & 1) * STAGE_SZ;
        #pragma unroll
        for (int kk = 0; kk < 4; ++kk) {
            uint32_t a[2][4], bf[4][2];
            #pragma unroll
            for (int i = 0; i < 2; ++i) {
                uint32_t m = (uint32_t)(wm * 32 + i * 16 + (lane & 15));
                uint32_t k2 = (uint32_t)(kk * 16 + ((lane & 16) >> 1)) * 2;
                ldsm4(a[i], aBase + m * 128 + (k2 ^ swx));
            }
            #pragma unroll
            for (int jj = 0; jj < 2; ++jj) {
                uint32_t n = (uint32_t)(wn * 32 + jj * 16 + (lane & 7) + ((lane & 16) >> 1));
                uint32_t k2 = (uint32_t)(kk * 16 + (lane & 8)) * 2;
                uint32_t r[4];
                ldsm4(r, aBase + 16384 + n * 128 + (k2 ^ swx));
                bf[jj * 2][0] = r[0]; bf[jj * 2][1] = r[1];
                bf[jj * 2 + 1][0] = r[2]; bf[jj * 2 + 1][1] = r[3];
            }
            #pragma unroll
            for (int i = 0; i < 2; ++i)
                #pragma unroll
                for (int j = 0; j < 4; ++j)
                    mma16816(acc[i][j], a[i], bf[j]);
        }
        __syncthreads();
        if (s < 2) prefetch(s + 2, s & 1);
        CP_COMMIT();
    }

    // ---------- fused epilogue ----------
    #pragma unroll
    for (int j = 0; j < 4; ++j) {
        int cl = wn * 32 + j * 8 + (lane & 3) * 2;
        int c0 = nTile + cl;
        float bs0 = bias[c0], bs1 = bias[c0 + 1];
        #pragma unroll
        for (int i = 0; i < 2; ++i) {
            #pragma unroll
            for (int half = 0; half < 2; ++half) {
                int m0 = rowBase + wm * 32 + i * 16 + (lane >> 2) + half * 8;
                if (m0 >= NN) continue;
                float v0 = acc[i][j][half * 2 + 0] + bs0;
                float v1 = acc[i][j][half * 2 + 1] + bs1;
                if (MODE == 0) {
                    if (c0 < 128) {
                        *(__half2*)(zP + (size_t)m0 * HD + c0) =
                            __float22half2_rn(make_float2(sigf(v0), sigf(v1)));
                    } else {
                        int n2 = c0 - 128;
                        float2 hv = __half22float2(*(__half2*)(hP + (size_t)m0 * HD + n2));
                        *(__half2*)(rhP + (size_t)m0 * HD + n2) =
                            __float22half2_rn(make_float2(sigf(v0) * hv.x, sigf(v1) * hv.y));
                    }
                } else {
                    float2 hv = __half22float2(*(__half2*)(hP + (size_t)m0 * HD + c0));
                    float2 zv = __half22float2(*(__half2*)(zP + (size_t)m0 * HD + c0));
                    float o0 = zv.x * hv.x + (1.f - zv.x) * tanhf(v0);
                    float o1 = zv.y * hv.y + (1.f - zv.y) * tanhf(v1);
                    *(__half2*)(hP + (size_t)m0 * HD + c0) =
                        __float22half2_rn(make_float2(o0, o1));
                    if (outF)
                        *(float2*)(outF + (size_t)m0 * HD + c0) = make_float2(o0, o1);
                }
            }
        }
    }
}

// ================= host =================
extern "C" void kernel_launch(void* const* d_in, const int* in_sizes, int n_in,
                              void* d_out, int out_size) {
    if (n_in < 15) return;
    const float* x   = (const float*)d_in[0];
    const float* h0  = (const float*)d_in[1];
    const int*   ei  = (const int*)  d_in[2];
    const float* Wxz = (const float*)d_in[3];
    const float* Whz = (const float*)d_in[4];
    const float* Wxr = (const float*)d_in[5];
    const float* Whr = (const float*)d_in[6];
    const float* Wxh = (const float*)d_in[7];
    const float* Whh = (const float*)d_in[8];
    const float* bxz = (const float*)d_in[9];
    const float* bhz = (const float*)d_in[10];
    const float* bxr = (const float*)d_in[11];
    const float* bhr = (const float*)d_in[12];
    const float* bxh = (const float*)d_in[13];
    const float* bhh = (const float*)d_in[14];
    float* out = (float*)d_out;

    float *p_bzr, *p_bh;
    __half *p_xf16, *p_hf16, *p_z0, *p_z1, *p_rhf16, *p_aX, *p_aY, *p_aH0, *p_aR, *p_Bzr, *p_Bh;
    cudaGetSymbolAddress((void**)&p_xf16,  g_xf16);
    cudaGetSymbolAddress((void**)&p_hf16,  g_hf16);
    cudaGetSymbolAddress((void**)&p_z0,    g_z0);
    cudaGetSymbolAddress((void**)&p_z1,    g_z1);
    cudaGetSymbolAddress((void**)&p_rhf16, g_rhf16);
    cudaGetSymbolAddress((void**)&p_aX,    g_aX);
    cudaGetSymbolAddress((void**)&p_aY,    g_aY);
    cudaGetSymbolAddress((void**)&p_aH0,   g_aH0);
    cudaGetSymbolAddress((void**)&p_aR,    g_aR);
    cudaGetSymbolAddress((void**)&p_Bzr,   g_Bzr);
    cudaGetSymbolAddress((void**)&p_Bh,    g_Bh);
    cudaGetSymbolAddress((void**)&p_bzr,   g_bzr);
    cudaGetSymbolAddress((void**)&p_bh,    g_bh);

    cudaFuncSetAttribute((const void*)k_mma_gemm<0>,
                         cudaFuncAttributeMaxDynamicSharedMemorySize, SMEM_GEMM);
    cudaFuncSetAttribute((const void*)k_mma_gemm<1>,
                         cudaFuncAttributeMaxDynamicSharedMemorySize, SMEM_GEMM);

    static cudaStream_t s2 = nullptr;
    static cudaEvent_t evS = nullptr, evI = nullptr, e1 = nullptr, e2 = nullptr,
                       e3 = nullptr, evF = nullptr, evG = nullptr;
    if (!s2) {
        cudaStreamCreateWithFlags(&s2, cudaStreamNonBlocking);
        cudaEventCreateWithFlags(&evS, cudaEventDisableTiming);
        cudaEventCreateWithFlags(&evI, cudaEventDisableTiming);
        cudaEventCreateWithFlags(&e1,  cudaEventDisableTiming);
        cudaEventCreateWithFlags(&e2,  cudaEventDisableTiming);
        cudaEventCreateWithFlags(&e3,  cudaEventDisableTiming);
        cudaEventCreateWithFlags(&evF, cudaEventDisableTiming);
        cudaEventCreateWithFlags(&evG, cudaEventDisableTiming);
    }

    const int NB = (NN + 1023) / 1024;
    const int spmm_blocks = (NN + 7) / 8;
    const int gM = (NN + 127) / 128;  // 391

    // ---- setup: fork k_init onto s2, CSR build on main ----
    k_zero<<<(NN + 255) / 256, 256>>>();
    cudaEventRecord(evS, 0);
    cudaStreamWaitEvent(s2, evS, 0);
    {
        int tot = NL * 256 * 256 + NL * 128 * 256 + NL * 256 + NL * 128
                + NL * NN * HD / 4 + NT * NN * HD / 4;
        k_init<<<(tot + 255) / 256, 256, 0, s2>>>(Wxz, Whz, Wxr, Whr, Wxh, Whh,
                                                  bxz, bhz, bxr, bhr, bxh, bhh,
                                                  (const float4*)h0, (const float4*)x);
    }
    cudaEventRecord(evI, s2);
    k_count<<<(NE + 255) / 256, 256>>>(ei);
    k_scan1<<<NB, 1024>>>();
    k_scan2<<<1, 64>>>();
    k_scan3<<<NB, 1024>>>();
    k_fill<<<(NE + 255) / 256, 256>>>(ei);
    cudaStreamWaitEvent(0, evI, 0);

    __half* h0_16 = p_hf16;
    __half* h1_16 = p_hf16 + (size_t)NN * HD;

    // prologue: aX = A@x_0, aH0 = A@h0_init
    k_spmm2<<<spmm_blocks, 256>>>(p_xf16, h0_16, p_aX, p_aH0);

    for (int t = 0; t < NT; ++t) {
        // A_rh: gemm0 L0 rh-half on main (writes rh)
        k_mma_gemm<0><<<dim3(gM, 2), 256, SMEM_GEMM>>>(
            p_aX, p_aH0, p_Bzr, p_bzr, h0_16, p_z0, p_rhf16, nullptr, 128);
        cudaEventRecord(e1, 0);
        cudaStreamWaitEvent(s2, e1, 0);
        // A_z: gemm0 L0 z-half on s2 (writes z0) — overlaps spmm B
        k_mma_gemm<0><<<dim3(gM, 2), 256, SMEM_GEMM, s2>>>(
            p_aX, p_aH0, p_Bzr, p_bzr, h0_16, p_z0, p_rhf16, nullptr, 0);
        cudaEventRecord(e2, s2);
        // B: spmm(rh)->aR; must wait G(t-1) which read aR
        if (t > 0) cudaStreamWaitEvent(0, evG, 0);
        k_spmm<<<spmm_blocks, 256>>>(p_rhf16, p_aR);
        cudaStreamWaitEvent(0, e2, 0);      // z0 ready (also orders A_z's aH0/aX reads before D/F writes)
        // C: gemm1 L0 -> h0
        k_mma_gemm<1><<<dim3(gM, 2), 256, SMEM_GEMM>>>(
            p_aX, p_aR, p_Bh, p_bh, h0_16, p_z0, nullptr, nullptr, 0);
        // D: spmm2(h0, h1) -> aH0, aY
        k_spmm2<<<spmm_blocks, 256>>>(h0_16, h1_16, p_aH0, p_aY);
        // E_rh: gemm0 L1 rh-half (writes rh)
        k_mma_gemm<0><<<dim3(gM, 2), 256, SMEM_GEMM>>>(
            p_aH0, p_aY, p_Bzr + 256 * 256, p_bzr + 256,
            h1_16, p_z1, p_rhf16, nullptr, 128);
        cudaEventRecord(e3, 0);
        cudaStreamWaitEvent(s2, e3, 0);
        // E_z on s2 (writes z1) — overlaps spmm2 F
        k_mma_gemm<0><<<dim3(gM, 2), 256, SMEM_GEMM, s2>>>(
            p_aH0, p_aY, p_Bzr + 256 * 256, p_bzr + 256,
            h1_16, p_z1, p_rhf16, nullptr, 0);
        // F: spmm2(rh, x_{t+1}) -> aR, aX  (folds next-step x aggregation)
        if (t + 1 < NT) {
            k_spmm2<<<spmm_blocks, 256>>>(p_rhf16, p_xf16 + (size_t)(t + 1) * NN * HD,
                                          p_aR, p_aX);
        } else {
            k_spmm<<<spmm_blocks, 256>>>(p_rhf16, p_aR);
        }
        // G: gemm1 L1 -> h1, out on s2 (serial after E_z; waits F for aR); overlaps A_rh(t+1)
        cudaEventRecord(evF, 0);
        cudaStreamWaitEvent(s2, evF, 0);
        k_mma_gemm<1><<<dim3(gM, 2), 256, SMEM_GEMM, s2>>>(
            p_aH0, p_aR, p_Bh + 128 * 256, p_bh + 128,
            h1_16, p_z1, nullptr, out + (size_t)t * NN * HD, 0);
        cudaEventRecord(evG, s2);
    }
    cudaStreamWaitEvent(0, evG, 0);
}